// round 2
// baseline (speedup 1.0000x reference)
#include <cuda_runtime.h>
#include <math.h>

#define NNODE 100000
#define NEDGE 200000
#define NG 64
#define FIN 128
#define NFILT 8
#define HIDDIM 256
#define OUTDIM 64
#define ATTD 128
#define NHEADS 4

// ---------------- scratch (device globals; no cudaMalloc allowed) ----------------
__device__ float g_T[NHEADS*ATTD*ATTD];   // W_h @ A_h
__device__ float g_r[NHEADS*ATTD];        // b_h @ A_h
__device__ float g_M[FIN*FIN];            // 0.25 * sum_h W A W^T
__device__ float g_u[FIN];
__device__ float g_v[FIN];
__device__ float g_c[1];
__device__ float g_z[NNODE*FIN];          // x @ M
__device__ float g_p[NNODE];
__device__ float g_q[NNODE];
__device__ float g_hid[NNODE*HIDDIM];     // relu(x@Wf1+b)
__device__ float g_x0a[NNODE*OUTDIM];
__device__ float g_x0b[NNODE*OUTDIM];
__device__ float g_hid2[NNODE*FIN];       // relu(x0@G2+b-xm2[batch])
__device__ float g_seg1[NG*OUTDIM];
__device__ float g_seg2[NG*OUTDIM];
__device__ float g_cnt[NG];
__device__ float g_xm1[NG*OUTDIM];
__device__ float g_xm2[NG*FIN];
__device__ float g_bn[2*FIN];
__device__ float g_bna[FIN];
__device__ float g_bnb[FIN];

// ---------------- zero the accumulators each run ----------------
__global__ void k_zero() {
    int t = threadIdx.x;
    for (int i = t; i < NG*OUTDIM; i += 256) { g_seg1[i] = 0.f; g_seg2[i] = 0.f; }
    for (int i = t; i < NG;        i += 256) g_cnt[i] = 0.f;
    for (int i = t; i < 2*FIN;     i += 256) g_bn[i] = 0.f;
}

// ---------------- attention precompute ----------------
// blocks 0..511: T[h][i][:] ; blocks 512..515: r[h][:]
__global__ void k_pre1(const float* __restrict__ W, const float* __restrict__ b,
                       const float* __restrict__ Aa) {
    __shared__ float w[ATTD];
    int bid = blockIdx.x, t = threadIdx.x;
    if (bid < NHEADS*ATTD) {
        int h = bid >> 7, i = bid & 127;
        w[t] = W[(h*ATTD + i)*ATTD + t];
        __syncthreads();
        const float* Ah = Aa + h*ATTD*ATTD;
        float s = 0.f;
        #pragma unroll 4
        for (int k = 0; k < ATTD; k++) s += w[k] * Ah[k*ATTD + t];
        g_T[(h*ATTD + i)*ATTD + t] = s;
    } else {
        int h = bid - NHEADS*ATTD;
        w[t] = b[h*ATTD + t];
        __syncthreads();
        const float* Ah = Aa + h*ATTD*ATTD;
        float s = 0.f;
        #pragma unroll 4
        for (int k = 0; k < ATTD; k++) s += w[k] * Ah[k*ATTD + t];
        g_r[h*ATTD + t] = s;
    }
}

// M[i][j] = 0.25 * sum_h sum_k T[h][i][k] * W[h][j][k]
__global__ void k_pre2(const float* __restrict__ W) {
    __shared__ float Ts[NHEADS*ATTD];
    int i = blockIdx.x, t = threadIdx.x;
    for (int h = 0; h < NHEADS; h++) Ts[h*ATTD + t] = g_T[(h*ATTD + i)*ATTD + t];
    __syncthreads();
    float m = 0.f;
    for (int h = 0; h < NHEADS; h++) {
        const float* Wr = W + (size_t)(h*ATTD + t)*ATTD;
        const float* Th = Ts + h*ATTD;
        #pragma unroll 4
        for (int k = 0; k < ATTD; k++) m += Th[k] * Wr[k];
    }
    g_M[i*FIN + t] = 0.25f * m;
}

// u[j] = 0.25 sum_hk T[h][j][k] b[h][k] ; v[j] = 0.25 sum_hk r[h][k] W[h][j][k] ; c
__global__ void k_pre3(const float* __restrict__ W, const float* __restrict__ b) {
    __shared__ float bs[NHEADS*ATTD], rs[NHEADS*ATTD], red[128];
    int t = threadIdx.x;
    for (int i = t; i < NHEADS*ATTD; i += 128) { bs[i] = b[i]; rs[i] = g_r[i]; }
    __syncthreads();
    float u = 0.f, v = 0.f;
    for (int h = 0; h < NHEADS; h++) {
        const float* Tr = g_T + (size_t)(h*ATTD + t)*ATTD;
        const float* Wr = W   + (size_t)(h*ATTD + t)*ATTD;
        #pragma unroll 4
        for (int k = 0; k < ATTD; k++) {
            u += Tr[k] * bs[h*ATTD + k];
            v += rs[h*ATTD + k] * Wr[k];
        }
    }
    g_u[t] = 0.25f * u; g_v[t] = 0.25f * v;
    float pc = 0.f;
    for (int i = t; i < NHEADS*ATTD; i += 128) pc += rs[i] * bs[i];
    red[t] = pc; __syncthreads();
    if (t == 0) { float s = 0.f; for (int i = 0; i < 128; i++) s += red[i]; g_c[0] = 0.25f * s; }
}

// ---------------- generic tiled fp32 GEMM: C = act(A@B + bias - sub[batch]) ----------------
// block: 64 rows x BN cols, 256 threads, 4xTN micro-tile, K = BK (full)
template<int BK, int BN, bool RELU, bool BIAS, bool SUB>
__global__ void gemm_k(const float* __restrict__ A, int lda,
                       const float* __restrict__ B, int ldb,
                       const float* __restrict__ bias,
                       const float* __restrict__ sub, int ldsub,
                       const int* __restrict__ batch,
                       float* __restrict__ C, int ldc, int M) {
    constexpr int TN = BN / 16;
    extern __shared__ float sm[];
    float* As = sm;                      // [64][BK+4]
    float* Bs = sm + 64*(BK+4);          // [BK][BN]
    const int t = threadIdx.x;
    const int row0 = blockIdx.y * 64;
    const int col0 = blockIdx.x * BN;

    {
        constexpr int AV = 64*BK/4;
        #pragma unroll
        for (int i = t; i < AV; i += 256) {
            int r = i / (BK/4), k4 = (i % (BK/4)) * 4;
            float4 v = make_float4(0.f, 0.f, 0.f, 0.f);
            if (row0 + r < M) v = *(const float4*)(A + (size_t)(row0 + r)*lda + k4);
            *(float4*)(As + r*(BK+4) + k4) = v;
        }
        constexpr int BV = BK*BN/4;
        #pragma unroll
        for (int i = t; i < BV; i += 256) {
            int k = i / (BN/4), c4 = (i % (BN/4)) * 4;
            *(float4*)(Bs + k*BN + c4) = *(const float4*)(B + (size_t)k*ldb + col0 + c4);
        }
    }
    __syncthreads();

    const int tx = t & 15, ty = t >> 4;
    float acc[4][TN];
    #pragma unroll
    for (int j = 0; j < 4; j++)
        #pragma unroll
        for (int n = 0; n < TN; n++) acc[j][n] = 0.f;

    #pragma unroll 8
    for (int k = 0; k < BK; k++) {
        float a[4];
        #pragma unroll
        for (int j = 0; j < 4; j++) a[j] = As[(ty*4 + j)*(BK+4) + k];
        float bf[TN];
        #pragma unroll
        for (int n = 0; n < TN; n++) bf[n] = Bs[k*BN + tx*TN + n];
        #pragma unroll
        for (int j = 0; j < 4; j++)
            #pragma unroll
            for (int n = 0; n < TN; n++) acc[j][n] = fmaf(a[j], bf[n], acc[j][n]);
    }

    #pragma unroll
    for (int j = 0; j < 4; j++) {
        int gr = row0 + ty*4 + j;
        if (gr >= M) continue;
        const float* subrow = nullptr;
        if (SUB) subrow = sub + (size_t)batch[gr] * ldsub;
        #pragma unroll
        for (int n = 0; n < TN; n++) {
            int gc = col0 + tx*TN + n;
            float v = acc[j][n];
            if (BIAS) v += bias[gc];
            if (SUB)  v -= subrow[gc];
            if (RELU) v = fmaxf(v, 0.f);
            C[(size_t)gr*ldc + gc] = v;
        }
    }
}

// ---------------- p = x.u, q = x.v per node ----------------
__global__ void k_pq(const float* __restrict__ x) {
    int wid = (blockIdx.x * blockDim.x + threadIdx.x) >> 5;
    int l = threadIdx.x & 31;
    if (wid >= NNODE) return;
    float4 xv = *(const float4*)(x + (size_t)wid*FIN + l*4);
    float4 uu = *(const float4*)(g_u + l*4);
    float4 vv = *(const float4*)(g_v + l*4);
    float p = xv.x*uu.x + xv.y*uu.y + xv.z*uu.z + xv.w*uu.w;
    float q = xv.x*vv.x + xv.y*vv.y + xv.z*vv.z + xv.w*vv.w;
    #pragma unroll
    for (int o = 16; o; o >>= 1) {
        p += __shfl_xor_sync(0xffffffffu, p, o);
        q += __shfl_xor_sync(0xffffffffu, q, o);
    }
    if (l == 0) { g_p[wid] = p; g_q[wid] = q; }
}

// ---------------- edge attention: sigmoid(z[row].x[col] + p[row] + q[col] + c) ----------------
__global__ void k_att(const float* __restrict__ x, const int* __restrict__ ei,
                      float* __restrict__ out) {
    int wid = (blockIdx.x * blockDim.x + threadIdx.x) >> 5;
    int l = threadIdx.x & 31;
    if (wid >= NEDGE) return;
    int row = ei[wid], col = ei[NEDGE + wid];
    float4 zv = *(const float4*)(g_z + (size_t)row*FIN + l*4);
    float4 xv = *(const float4*)(x   + (size_t)col*FIN + l*4);
    float d = zv.x*xv.x + zv.y*xv.y + zv.z*xv.z + zv.w*xv.w;
    #pragma unroll
    for (int o = 16; o; o >>= 1) d += __shfl_xor_sync(0xffffffffu, d, o);
    if (l == 0) {
        float s = d + g_p[row] + g_q[col] + g_c[0];
        out[(size_t)NNODE*FIN + wid] = 1.f / (1.f + expf(-s));
    }
}

// ---------------- fv = hid@Wf2+b ; x0a = relu(repeat(fv,2)@Wl0 + b) ----------------
__global__ void k_fvl0(const float* __restrict__ W_f2, const float* __restrict__ b_f2,
                       const float* __restrict__ W_l0, const float* __restrict__ b_l0) {
    __shared__ float f2t[NFILT][HIDDIM];
    __shared__ float fold[NFILT][OUTDIM];
    __shared__ float bl0[OUTDIM], bf2[NFILT];
    int t = threadIdx.x;
    for (int i = t; i < HIDDIM*NFILT; i += 256) { int k = i / NFILT, j = i % NFILT; f2t[j][k] = W_f2[i]; }
    for (int i = t; i < NFILT*OUTDIM; i += 256) {
        int j = i / OUTDIM, o = i % OUTDIM;
        fold[j][o] = W_l0[(2*j)*OUTDIM + o] + W_l0[(2*j+1)*OUTDIM + o];
    }
    if (t < OUTDIM) bl0[t] = b_l0[t];
    if (t < NFILT)  bf2[t] = b_f2[t];
    __syncthreads();
    int w = t >> 5, l = t & 31;
    int n = blockIdx.x * 8 + w;
    if (n >= NNODE) return;
    float acc[NFILT];
    #pragma unroll
    for (int j = 0; j < NFILT; j++) acc[j] = 0.f;
    const float* hr = g_hid + (size_t)n*HIDDIM;
    #pragma unroll
    for (int it = 0; it < HIDDIM/32; it++) {
        int k = it*32 + l;
        float hv = hr[k];
        #pragma unroll
        for (int j = 0; j < NFILT; j++) acc[j] = fmaf(hv, f2t[j][k], acc[j]);
    }
    #pragma unroll
    for (int j = 0; j < NFILT; j++)
        #pragma unroll
        for (int o = 16; o; o >>= 1) acc[j] += __shfl_xor_sync(0xffffffffu, acc[j], o);
    float fv[NFILT];
    #pragma unroll
    for (int j = 0; j < NFILT; j++) fv[j] = acc[j] + bf2[j];
    #pragma unroll
    for (int rep = 0; rep < 2; rep++) {
        int o = l + 32*rep;
        float s = bl0[o];
        #pragma unroll
        for (int j = 0; j < NFILT; j++) s = fmaf(fv[j], fold[j][o], s);
        g_x0a[(size_t)n*OUTDIM + o] = fmaxf(s, 0.f);
    }
}

// ---------------- segment sum over sorted batch (run-length compressed atomics) ----------------
__global__ void k_seg(const float* __restrict__ v, const int* __restrict__ batch,
                      float* __restrict__ sum, int do_cnt) {
    int t = threadIdx.x;
    int f = t & 63, w = t >> 6;
    int r0 = blockIdx.x * 512;
    int rend = min(r0 + 512, NNODE);
    float acc = 0.f, ccnt = 0.f;
    int cur = -1;
    for (int r = r0 + w; r < rend; r += 4) {
        int g = __ldg(&batch[r]);
        if (g != cur) {
            if (cur >= 0) {
                atomicAdd(&sum[cur*64 + f], acc);
                if (do_cnt && f == 0) atomicAdd(&g_cnt[cur], ccnt);
            }
            acc = 0.f; ccnt = 0.f; cur = g;
        }
        acc += v[(size_t)r*64 + f];
        if (do_cnt && f == 0) ccnt += 1.f;
    }
    if (cur >= 0) {
        atomicAdd(&sum[cur*64 + f], acc);
        if (do_cnt && f == 0) atomicAdd(&g_cnt[cur], ccnt);
    }
}

// ---------------- xm1 = (seg1/cnt) @ L1 ----------------
__global__ void k_mean1(const float* __restrict__ L1) {
    __shared__ float mean[OUTDIM];
    int g = blockIdx.x, t = threadIdx.x; // 64 threads
    float c = fmaxf(g_cnt[g], 1.f);
    mean[t] = g_seg1[g*64 + t] / c;
    __syncthreads();
    float s = 0.f;
    #pragma unroll 4
    for (int k = 0; k < 64; k++) s += mean[k] * L1[k*64 + t];
    g_xm1[g*64 + t] = s;
}

// ---------------- xm2 = (seg2/cnt) @ L2 ----------------
__global__ void k_mean2(const float* __restrict__ L2) {
    __shared__ float mean[OUTDIM];
    int g = blockIdx.x, t = threadIdx.x; // 128 threads
    if (t < 64) mean[t] = g_seg2[g*64 + t] / fmaxf(g_cnt[g], 1.f);
    __syncthreads();
    float s = 0.f;
    #pragma unroll 4
    for (int k = 0; k < 64; k++) s += mean[k] * L2[k*128 + t];
    g_xm2[g*128 + t] = s;
}

// ---------------- BN sums over hid2 ----------------
__global__ void k_bnsum() {
    int t = threadIdx.x;
    int f = t & 127, w = t >> 7;
    int r0 = blockIdx.x * 512, rend = min(r0 + 512, NNODE);
    float s1 = 0.f, s2 = 0.f;
    for (int r = r0 + w; r < rend; r += 2) {
        float v = g_hid2[(size_t)r*128 + f];
        s1 += v; s2 += v*v;
    }
    __shared__ float sh[256];
    sh[t] = s1; __syncthreads();
    if (t < 128) atomicAdd(&g_bn[f], sh[t] + sh[t + 128]);
    __syncthreads();
    sh[t] = s2; __syncthreads();
    if (t < 128) atomicAdd(&g_bn[128 + f], sh[t] + sh[t + 128]);
}

__global__ void k_bnfin(const float* __restrict__ gamma, const float* __restrict__ beta) {
    int f = threadIdx.x;
    float mu = g_bn[f] / (float)NNODE;
    float var = g_bn[128 + f] / (float)NNODE - mu*mu;
    float a = gamma[f] * rsqrtf(var + 1e-5f);
    g_bna[f] = a;
    g_bnb[f] = beta[f] - mu*a;
}

// ---------------- out = x + hid2*a + b ----------------
__global__ void k_out(const float* __restrict__ x, float* __restrict__ out) {
    int i = blockIdx.x * blockDim.x + threadIdx.x;
    if (i >= NNODE*FIN/4) return;
    int f4 = (i & 31) * 4;
    float4 xv = ((const float4*)x)[i];
    float4 hv = ((const float4*)g_hid2)[i];
    float4 a  = *(const float4*)(g_bna + f4);
    float4 b  = *(const float4*)(g_bnb + f4);
    float4 o;
    o.x = xv.x + hv.x*a.x + b.x;
    o.y = xv.y + hv.y*a.y + b.y;
    o.z = xv.z + hv.z*a.z + b.z;
    o.w = xv.w + hv.w*a.w + b.w;
    ((float4*)out)[i] = o;
}

// ---------------- host launch ----------------
static inline int smem_bytes(int BK, int BN) { return (64*(BK+4) + BK*BN) * 4; }

extern "C" void kernel_launch(void* const* d_in, const int* in_sizes, int n_in,
                              void* d_out, int out_size) {
    const float* x      = (const float*)d_in[0];
    const int*   ei     = (const int*)  d_in[1];
    const int*   batch  = (const int*)  d_in[2];
    const float* W_f1   = (const float*)d_in[3];
    const float* b_f1   = (const float*)d_in[4];
    const float* W_f2   = (const float*)d_in[5];
    const float* b_f2   = (const float*)d_in[6];
    const float* W_l0   = (const float*)d_in[7];
    const float* b_l0   = (const float*)d_in[8];
    const float* G1     = (const float*)d_in[9];
    const float* b_g1   = (const float*)d_in[10];
    const float* L1     = (const float*)d_in[11];
    const float* G2     = (const float*)d_in[12];
    const float* b_g2   = (const float*)d_in[13];
    const float* L2     = (const float*)d_in[14];
    const float* gamma  = (const float*)d_in[15];
    const float* beta   = (const float*)d_in[16];
    const float* W_att  = (const float*)d_in[17];
    const float* b_att  = (const float*)d_in[18];
    const float* A_att  = (const float*)d_in[19];
    float* out = (float*)d_out;

    float *pM, *pz, *phid, *px0a, *px0b, *pxm1, *pxm2, *phid2, *pseg1, *pseg2;
    cudaGetSymbolAddress((void**)&pM,    g_M);
    cudaGetSymbolAddress((void**)&pz,    g_z);
    cudaGetSymbolAddress((void**)&phid,  g_hid);
    cudaGetSymbolAddress((void**)&px0a,  g_x0a);
    cudaGetSymbolAddress((void**)&px0b,  g_x0b);
    cudaGetSymbolAddress((void**)&pxm1,  g_xm1);
    cudaGetSymbolAddress((void**)&pxm2,  g_xm2);
    cudaGetSymbolAddress((void**)&phid2, g_hid2);
    cudaGetSymbolAddress((void**)&pseg1, g_seg1);
    cudaGetSymbolAddress((void**)&pseg2, g_seg2);

    cudaFuncSetAttribute(gemm_k<128,128,false,false,false>,
                         cudaFuncAttributeMaxDynamicSharedMemorySize, smem_bytes(128,128));
    cudaFuncSetAttribute(gemm_k<128,128,true,true,false>,
                         cudaFuncAttributeMaxDynamicSharedMemorySize, smem_bytes(128,128));
    cudaFuncSetAttribute(gemm_k<64,64,true,true,true>,
                         cudaFuncAttributeMaxDynamicSharedMemorySize, smem_bytes(64,64));
    cudaFuncSetAttribute(gemm_k<64,128,true,true,true>,
                         cudaFuncAttributeMaxDynamicSharedMemorySize, smem_bytes(64,128));

    const int rowBlocks = (NNODE + 63) / 64;   // 1563

    k_zero<<<1, 256>>>();
    k_pre1<<<NHEADS*ATTD + NHEADS, 128>>>(W_att, b_att, A_att);
    k_pre2<<<128, 128>>>(W_att);
    k_pre3<<<1, 128>>>(W_att, b_att);

    // z = x @ M
    gemm_k<128,128,false,false,false><<<dim3(1, rowBlocks), 256, smem_bytes(128,128)>>>(
        x, FIN, pM, FIN, nullptr, nullptr, 0, nullptr, pz, FIN, NNODE);
    k_pq<<<(NNODE*32 + 255)/256, 256>>>(x);
    k_att<<<(NEDGE*32 + 255)/256, 256>>>(x, ei, out);

    // hid = relu(x @ W_f1 + b_f1)
    gemm_k<128,128,true,true,false><<<dim3(2, rowBlocks), 256, smem_bytes(128,128)>>>(
        x, FIN, W_f1, HIDDIM, b_f1, nullptr, 0, nullptr, phid, HIDDIM, NNODE);
    k_fvl0<<<(NNODE + 7)/8, 256>>>(W_f2, b_f2, W_l0, b_l0);

    k_seg<<<(NNODE + 511)/512, 256>>>(px0a, batch, pseg1, 1);
    k_mean1<<<NG, 64>>>(L1);
    // x0b = relu(x0a @ G1 + b_g1 - xm1[batch])
    gemm_k<64,64,true,true,true><<<dim3(1, rowBlocks), 256, smem_bytes(64,64)>>>(
        px0a, OUTDIM, G1, OUTDIM, b_g1, pxm1, OUTDIM, batch, px0b, OUTDIM, NNODE);

    k_seg<<<(NNODE + 511)/512, 256>>>(px0b, batch, pseg2, 0);
    k_mean2<<<NG, 128>>>(L2);
    // hid2 = relu(x0b @ G2 + b_g2 - xm2[batch])
    gemm_k<64,128,true,true,true><<<dim3(1, rowBlocks), 256, smem_bytes(64,128)>>>(
        px0b, OUTDIM, G2, FIN, b_g2, pxm2, FIN, batch, phid2, FIN, NNODE);

    k_bnsum<<<(NNODE + 511)/512, 256>>>();
    k_bnfin<<<1, 128>>>(gamma, beta);
    k_out<<<(NNODE*FIN/4 + 255)/256, 256>>>(x, out);
}

// round 3
// speedup vs baseline: 1.1895x; 1.1895x over previous
#include <cuda_runtime.h>
#include <math.h>

#define NNODE 100000
#define NEDGE 200000
#define NG 64
#define FIN 128
#define NFILT 8
#define HIDDIM 256
#define OUTDIM 64
#define ATTD 128
#define NHEADS 4

// ---------------- scratch ----------------
__device__ float g_T[NHEADS*ATTD*ATTD];   // W_h @ A_h
__device__ float g_Wt[NHEADS*ATTD*ATTD];  // W transposed per head
__device__ float g_r[NHEADS*ATTD];        // b_h @ A_h
__device__ float g_M[FIN*FIN];            // 0.25 * sum_h W A W^T
__device__ float g_u[FIN];
__device__ float g_v[FIN];
__device__ float g_c[1];
__device__ float g_z[NNODE*FIN];          // x @ M
__device__ float g_p[NNODE];
__device__ float g_q[NNODE];
__device__ float g_fv[NNODE*NFILT];       // hid @ Wf2 (atomic)
__device__ float g_x0a[NNODE*OUTDIM];
__device__ float g_x0b[NNODE*OUTDIM];
__device__ float g_hid2[NNODE*FIN];
__device__ float g_seg1[NG*OUTDIM];
__device__ float g_seg2[NG*OUTDIM];
__device__ float g_cnt[NG];
__device__ float g_xm1[NG*OUTDIM];
__device__ float g_xm2[NG*FIN];
__device__ float g_bn[2*FIN];
__device__ float g_bna[FIN];
__device__ float g_bnb[FIN];

// ---------------- zero accumulators ----------------
__global__ void k_zero() {
    int i = blockIdx.x * 256 + threadIdx.x;
    if (i < NNODE*NFILT) g_fv[i] = 0.f;
    if (i < NG*OUTDIM) { g_seg1[i] = 0.f; g_seg2[i] = 0.f; }
    if (i < NG)        g_cnt[i] = 0.f;
    if (i < 2*FIN)     g_bn[i] = 0.f;
}

// ---------------- attention precompute ----------------
// blocks 0..511: T[h][i][:] = W[h][i][:] @ A[h] ; blocks 512..515: r[h][:]
__global__ void k_pre1(const float* __restrict__ W, const float* __restrict__ b,
                       const float* __restrict__ Aa) {
    __shared__ float w[ATTD];
    int bid = blockIdx.x, t = threadIdx.x;
    if (bid < NHEADS*ATTD) {
        int h = bid >> 7, i = bid & 127;
        w[t] = W[(h*ATTD + i)*ATTD + t];
        __syncthreads();
        const float* Ah = Aa + h*ATTD*ATTD;
        float s = 0.f;
        #pragma unroll 4
        for (int k = 0; k < ATTD; k++) s += w[k] * Ah[k*ATTD + t];
        g_T[(h*ATTD + i)*ATTD + t] = s;
    } else {
        int h = bid - NHEADS*ATTD;
        w[t] = b[h*ATTD + t];
        __syncthreads();
        const float* Ah = Aa + h*ATTD*ATTD;
        float s = 0.f;
        #pragma unroll 4
        for (int k = 0; k < ATTD; k++) s += w[k] * Ah[k*ATTD + t];
        g_r[h*ATTD + t] = s;
    }
}

// transpose W per head: Wt[h][k][j] = W[h][j][k]
__global__ void k_wt(const float* __restrict__ W) {
    __shared__ float tile[32][33];
    int h = blockIdx.z;
    int j0 = blockIdx.x * 32, k0 = blockIdx.y * 32;
    int tx = threadIdx.x, ty = threadIdx.y; // 32 x 8
    for (int r = ty; r < 32; r += 8)
        tile[r][tx] = W[(size_t)(h*ATTD + j0 + r)*ATTD + k0 + tx];
    __syncthreads();
    for (int r = ty; r < 32; r += 8)
        g_Wt[(size_t)(h*ATTD + k0 + r)*ATTD + j0 + tx] = tile[tx][r];
}

// M[i][j] = 0.25 * sum_h sum_k T[h][i][k] * Wt[h][k][j]   (coalesced in j)
__global__ void k_pre2() {
    __shared__ float Ts[NHEADS*ATTD];
    int i = blockIdx.x, j = threadIdx.x;
    #pragma unroll
    for (int h = 0; h < NHEADS; h++)
        Ts[h*ATTD + j] = g_T[(size_t)(h*ATTD + i)*ATTD + j];
    __syncthreads();
    float m = 0.f;
    #pragma unroll
    for (int h = 0; h < NHEADS; h++) {
        const float* Wth = g_Wt + (size_t)h*ATTD*ATTD;
        #pragma unroll 4
        for (int k = 0; k < ATTD; k++) m = fmaf(Ts[h*ATTD + k], Wth[k*ATTD + j], m);
    }
    g_M[i*FIN + j] = 0.25f * m;
}

// u[j], v[j], c with coalesced reads + warp reductions. grid = 129, block = 128.
__global__ void k_uvc(const float* __restrict__ W, const float* __restrict__ b) {
    __shared__ float red[8];
    int j = blockIdx.x, k = threadIdx.x;
    int wid = k >> 5, l = k & 31;
    if (j < FIN) {
        float u = 0.f, v = 0.f;
        #pragma unroll
        for (int h = 0; h < NHEADS; h++) {
            u += g_T[(size_t)(h*ATTD + j)*ATTD + k] * b[h*ATTD + k];
            v += g_r[h*ATTD + k] * W[(size_t)(h*ATTD + j)*ATTD + k];
        }
        #pragma unroll
        for (int o = 16; o; o >>= 1) {
            u += __shfl_xor_sync(0xffffffffu, u, o);
            v += __shfl_xor_sync(0xffffffffu, v, o);
        }
        if (l == 0) { red[wid] = u; red[4 + wid] = v; }
        __syncthreads();
        if (k == 0) g_u[j] = 0.25f * (red[0] + red[1] + red[2] + red[3]);
        if (k == 1) g_v[j] = 0.25f * (red[4] + red[5] + red[6] + red[7]);
    } else {
        float c = 0.f;
        for (int i = k; i < NHEADS*ATTD; i += 128) c += g_r[i] * b[i];
        #pragma unroll
        for (int o = 16; o; o >>= 1) c += __shfl_xor_sync(0xffffffffu, c, o);
        if (l == 0) red[wid] = c;
        __syncthreads();
        if (k == 0) g_c[0] = 0.25f * (red[0] + red[1] + red[2] + red[3]);
    }
}

// ---------------- tiled SGEMM: C = act(A@B + bias - sub[batch]) or fused fv ----------------
// BK=32 k-tiles, A staged transposed in smem, TM x TN micro-tiles, 256 threads.
template<int BM, int BN, int TM, int TN, bool RELU, bool BIAS, bool SUB, bool FV>
__global__ void __launch_bounds__(256)
gemm2(const float* __restrict__ A, int lda,
      const float* __restrict__ B, int ldb,
      const float* __restrict__ bias,
      const float* __restrict__ sub, int ldsub,
      const int* __restrict__ batch,
      float* __restrict__ C, int ldc, int M, int K,
      const float* __restrict__ Wf2, float* __restrict__ fvout) {
    constexpr int BK = 32;
    constexpr int TX = BN / TN, TY = BM / TM;
    static_assert(TX * TY == 256, "bad tile config");
    __shared__ float As[BK][BM];
    __shared__ float Bs[BK][BN];
    const int t = threadIdx.x;
    const int tx = t % TX, ty = t / TX;
    const int row0 = blockIdx.y * BM, col0 = blockIdx.x * BN;

    float acc[TM][TN] = {};

    const int ktiles = K / BK;
    for (int kt = 0; kt < ktiles; kt++) {
        // A: BM x BK, load float4 along K, store transposed
        #pragma unroll
        for (int i = t; i < BM*BK/4; i += 256) {
            int r = i / (BK/4);
            int kk = (i % (BK/4)) * 4;
            float4 v = make_float4(0.f, 0.f, 0.f, 0.f);
            int gr = row0 + r;
            if (gr < M) v = *(const float4*)(A + (size_t)gr*lda + kt*BK + kk);
            As[kk+0][r] = v.x; As[kk+1][r] = v.y; As[kk+2][r] = v.z; As[kk+3][r] = v.w;
        }
        // B: BK x BN, direct float4
        #pragma unroll
        for (int i = t; i < BK*BN/4; i += 256) {
            int k = i / (BN/4);
            int n = (i % (BN/4)) * 4;
            *(float4*)(&Bs[k][n]) = *(const float4*)(B + (size_t)(kt*BK + k)*ldb + col0 + n);
        }
        __syncthreads();
        #pragma unroll 8
        for (int k = 0; k < BK; k++) {
            float a[TM], bf[TN];
            #pragma unroll
            for (int m = 0; m < TM; m++) a[m] = As[k][ty*TM + m];
            #pragma unroll
            for (int n = 0; n < TN; n++) bf[n] = Bs[k][tx*TN + n];
            #pragma unroll
            for (int m = 0; m < TM; m++)
                #pragma unroll
                for (int n = 0; n < TN; n++) acc[m][n] = fmaf(a[m], bf[n], acc[m][n]);
        }
        __syncthreads();
    }

    if (FV) {
        // fv_partial[m][j] = sum_n relu(acc+bias) * Wf2[gc][j]; reduce over TX lanes.
        float fvacc[TM][NFILT] = {};
        #pragma unroll
        for (int n = 0; n < TN; n++) {
            int gc = col0 + tx*TN + n;
            float w[8];
            *(float4*)(w)     = *(const float4*)(Wf2 + gc*NFILT);
            *(float4*)(w + 4) = *(const float4*)(Wf2 + gc*NFILT + 4);
            float bb = bias[gc];
            #pragma unroll
            for (int m = 0; m < TM; m++) {
                float v = fmaxf(acc[m][n] + bb, 0.f);
                #pragma unroll
                for (int j = 0; j < NFILT; j++) fvacc[m][j] = fmaf(v, w[j], fvacc[m][j]);
            }
        }
        #pragma unroll
        for (int m = 0; m < TM; m++) {
            int gr = row0 + ty*TM + m;
            #pragma unroll
            for (int j = 0; j < NFILT; j++) {
                float s = fvacc[m][j];
                #pragma unroll
                for (int o = TX/2; o; o >>= 1) s += __shfl_xor_sync(0xffffffffu, s, o);
                if (tx == 0 && gr < M) atomicAdd(&fvout[(size_t)gr*NFILT + j], s);
            }
        }
        return;
    }

    #pragma unroll
    for (int m = 0; m < TM; m++) {
        int gr = row0 + ty*TM + m;
        if (gr >= M) continue;
        const float* subrow = nullptr;
        if (SUB) subrow = sub + (size_t)batch[gr] * ldsub;
        #pragma unroll
        for (int n = 0; n < TN; n++) {
            int gc = col0 + tx*TN + n;
            float v = acc[m][n];
            if (BIAS) v += bias[gc];
            if (SUB)  v -= subrow[gc];
            if (RELU) v = fmaxf(v, 0.f);
            C[(size_t)gr*ldc + gc] = v;
        }
    }
}

// ---------------- p = x.u, q = x.v ----------------
__global__ void k_pq(const float* __restrict__ x) {
    int wid = (blockIdx.x * blockDim.x + threadIdx.x) >> 5;
    int l = threadIdx.x & 31;
    if (wid >= NNODE) return;
    float4 xv = *(const float4*)(x + (size_t)wid*FIN + l*4);
    float4 uu = *(const float4*)(g_u + l*4);
    float4 vv = *(const float4*)(g_v + l*4);
    float p = xv.x*uu.x + xv.y*uu.y + xv.z*uu.z + xv.w*uu.w;
    float q = xv.x*vv.x + xv.y*vv.y + xv.z*vv.z + xv.w*vv.w;
    #pragma unroll
    for (int o = 16; o; o >>= 1) {
        p += __shfl_xor_sync(0xffffffffu, p, o);
        q += __shfl_xor_sync(0xffffffffu, q, o);
    }
    if (l == 0) { g_p[wid] = p; g_q[wid] = q; }
}

// ---------------- edge attention ----------------
__global__ void k_att(const float* __restrict__ x, const int* __restrict__ ei,
                      float* __restrict__ out) {
    int wid = (blockIdx.x * blockDim.x + threadIdx.x) >> 5;
    int l = threadIdx.x & 31;
    if (wid >= NEDGE) return;
    int row = ei[wid], col = ei[NEDGE + wid];
    float4 zv = *(const float4*)(g_z + (size_t)row*FIN + l*4);
    float4 xv = *(const float4*)(x   + (size_t)col*FIN + l*4);
    float d = zv.x*xv.x + zv.y*xv.y + zv.z*xv.z + zv.w*xv.w;
    #pragma unroll
    for (int o = 16; o; o >>= 1) d += __shfl_xor_sync(0xffffffffu, d, o);
    if (l == 0) {
        float s = d + g_p[row] + g_q[col] + g_c[0];
        out[(size_t)NNODE*FIN + wid] = 1.f / (1.f + expf(-s));
    }
}

// ---------------- x0a = relu((fv+b_f2) @ fold + b_l0), warp per node ----------------
__global__ void k_x0a(const float* __restrict__ b_f2, const float* __restrict__ W_l0,
                      const float* __restrict__ b_l0) {
    __shared__ float fold[NFILT][OUTDIM];
    __shared__ float bl0[OUTDIM], bf2[NFILT];
    int t = threadIdx.x;
    for (int i = t; i < NFILT*OUTDIM; i += 256) {
        int j = i / OUTDIM, o = i % OUTDIM;
        fold[j][o] = W_l0[(2*j)*OUTDIM + o] + W_l0[(2*j+1)*OUTDIM + o];
    }
    if (t < OUTDIM) bl0[t] = b_l0[t];
    if (t < NFILT)  bf2[t] = b_f2[t];
    __syncthreads();
    int w = t >> 5, l = t & 31;
    int n = blockIdx.x * 8 + w;
    if (n >= NNODE) return;
    float fv[8];
    *(float4*)(fv)     = *(const float4*)(g_fv + (size_t)n*NFILT);
    *(float4*)(fv + 4) = *(const float4*)(g_fv + (size_t)n*NFILT + 4);
    #pragma unroll
    for (int j = 0; j < NFILT; j++) fv[j] += bf2[j];
    #pragma unroll
    for (int rep = 0; rep < 2; rep++) {
        int o = l + 32*rep;
        float s = bl0[o];
        #pragma unroll
        for (int j = 0; j < NFILT; j++) s = fmaf(fv[j], fold[j][o], s);
        g_x0a[(size_t)n*OUTDIM + o] = fmaxf(s, 0.f);
    }
}

// ---------------- segment sum over sorted batch ----------------
__global__ void k_seg(const float* __restrict__ v, const int* __restrict__ batch,
                      float* __restrict__ sum, int do_cnt) {
    int t = threadIdx.x;
    int f = t & 63, w = t >> 6;
    int r0 = blockIdx.x * 512;
    int rend = min(r0 + 512, NNODE);
    float acc = 0.f, ccnt = 0.f;
    int cur = -1;
    for (int r = r0 + w; r < rend; r += 4) {
        int g = __ldg(&batch[r]);
        if (g != cur) {
            if (cur >= 0) {
                atomicAdd(&sum[cur*64 + f], acc);
                if (do_cnt && f == 0) atomicAdd(&g_cnt[cur], ccnt);
            }
            acc = 0.f; ccnt = 0.f; cur = g;
        }
        acc += v[(size_t)r*64 + f];
        if (do_cnt && f == 0) ccnt += 1.f;
    }
    if (cur >= 0) {
        atomicAdd(&sum[cur*64 + f], acc);
        if (do_cnt && f == 0) atomicAdd(&g_cnt[cur], ccnt);
    }
}

__global__ void k_mean1(const float* __restrict__ L1) {
    __shared__ float mean[OUTDIM];
    int g = blockIdx.x, t = threadIdx.x; // 64 threads
    float c = fmaxf(g_cnt[g], 1.f);
    mean[t] = g_seg1[g*64 + t] / c;
    __syncthreads();
    float s = 0.f;
    #pragma unroll 4
    for (int k = 0; k < 64; k++) s += mean[k] * L1[k*64 + t];
    g_xm1[g*64 + t] = s;
}

__global__ void k_mean2(const float* __restrict__ L2) {
    __shared__ float mean[OUTDIM];
    int g = blockIdx.x, t = threadIdx.x; // 128 threads
    if (t < 64) mean[t] = g_seg2[g*64 + t] / fmaxf(g_cnt[g], 1.f);
    __syncthreads();
    float s = 0.f;
    #pragma unroll 4
    for (int k = 0; k < 64; k++) s += mean[k] * L2[k*128 + t];
    g_xm2[g*128 + t] = s;
}

// ---------------- BN ----------------
__global__ void k_bnsum() {
    int t = threadIdx.x;
    int f = t & 127, w = t >> 7;
    int r0 = blockIdx.x * 512, rend = min(r0 + 512, NNODE);
    float s1 = 0.f, s2 = 0.f;
    for (int r = r0 + w; r < rend; r += 2) {
        float v = g_hid2[(size_t)r*128 + f];
        s1 += v; s2 += v*v;
    }
    __shared__ float sh[256];
    sh[t] = s1; __syncthreads();
    if (t < 128) atomicAdd(&g_bn[f], sh[t] + sh[t + 128]);
    __syncthreads();
    sh[t] = s2; __syncthreads();
    if (t < 128) atomicAdd(&g_bn[128 + f], sh[t] + sh[t + 128]);
}

__global__ void k_bnfin(const float* __restrict__ gamma, const float* __restrict__ beta) {
    int f = threadIdx.x;
    float mu = g_bn[f] / (float)NNODE;
    float var = g_bn[128 + f] / (float)NNODE - mu*mu;
    float a = gamma[f] * rsqrtf(var + 1e-5f);
    g_bna[f] = a;
    g_bnb[f] = beta[f] - mu*a;
}

__global__ void k_out(const float* __restrict__ x, float* __restrict__ out) {
    int i = blockIdx.x * blockDim.x + threadIdx.x;
    if (i >= NNODE*FIN/4) return;
    int f4 = (i & 31) * 4;
    float4 xv = ((const float4*)x)[i];
    float4 hv = ((const float4*)g_hid2)[i];
    float4 a  = *(const float4*)(g_bna + f4);
    float4 b  = *(const float4*)(g_bnb + f4);
    float4 o;
    o.x = xv.x + hv.x*a.x + b.x;
    o.y = xv.y + hv.y*a.y + b.y;
    o.z = xv.z + hv.z*a.z + b.z;
    o.w = xv.w + hv.w*a.w + b.w;
    ((float4*)out)[i] = o;
}

// ---------------- host launch ----------------
extern "C" void kernel_launch(void* const* d_in, const int* in_sizes, int n_in,
                              void* d_out, int out_size) {
    const float* x      = (const float*)d_in[0];
    const int*   ei     = (const int*)  d_in[1];
    const int*   batch  = (const int*)  d_in[2];
    const float* W_f1   = (const float*)d_in[3];
    const float* b_f1   = (const float*)d_in[4];
    const float* W_f2   = (const float*)d_in[5];
    const float* b_f2   = (const float*)d_in[6];
    const float* W_l0   = (const float*)d_in[7];
    const float* b_l0   = (const float*)d_in[8];
    const float* G1     = (const float*)d_in[9];
    const float* b_g1   = (const float*)d_in[10];
    const float* L1     = (const float*)d_in[11];
    const float* G2     = (const float*)d_in[12];
    const float* b_g2   = (const float*)d_in[13];
    const float* L2     = (const float*)d_in[14];
    const float* gamma  = (const float*)d_in[15];
    const float* beta   = (const float*)d_in[16];
    const float* W_att  = (const float*)d_in[17];
    const float* b_att  = (const float*)d_in[18];
    const float* A_att  = (const float*)d_in[19];
    float* out = (float*)d_out;

    float *pM, *pz, *pfv, *px0a, *px0b, *pxm1, *pxm2, *phid2, *pseg1, *pseg2;
    cudaGetSymbolAddress((void**)&pM,    g_M);
    cudaGetSymbolAddress((void**)&pz,    g_z);
    cudaGetSymbolAddress((void**)&pfv,   g_fv);
    cudaGetSymbolAddress((void**)&px0a,  g_x0a);
    cudaGetSymbolAddress((void**)&px0b,  g_x0b);
    cudaGetSymbolAddress((void**)&pxm1,  g_xm1);
    cudaGetSymbolAddress((void**)&pxm2,  g_xm2);
    cudaGetSymbolAddress((void**)&phid2, g_hid2);
    cudaGetSymbolAddress((void**)&pseg1, g_seg1);
    cudaGetSymbolAddress((void**)&pseg2, g_seg2);

    const int rb128 = (NNODE + 127) / 128;  // 782
    const int rb64  = (NNODE + 63) / 64;    // 1563

    k_zero<<<(NNODE*NFILT + 255)/256, 256>>>();
    k_pre1<<<NHEADS*ATTD + NHEADS, 128>>>(W_att, b_att, A_att);
    k_wt<<<dim3(4, 4, 4), dim3(32, 8)>>>(W_att);
    k_pre2<<<128, 128>>>();
    k_uvc<<<FIN + 1, 128>>>(W_att, b_att);

    // z = x @ M   (128x128x128 tiles)
    gemm2<128,128,8,8,false,false,false,false><<<dim3(1, rb128), 256>>>(
        x, FIN, pM, FIN, nullptr, nullptr, 0, nullptr, pz, FIN, NNODE, FIN, nullptr, nullptr);
    k_pq<<<(NNODE*32 + 255)/256, 256>>>(x);
    k_att<<<(NEDGE*32 + 255)/256, 256>>>(x, ei, out);

    // fv += relu(x @ W_f1 + b_f1) @ W_f2  (fused, hid never materialized)
    gemm2<64,128,4,8,true,true,false,true><<<dim3(2, rb64), 256>>>(
        x, FIN, W_f1, HIDDIM, b_f1, nullptr, 0, nullptr, nullptr, 0, NNODE, FIN, W_f2, pfv);
    k_x0a<<<(NNODE + 7)/8, 256>>>(b_f2, W_l0, b_l0);

    k_seg<<<(NNODE + 511)/512, 256>>>(px0a, batch, pseg1, 1);
    k_mean1<<<NG, 64>>>(L1);
    // x0b = relu(x0a @ G1 + b_g1 - xm1[batch])
    gemm2<128,64,4,8,true,true,true,false><<<dim3(1, rb128), 256>>>(
        px0a, OUTDIM, G1, OUTDIM, b_g1, pxm1, OUTDIM, batch, px0b, OUTDIM, NNODE, OUTDIM, nullptr, nullptr);

    k_seg<<<(NNODE + 511)/512, 256>>>(px0b, batch, pseg2, 0);
    k_mean2<<<NG, 128>>>(L2);
    // hid2 = relu(x0b @ G2 + b_g2 - xm2[batch])
    gemm2<128,128,8,8,true,true,true,false><<<dim3(1, rb128), 256>>>(
        px0b, OUTDIM, G2, FIN, b_g2, pxm2, FIN, batch, phid2, FIN, NNODE, OUTDIM, nullptr, nullptr);

    k_bnsum<<<(NNODE + 511)/512, 256>>>();
    k_bnfin<<<1, 128>>>(gamma, beta);
    k_out<<<(NNODE*FIN/4 + 255)/256, 256>>>(x, out);
}

// round 6
// speedup vs baseline: 1.3656x; 1.1480x over previous
#include <cuda_runtime.h>
#include <stdint.h>
#include <stddef.h>
#include <math.h>

#define NNODE 100000
#define NEDGE 200000
#define NG 64
#define FIN 128
#define NFILT 8
#define HIDDIM 256
#define OUTDIM 64
#define ATTD 128
#define NHEADS 4

// ---------------- scratch ----------------
__device__ float g_T[NHEADS*ATTD*ATTD];   // W_h @ A_h
__device__ float g_r[NHEADS*ATTD];        // b_h @ A_h
__device__ float g_M[FIN*FIN];            // 0.25 * sum_h W A W^T (atomic)
__device__ float g_u[FIN];
__device__ float g_v[FIN];
__device__ float g_c[1];
__device__ float g_z[NNODE*FIN];          // x @ M
__device__ float g_p[NNODE];
__device__ float g_q[NNODE];
__device__ float g_fv[NNODE*NFILT];       // hid @ Wf2 (atomic)
__device__ float g_x0a[NNODE*OUTDIM];
__device__ float g_x0b[NNODE*OUTDIM];
__device__ float g_hid2[NNODE*FIN];
__device__ float g_seg1[NG*OUTDIM];
__device__ float g_seg2[NG*OUTDIM];
__device__ float g_cnt[NG];
__device__ float g_xm1[NG*OUTDIM];
__device__ float g_xm2[NG*FIN];
__device__ float g_bn[2*FIN];
__device__ float g_bna[FIN];
__device__ float g_bnb[FIN];

__device__ __forceinline__ uint32_t f2tf32(float f) {
    uint32_t u;
    asm("cvt.rna.tf32.f32 %0, %1;" : "=r"(u) : "f"(f));
    return u;
}

__device__ __forceinline__ void mma_tf32(float c[4], const uint32_t a[4], const uint32_t b[2]) {
    asm volatile("mma.sync.aligned.m16n8k8.row.col.f32.tf32.tf32.f32 "
                 "{%0,%1,%2,%3}, {%4,%5,%6,%7}, {%8,%9}, {%0,%1,%2,%3};\n"
                 : "+f"(c[0]), "+f"(c[1]), "+f"(c[2]), "+f"(c[3])
                 : "r"(a[0]), "r"(a[1]), "r"(a[2]), "r"(a[3]), "r"(b[0]), "r"(b[1]));
}

// ---------------- zero accumulators ----------------
__global__ void k_zero() {
    int i = blockIdx.x * 256 + threadIdx.x;
    if (i < NNODE*NFILT) g_fv[i] = 0.f;
    if (i < FIN*FIN)   g_M[i] = 0.f;
    if (i < NG*OUTDIM) { g_seg1[i] = 0.f; g_seg2[i] = 0.f; }
    if (i < NG)        g_cnt[i] = 0.f;
    if (i < 2*FIN)     g_bn[i] = 0.f;
}

// ---------------- attention precompute ----------------
__global__ void k_pre1(const float* __restrict__ W, const float* __restrict__ b,
                       const float* __restrict__ Aa) {
    __shared__ float w[ATTD];
    int bid = blockIdx.x, t = threadIdx.x;
    if (bid < NHEADS*ATTD) {
        int h = bid >> 7, i = bid & 127;
        w[t] = W[(h*ATTD + i)*ATTD + t];
        __syncthreads();
        const float* Ah = Aa + h*ATTD*ATTD;
        float s = 0.f;
        #pragma unroll 4
        for (int k = 0; k < ATTD; k++) s += w[k] * Ah[k*ATTD + t];
        g_T[(h*ATTD + i)*ATTD + t] = s;
    } else {
        int h = bid - NHEADS*ATTD;
        w[t] = b[h*ATTD + t];
        __syncthreads();
        const float* Ah = Aa + h*ATTD*ATTD;
        float s = 0.f;
        #pragma unroll 4
        for (int k = 0; k < ATTD; k++) s += w[k] * Ah[k*ATTD + t];
        g_r[h*ATTD + t] = s;
    }
}

// M += 0.25 * T_h @ W_h^T  — NT GEMM, 32x32 tile per block, grid (4,4,4=head)
// smem stride 36 (multiple of 4) so float4 stores stay 16B-aligned.
__global__ void __launch_bounds__(256) k_mgemm(const float* __restrict__ W) {
    __shared__ float Tt[32][36], Ws[32][36];
    int it = blockIdx.x * 32, jt = blockIdx.y * 32, h = blockIdx.z;
    int t = threadIdx.x;
    int tx = t & 15, ty = t >> 4;  // 16x16, 2x2 micro
    float acc[2][2] = {};
    for (int kt = 0; kt < ATTD; kt += 32) {
        int r = t >> 3, k4 = (t & 7) << 2;
        *(float4*)&Tt[r][k4] = *(const float4*)(g_T + (size_t)(h*ATTD + it + r)*ATTD + kt + k4);
        *(float4*)&Ws[r][k4] = *(const float4*)(W   + (size_t)(h*ATTD + jt + r)*ATTD + kt + k4);
        __syncthreads();
        #pragma unroll 8
        for (int k = 0; k < 32; k++) {
            float a0 = Tt[ty*2][k], a1 = Tt[ty*2+1][k];
            float b0 = Ws[tx*2][k], b1 = Ws[tx*2+1][k];
            acc[0][0] = fmaf(a0, b0, acc[0][0]);
            acc[0][1] = fmaf(a0, b1, acc[0][1]);
            acc[1][0] = fmaf(a1, b0, acc[1][0]);
            acc[1][1] = fmaf(a1, b1, acc[1][1]);
        }
        __syncthreads();
    }
    #pragma unroll
    for (int i = 0; i < 2; i++)
        #pragma unroll
        for (int j = 0; j < 2; j++)
            atomicAdd(&g_M[(it + ty*2 + i)*FIN + jt + tx*2 + j], 0.25f * acc[i][j]);
}

// u[j], v[j], c — coalesced + warp reductions
__global__ void k_uvc(const float* __restrict__ W, const float* __restrict__ b) {
    __shared__ float red[8];
    int j = blockIdx.x, k = threadIdx.x;
    int wid = k >> 5, l = k & 31;
    if (j < FIN) {
        float u = 0.f, v = 0.f;
        #pragma unroll
        for (int h = 0; h < NHEADS; h++) {
            u += g_T[(size_t)(h*ATTD + j)*ATTD + k] * b[h*ATTD + k];
            v += g_r[h*ATTD + k] * W[(size_t)(h*ATTD + j)*ATTD + k];
        }
        #pragma unroll
        for (int o = 16; o; o >>= 1) {
            u += __shfl_xor_sync(0xffffffffu, u, o);
            v += __shfl_xor_sync(0xffffffffu, v, o);
        }
        if (l == 0) { red[wid] = u; red[4 + wid] = v; }
        __syncthreads();
        if (k == 0) g_u[j] = 0.25f * (red[0] + red[1] + red[2] + red[3]);
        if (k == 1) g_v[j] = 0.25f * (red[4] + red[5] + red[6] + red[7]);
    } else {
        float c = 0.f;
        for (int i = k; i < NHEADS*ATTD; i += 128) c += g_r[i] * b[i];
        #pragma unroll
        for (int o = 16; o; o >>= 1) c += __shfl_xor_sync(0xffffffffu, c, o);
        if (l == 0) red[wid] = c;
        __syncthreads();
        if (k == 0) g_c[0] = 0.25f * (red[0] + red[1] + red[2] + red[3]);
    }
}

// ================= tf32 tensor-core GEMMs (K = 128 fixed) =================
// BM=128, BN=64, 256 threads = 8 warps in 4(M) x 2(N); warp tile 32x32
// = 2(m16) x 4(n8) mma tiles. Full-K smem staging.
#define AS_STRIDE 132
#define BS_STRIDE 72
#define SM_AS (128*AS_STRIDE)
#define SM_BS (128*BS_STRIDE)

// z = A @ B  (A: M x 128, B: 128 x 128, col block of 64)
__global__ void __launch_bounds__(256) zgemm_tf32(const float* __restrict__ A,
                                                  const float* __restrict__ B,
                                                  float* __restrict__ C, int M) {
    extern __shared__ uint32_t smbuf[];
    uint32_t (*As)[AS_STRIDE] = (uint32_t(*)[AS_STRIDE])smbuf;
    uint32_t (*Bs)[BS_STRIDE] = (uint32_t(*)[BS_STRIDE])(smbuf + SM_AS);
    const int t = threadIdx.x;
    const int row0 = blockIdx.y * 128, col0 = blockIdx.x * 64;

    #pragma unroll
    for (int i = t; i < 128*32; i += 256) {
        int r = i >> 5, k4 = (i & 31) << 2;
        float4 v = make_float4(0.f, 0.f, 0.f, 0.f);
        if (row0 + r < M) v = *(const float4*)(A + (size_t)(row0 + r)*FIN + k4);
        As[r][k4+0] = f2tf32(v.x); As[r][k4+1] = f2tf32(v.y);
        As[r][k4+2] = f2tf32(v.z); As[r][k4+3] = f2tf32(v.w);
    }
    #pragma unroll
    for (int i = t; i < 128*16; i += 256) {
        int k = i >> 4, n4 = (i & 15) << 2;
        float4 v = *(const float4*)(B + (size_t)k*FIN + col0 + n4);
        Bs[k][n4+0] = f2tf32(v.x); Bs[k][n4+1] = f2tf32(v.y);
        Bs[k][n4+2] = f2tf32(v.z); Bs[k][n4+3] = f2tf32(v.w);
    }
    __syncthreads();

    const int wid = t >> 5, lane = t & 31;
    const int wm = (wid & 3) * 32, wn = (wid >> 2) * 32;
    const int g = lane >> 2, tg = lane & 3;

    float acc[2][4][4] = {};
    #pragma unroll
    for (int ko = 0; ko < 16; ko++) {
        int k0 = ko * 8;
        uint32_t a[2][4], b[4][2];
        #pragma unroll
        for (int mt = 0; mt < 2; mt++) {
            int r = wm + mt*16 + g;
            a[mt][0] = As[r][k0 + tg];
            a[mt][1] = As[r + 8][k0 + tg];
            a[mt][2] = As[r][k0 + tg + 4];
            a[mt][3] = As[r + 8][k0 + tg + 4];
        }
        #pragma unroll
        for (int nt = 0; nt < 4; nt++) {
            int n = wn + nt*8 + g;
            b[nt][0] = Bs[k0 + tg][n];
            b[nt][1] = Bs[k0 + tg + 4][n];
        }
        #pragma unroll
        for (int mt = 0; mt < 2; mt++)
            #pragma unroll
            for (int nt = 0; nt < 4; nt++)
                mma_tf32(acc[mt][nt], a[mt], b[nt]);
    }

    #pragma unroll
    for (int mt = 0; mt < 2; mt++) {
        int r = row0 + wm + mt*16 + g;
        #pragma unroll
        for (int nt = 0; nt < 4; nt++) {
            int c = col0 + wn + nt*8 + 2*tg;
            if (r < M)     *(float2*)(C + (size_t)r*FIN + c)     = make_float2(acc[mt][nt][0], acc[mt][nt][1]);
            if (r + 8 < M) *(float2*)(C + (size_t)(r+8)*FIN + c) = make_float2(acc[mt][nt][2], acc[mt][nt][3]);
        }
    }
}

// fv += relu(A @ W_f1 + b_f1) @ W_f2 — hid never materialized.
__global__ void __launch_bounds__(256) fvgemm_tf32(const float* __restrict__ A,
                                                   const float* __restrict__ Wf1,
                                                   const float* __restrict__ bf1,
                                                   const float* __restrict__ Wf2,
                                                   float* __restrict__ fvout, int M) {
    extern __shared__ uint32_t smbuf[];
    uint32_t (*As)[AS_STRIDE] = (uint32_t(*)[AS_STRIDE])smbuf;
    uint32_t (*Bs)[BS_STRIDE] = (uint32_t(*)[BS_STRIDE])(smbuf + SM_AS);
    float* Wf2s = (float*)(smbuf + SM_AS + SM_BS);   // [64][8]
    float* bf1s = Wf2s + 64*8;                       // [64]
    const int t = threadIdx.x;
    const int row0 = blockIdx.y * 128, col0 = blockIdx.x * 64;

    #pragma unroll
    for (int i = t; i < 128*32; i += 256) {
        int r = i >> 5, k4 = (i & 31) << 2;
        float4 v = make_float4(0.f, 0.f, 0.f, 0.f);
        if (row0 + r < M) v = *(const float4*)(A + (size_t)(row0 + r)*FIN + k4);
        As[r][k4+0] = f2tf32(v.x); As[r][k4+1] = f2tf32(v.y);
        As[r][k4+2] = f2tf32(v.z); As[r][k4+3] = f2tf32(v.w);
    }
    #pragma unroll
    for (int i = t; i < 128*16; i += 256) {
        int k = i >> 4, n4 = (i & 15) << 2;
        float4 v = *(const float4*)(Wf1 + (size_t)k*HIDDIM + col0 + n4);
        Bs[k][n4+0] = f2tf32(v.x); Bs[k][n4+1] = f2tf32(v.y);
        Bs[k][n4+2] = f2tf32(v.z); Bs[k][n4+3] = f2tf32(v.w);
    }
    if (t < 128) {  // Wf2 rows col0..col0+63 (8 floats each) + bias
        int r = t >> 1, half = t & 1;
        *(float4*)(Wf2s + r*8 + half*4) = *(const float4*)(Wf2 + (size_t)(col0 + r)*NFILT + half*4);
        if (half == 0) bf1s[r] = bf1[col0 + r];
    }
    __syncthreads();

    const int wid = t >> 5, lane = t & 31;
    const int wm = (wid & 3) * 32, wnid = wid >> 2, wn = wnid * 32;
    const int g = lane >> 2, tg = lane & 3;

    float acc[2][4][4] = {};
    #pragma unroll
    for (int ko = 0; ko < 16; ko++) {
        int k0 = ko * 8;
        uint32_t a[2][4], b[4][2];
        #pragma unroll
        for (int mt = 0; mt < 2; mt++) {
            int r = wm + mt*16 + g;
            a[mt][0] = As[r][k0 + tg];
            a[mt][1] = As[r + 8][k0 + tg];
            a[mt][2] = As[r][k0 + tg + 4];
            a[mt][3] = As[r + 8][k0 + tg + 4];
        }
        #pragma unroll
        for (int nt = 0; nt < 4; nt++) {
            int n = wn + nt*8 + g;
            b[nt][0] = Bs[k0 + tg][n];
            b[nt][1] = Bs[k0 + tg + 4][n];
        }
        #pragma unroll
        for (int mt = 0; mt < 2; mt++)
            #pragma unroll
            for (int nt = 0; nt < 4; nt++)
                mma_tf32(acc[mt][nt], a[mt], b[nt]);
    }

    // epilogue: fvacc[4 rows][8 filt]
    float fvacc[4][NFILT] = {};
    #pragma unroll
    for (int mt = 0; mt < 2; mt++) {
        #pragma unroll
        for (int nt = 0; nt < 4; nt++) {
            int nA = wn + nt*8 + 2*tg, nB = nA + 1;
            float bA = bf1s[nA], bB = bf1s[nB];
            const float* wA = Wf2s + nA*NFILT;
            const float* wB = Wf2s + nB*NFILT;
            float v00 = fmaxf(acc[mt][nt][0] + bA, 0.f);
            float v01 = fmaxf(acc[mt][nt][1] + bB, 0.f);
            float v10 = fmaxf(acc[mt][nt][2] + bA, 0.f);
            float v11 = fmaxf(acc[mt][nt][3] + bB, 0.f);
            #pragma unroll
            for (int j = 0; j < NFILT; j++) {
                fvacc[mt*2+0][j] += v00*wA[j] + v01*wB[j];
                fvacc[mt*2+1][j] += v10*wA[j] + v11*wB[j];
            }
        }
    }
    // reduce over the 4 lanes of each quad (sum over the warp's 32 n-cols)
    #pragma unroll
    for (int ridx = 0; ridx < 4; ridx++)
        #pragma unroll
        for (int j = 0; j < NFILT; j++) {
            float s = fvacc[ridx][j];
            s += __shfl_xor_sync(0xffffffffu, s, 1);
            s += __shfl_xor_sync(0xffffffffu, s, 2);
            fvacc[ridx][j] = s;
        }
    // pair-reduce the two warpN halves through smem, then atomics from half 0
    __syncthreads();
    float* red = (float*)Bs;   // [128 rows][8]
    if (wnid == 1 && tg == 0) {
        #pragma unroll
        for (int ridx = 0; ridx < 4; ridx++) {
            int rl = wm + (ridx >> 1)*16 + (ridx & 1)*8 + g;
            #pragma unroll
            for (int j = 0; j < NFILT; j++) red[rl*NFILT + j] = fvacc[ridx][j];
        }
    }
    __syncthreads();
    if (wnid == 0 && tg == 0) {
        #pragma unroll
        for (int ridx = 0; ridx < 4; ridx++) {
            int rl = wm + (ridx >> 1)*16 + (ridx & 1)*8 + g;
            int gr = row0 + rl;
            if (gr < M) {
                #pragma unroll
                for (int j = 0; j < NFILT; j++)
                    atomicAdd(&fvout[(size_t)gr*NFILT + j], fvacc[ridx][j] + red[rl*NFILT + j]);
            }
        }
    }
}

// ---------------- fp32 tiled SGEMM (DeepSet layers, kept exact) ----------------
template<int BM, int BN, int TM, int TN, bool RELU, bool BIAS, bool SUB>
__global__ void __launch_bounds__(256)
gemm2(const float* __restrict__ A, int lda,
      const float* __restrict__ B, int ldb,
      const float* __restrict__ bias,
      const float* __restrict__ sub, int ldsub,
      const int* __restrict__ batch,
      float* __restrict__ C, int ldc, int M, int K) {
    constexpr int BK = 32;
    constexpr int TX = BN / TN, TY = BM / TM;
    static_assert(TX * TY == 256, "bad tile config");
    __shared__ float As[BK][BM];
    __shared__ float Bs[BK][BN];
    const int t = threadIdx.x;
    const int tx = t % TX, ty = t / TX;
    const int row0 = blockIdx.y * BM, col0 = blockIdx.x * BN;

    float acc[TM][TN] = {};
    const int ktiles = K / BK;
    for (int kt = 0; kt < ktiles; kt++) {
        #pragma unroll
        for (int i = t; i < BM*BK/4; i += 256) {
            int r = i / (BK/4);
            int kk = (i % (BK/4)) * 4;
            float4 v = make_float4(0.f, 0.f, 0.f, 0.f);
            int gr = row0 + r;
            if (gr < M) v = *(const float4*)(A + (size_t)gr*lda + kt*BK + kk);
            As[kk+0][r] = v.x; As[kk+1][r] = v.y; As[kk+2][r] = v.z; As[kk+3][r] = v.w;
        }
        #pragma unroll
        for (int i = t; i < BK*BN/4; i += 256) {
            int k = i / (BN/4);
            int n = (i % (BN/4)) * 4;
            *(float4*)(&Bs[k][n]) = *(const float4*)(B + (size_t)(kt*BK + k)*ldb + col0 + n);
        }
        __syncthreads();
        #pragma unroll 8
        for (int k = 0; k < BK; k++) {
            float a[TM], bf[TN];
            #pragma unroll
            for (int m = 0; m < TM; m++) a[m] = As[k][ty*TM + m];
            #pragma unroll
            for (int n = 0; n < TN; n++) bf[n] = Bs[k][tx*TN + n];
            #pragma unroll
            for (int m = 0; m < TM; m++)
                #pragma unroll
                for (int n = 0; n < TN; n++) acc[m][n] = fmaf(a[m], bf[n], acc[m][n]);
        }
        __syncthreads();
    }

    #pragma unroll
    for (int m = 0; m < TM; m++) {
        int gr = row0 + ty*TM + m;
        if (gr >= M) continue;
        const float* subrow = nullptr;
        if (SUB) subrow = sub + (size_t)batch[gr] * ldsub;
        #pragma unroll
        for (int n = 0; n < TN; n++) {
            int gc = col0 + tx*TN + n;
            float v = acc[m][n];
            if (BIAS) v += bias[gc];
            if (SUB)  v -= subrow[gc];
            if (RELU) v = fmaxf(v, 0.f);
            C[(size_t)gr*ldc + gc] = v;
        }
    }
}

// ---------------- p = x.u, q = x.v ----------------
__global__ void k_pq(const float* __restrict__ x) {
    int wid = (blockIdx.x * blockDim.x + threadIdx.x) >> 5;
    int l = threadIdx.x & 31;
    if (wid >= NNODE) return;
    float4 xv = *(const float4*)(x + (size_t)wid*FIN + l*4);
    float4 uu = *(const float4*)(g_u + l*4);
    float4 vv = *(const float4*)(g_v + l*4);
    float p = xv.x*uu.x + xv.y*uu.y + xv.z*uu.z + xv.w*uu.w;
    float q = xv.x*vv.x + xv.y*vv.y + xv.z*vv.z + xv.w*vv.w;
    #pragma unroll
    for (int o = 16; o; o >>= 1) {
        p += __shfl_xor_sync(0xffffffffu, p, o);
        q += __shfl_xor_sync(0xffffffffu, q, o);
    }
    if (l == 0) { g_p[wid] = p; g_q[wid] = q; }
}

// ---------------- edge attention ----------------
__global__ void k_att(const float* __restrict__ x, const int* __restrict__ ei,
                      float* __restrict__ out) {
    int wid = (blockIdx.x * blockDim.x + threadIdx.x) >> 5;
    int l = threadIdx.x & 31;
    if (wid >= NEDGE) return;
    int row = ei[wid], col = ei[NEDGE + wid];
    float4 zv = *(const float4*)(g_z + (size_t)row*FIN + l*4);
    float4 xv = *(const float4*)(x   + (size_t)col*FIN + l*4);
    float d = zv.x*xv.x + zv.y*xv.y + zv.z*xv.z + zv.w*xv.w;
    #pragma unroll
    for (int o = 16; o; o >>= 1) d += __shfl_xor_sync(0xffffffffu, d, o);
    if (l == 0) {
        float s = d + g_p[row] + g_q[col] + g_c[0];
        out[(size_t)NNODE*FIN + wid] = 1.f / (1.f + expf(-s));
    }
}

// ---------------- x0a = relu((fv+b_f2) @ fold + b_l0) ----------------
__global__ void k_x0a(const float* __restrict__ b_f2, const float* __restrict__ W_l0,
                      const float* __restrict__ b_l0) {
    __shared__ float fold[NFILT][OUTDIM];
    __shared__ float bl0[OUTDIM], bf2[NFILT];
    int t = threadIdx.x;
    for (int i = t; i < NFILT*OUTDIM; i += 256) {
        int j = i / OUTDIM, o = i % OUTDIM;
        fold[j][o] = W_l0[(2*j)*OUTDIM + o] + W_l0[(2*j+1)*OUTDIM + o];
    }
    if (t < OUTDIM) bl0[t] = b_l0[t];
    if (t < NFILT)  bf2[t] = b_f2[t];
    __syncthreads();
    int w = t >> 5, l = t & 31;
    int n = blockIdx.x * 8 + w;
    if (n >= NNODE) return;
    float fv[8];
    *(float4*)(fv)     = *(const float4*)(g_fv + (size_t)n*NFILT);
    *(float4*)(fv + 4) = *(const float4*)(g_fv + (size_t)n*NFILT + 4);
    #pragma unroll
    for (int j = 0; j < NFILT; j++) fv[j] += bf2[j];
    #pragma unroll
    for (int rep = 0; rep < 2; rep++) {
        int o = l + 32*rep;
        float s = bl0[o];
        #pragma unroll
        for (int j = 0; j < NFILT; j++) s = fmaf(fv[j], fold[j][o], s);
        g_x0a[(size_t)n*OUTDIM + o] = fmaxf(s, 0.f);
    }
}

// ---------------- segment sum over sorted batch ----------------
__global__ void k_seg(const float* __restrict__ v, const int* __restrict__ batch,
                      float* __restrict__ sum, int do_cnt) {
    int t = threadIdx.x;
    int f = t & 63, w = t >> 6;
    int r0 = blockIdx.x * 512;
    int rend = min(r0 + 512, NNODE);
    float acc = 0.f, ccnt = 0.f;
    int cur = -1;
    for (int r = r0 + w; r < rend; r += 4) {
        int g = __ldg(&batch[r]);
        if (g != cur) {
            if (cur >= 0) {
                atomicAdd(&sum[cur*64 + f], acc);
                if (do_cnt && f == 0) atomicAdd(&g_cnt[cur], ccnt);
            }
            acc = 0.f; ccnt = 0.f; cur = g;
        }
        acc += v[(size_t)r*64 + f];
        if (do_cnt && f == 0) ccnt += 1.f;
    }
    if (cur >= 0) {
        atomicAdd(&sum[cur*64 + f], acc);
        if (do_cnt && f == 0) atomicAdd(&g_cnt[cur], ccnt);
    }
}

__global__ void k_mean1(const float* __restrict__ L1) {
    __shared__ float mean[OUTDIM];
    int g = blockIdx.x, t = threadIdx.x;
    float c = fmaxf(g_cnt[g], 1.f);
    mean[t] = g_seg1[g*64 + t] / c;
    __syncthreads();
    float s = 0.f;
    #pragma unroll 4
    for (int k = 0; k < 64; k++) s += mean[k] * L1[k*64 + t];
    g_xm1[g*64 + t] = s;
}

__global__ void k_mean2(const float* __restrict__ L2) {
    __shared__ float mean[OUTDIM];
    int g = blockIdx.x, t = threadIdx.x;
    if (t < 64) mean[t] = g_seg2[g*64 + t] / fmaxf(g_cnt[g], 1.f);
    __syncthreads();
    float s = 0.f;
    #pragma unroll 4
    for (int k = 0; k < 64; k++) s += mean[k] * L2[k*128 + t];
    g_xm2[g*128 + t] = s;
}

// ---------------- BN ----------------
__global__ void k_bnsum() {
    int t = threadIdx.x;
    int f = t & 127, w = t >> 7;
    int r0 = blockIdx.x * 512, rend = min(r0 + 512, NNODE);
    float s1 = 0.f, s2 = 0.f;
    for (int r = r0 + w; r < rend; r += 2) {
        float v = g_hid2[(size_t)r*128 + f];
        s1 += v; s2 += v*v;
    }
    __shared__ float sh[256];
    sh[t] = s1; __syncthreads();
    if (t < 128) atomicAdd(&g_bn[f], sh[t] + sh[t + 128]);
    __syncthreads();
    sh[t] = s2; __syncthreads();
    if (t < 128) atomicAdd(&g_bn[128 + f], sh[t] + sh[t + 128]);
}

__global__ void k_bnfin(const float* __restrict__ gamma, const float* __restrict__ beta) {
    int f = threadIdx.x;
    float mu = g_bn[f] / (float)NNODE;
    float var = g_bn[128 + f] / (float)NNODE - mu*mu;
    float a = gamma[f] * rsqrtf(var + 1e-5f);
    g_bna[f] = a;
    g_bnb[f] = beta[f] - mu*a;
}

__global__ void k_out(const float* __restrict__ x, float* __restrict__ out) {
    int i = blockIdx.x * blockDim.x + threadIdx.x;
    if (i >= NNODE*FIN/4) return;
    int f4 = (i & 31) * 4;
    float4 xv = ((const float4*)x)[i];
    float4 hv = ((const float4*)g_hid2)[i];
    float4 a  = *(const float4*)(g_bna + f4);
    float4 b  = *(const float4*)(g_bnb + f4);
    float4 o;
    o.x = xv.x + hv.x*a.x + b.x;
    o.y = xv.y + hv.y*a.y + b.y;
    o.z = xv.z + hv.z*a.z + b.z;
    o.w = xv.w + hv.w*a.w + b.w;
    ((float4*)out)[i] = o;
}

// ---------------- host launch ----------------
extern "C" void kernel_launch(void* const* d_in, const int* in_sizes, int n_in,
                              void* d_out, int out_size) {
    const float* x      = (const float*)d_in[0];
    const int*   ei     = (const int*)  d_in[1];
    const int*   batch  = (const int*)  d_in[2];
    const float* W_f1   = (const float*)d_in[3];
    const float* b_f1   = (const float*)d_in[4];
    const float* W_f2   = (const float*)d_in[5];
    const float* b_f2   = (const float*)d_in[6];
    const float* W_l0   = (const float*)d_in[7];
    const float* b_l0   = (const float*)d_in[8];
    const float* G1     = (const float*)d_in[9];
    const float* b_g1   = (const float*)d_in[10];
    const float* L1     = (const float*)d_in[11];
    const float* G2     = (const float*)d_in[12];
    const float* b_g2   = (const float*)d_in[13];
    const float* L2     = (const float*)d_in[14];
    const float* gamma  = (const float*)d_in[15];
    const float* beta   = (const float*)d_in[16];
    const float* W_att  = (const float*)d_in[17];
    const float* b_att  = (const float*)d_in[18];
    const float* A_att  = (const float*)d_in[19];
    float* out = (float*)d_out;

    float *pM, *pz, *pfv, *px0a, *px0b, *pxm1, *pxm2, *phid2, *pseg1, *pseg2;
    cudaGetSymbolAddress((void**)&pM,    g_M);
    cudaGetSymbolAddress((void**)&pz,    g_z);
    cudaGetSymbolAddress((void**)&pfv,   g_fv);
    cudaGetSymbolAddress((void**)&px0a,  g_x0a);
    cudaGetSymbolAddress((void**)&px0b,  g_x0b);
    cudaGetSymbolAddress((void**)&pxm1,  g_xm1);
    cudaGetSymbolAddress((void**)&pxm2,  g_xm2);
    cudaGetSymbolAddress((void**)&phid2, g_hid2);
    cudaGetSymbolAddress((void**)&pseg1, g_seg1);
    cudaGetSymbolAddress((void**)&pseg2, g_seg2);

    const int SMZ  = (SM_AS + SM_BS) * 4;
    const int SMFV = SMZ + (64*NFILT + 64) * 4;
    cudaFuncSetAttribute(zgemm_tf32,  cudaFuncAttributeMaxDynamicSharedMemorySize, SMZ);
    cudaFuncSetAttribute(fvgemm_tf32, cudaFuncAttributeMaxDynamicSharedMemorySize, SMFV);

    const int rb128 = (NNODE + 127) / 128;  // 782

    k_zero<<<(NNODE*NFILT + 255)/256, 256>>>();
    k_pre1<<<NHEADS*ATTD + NHEADS, 128>>>(W_att, b_att, A_att);
    k_mgemm<<<dim3(4, 4, 4), 256>>>(W_att);
    k_uvc<<<FIN + 1, 128>>>(W_att, b_att);

    // z = x @ M  (tf32 tensor cores)
    zgemm_tf32<<<dim3(2, rb128), 256, SMZ>>>(x, pM, pz, NNODE);
    k_pq<<<(NNODE*32 + 255)/256, 256>>>(x);
    k_att<<<(NEDGE*32 + 255)/256, 256>>>(x, ei, out);

    // fv += relu(x @ W_f1 + b_f1) @ W_f2  (tf32 tensor cores, fused)
    fvgemm_tf32<<<dim3(4, rb128), 256, SMFV>>>(x, W_f1, b_f1, W_f2, pfv, NNODE);
    k_x0a<<<(NNODE + 7)/8, 256>>>(b_f2, W_l0, b_l0);

    k_seg<<<(NNODE + 511)/512, 256>>>(px0a, batch, pseg1, 1);
    k_mean1<<<NG, 64>>>(L1);
    gemm2<128,64,4,8,true,true,true><<<dim3(1, rb128), 256>>>(
        px0a, OUTDIM, G1, OUTDIM, b_g1, pxm1, OUTDIM, batch, px0b, OUTDIM, NNODE, OUTDIM);

    k_seg<<<(NNODE + 511)/512, 256>>>(px0b, batch, pseg2, 0);
    k_mean2<<<NG, 128>>>(L2);
    gemm2<128,128,8,8,true,true,true><<<dim3(1, rb128), 256>>>(
        px0b, OUTDIM, G2, FIN, b_g2, pxm2, FIN, batch, phid2, FIN, NNODE, OUTDIM);

    k_bnsum<<<(NNODE + 511)/512, 256>>>();
    k_bnfin<<<1, 128>>>(gamma, beta);
    k_out<<<(NNODE*FIN/4 + 255)/256, 256>>>(x, out);
}

// round 8
// speedup vs baseline: 1.7122x; 1.2538x over previous
#include <cuda_runtime.h>
#include <stdint.h>
#include <stddef.h>
#include <math.h>

#define NNODE 100000
#define NEDGE 200000
#define NG 64
#define FIN 128
#define NFILT 8
#define HIDDIM 256
#define OUTDIM 64
#define ATTD 128
#define NHEADS 4

// ---------------- scratch ----------------
__device__ float g_T[NHEADS*ATTD*ATTD];
__device__ float g_r[NHEADS*ATTD];
__device__ float g_M[FIN*FIN];
__device__ float g_u[FIN];
__device__ float g_v[FIN];
__device__ float g_c[1];
__device__ float g_z[NNODE*FIN];
__device__ float g_p[NNODE];
__device__ float g_q[NNODE];
__device__ float g_x0a[NNODE*OUTDIM];
__device__ float g_x0b[NNODE*OUTDIM];
__device__ float g_hid2[NNODE*FIN];
__device__ float g_seg1[NG*OUTDIM];
__device__ float g_seg2[NG*OUTDIM];
__device__ float g_cnt[NG];
__device__ float g_xm1[NG*OUTDIM];
__device__ float g_xm2[NG*FIN];
__device__ float g_bn[2*FIN];
__device__ float g_bna[FIN];
__device__ float g_bnb[FIN];

__device__ __forceinline__ uint32_t f2tf32(float f) {
    uint32_t u;
    asm("cvt.rna.tf32.f32 %0, %1;" : "=r"(u) : "f"(f));
    return u;
}

__device__ __forceinline__ void mma_tf32(float c[4], const uint32_t a[4], const uint32_t b[2]) {
    asm volatile("mma.sync.aligned.m16n8k8.row.col.f32.tf32.tf32.f32 "
                 "{%0,%1,%2,%3}, {%4,%5,%6,%7}, {%8,%9}, {%0,%1,%2,%3};\n"
                 : "+f"(c[0]), "+f"(c[1]), "+f"(c[2]), "+f"(c[3])
                 : "r"(a[0]), "r"(a[1]), "r"(a[2]), "r"(a[3]), "r"(b[0]), "r"(b[1]));
}

// ---------------- zero accumulators ----------------
__global__ void k_zero() {
    int i = blockIdx.x * 256 + threadIdx.x;
    if (i < FIN*FIN)   g_M[i] = 0.f;
    if (i < NG*OUTDIM) { g_seg1[i] = 0.f; g_seg2[i] = 0.f; }
    if (i < NG)        g_cnt[i] = 0.f;
    if (i < 2*FIN)     g_bn[i] = 0.f;
}

// ---------------- attention precompute ----------------
__global__ void k_pre1(const float* __restrict__ W, const float* __restrict__ b,
                       const float* __restrict__ Aa) {
    __shared__ float w[ATTD];
    int bid = blockIdx.x, t = threadIdx.x;
    if (bid < NHEADS*ATTD) {
        int h = bid >> 7, i = bid & 127;
        w[t] = W[(h*ATTD + i)*ATTD + t];
        __syncthreads();
        const float* Ah = Aa + h*ATTD*ATTD;
        float s = 0.f;
        #pragma unroll 4
        for (int k = 0; k < ATTD; k++) s += w[k] * Ah[k*ATTD + t];
        g_T[(h*ATTD + i)*ATTD + t] = s;
    } else {
        int h = bid - NHEADS*ATTD;
        w[t] = b[h*ATTD + t];
        __syncthreads();
        const float* Ah = Aa + h*ATTD*ATTD;
        float s = 0.f;
        #pragma unroll 4
        for (int k = 0; k < ATTD; k++) s += w[k] * Ah[k*ATTD + t];
        g_r[h*ATTD + t] = s;
    }
}

// M += 0.25 * T_h @ W_h^T
__global__ void __launch_bounds__(256) k_mgemm(const float* __restrict__ W) {
    __shared__ float Tt[32][36], Ws[32][36];
    int it = blockIdx.x * 32, jt = blockIdx.y * 32, h = blockIdx.z;
    int t = threadIdx.x;
    int tx = t & 15, ty = t >> 4;
    float acc[2][2] = {};
    for (int kt = 0; kt < ATTD; kt += 32) {
        int r = t >> 3, k4 = (t & 7) << 2;
        *(float4*)&Tt[r][k4] = *(const float4*)(g_T + (size_t)(h*ATTD + it + r)*ATTD + kt + k4);
        *(float4*)&Ws[r][k4] = *(const float4*)(W   + (size_t)(h*ATTD + jt + r)*ATTD + kt + k4);
        __syncthreads();
        #pragma unroll 8
        for (int k = 0; k < 32; k++) {
            float a0 = Tt[ty*2][k], a1 = Tt[ty*2+1][k];
            float b0 = Ws[tx*2][k], b1 = Ws[tx*2+1][k];
            acc[0][0] = fmaf(a0, b0, acc[0][0]);
            acc[0][1] = fmaf(a0, b1, acc[0][1]);
            acc[1][0] = fmaf(a1, b0, acc[1][0]);
            acc[1][1] = fmaf(a1, b1, acc[1][1]);
        }
        __syncthreads();
    }
    #pragma unroll
    for (int i = 0; i < 2; i++)
        #pragma unroll
        for (int j = 0; j < 2; j++)
            atomicAdd(&g_M[(it + ty*2 + i)*FIN + jt + tx*2 + j], 0.25f * acc[i][j]);
}

// u, v, c
__global__ void k_uvc(const float* __restrict__ W, const float* __restrict__ b) {
    __shared__ float red[8];
    int j = blockIdx.x, k = threadIdx.x;
    int wid = k >> 5, l = k & 31;
    if (j < FIN) {
        float u = 0.f, v = 0.f;
        #pragma unroll
        for (int h = 0; h < NHEADS; h++) {
            u += g_T[(size_t)(h*ATTD + j)*ATTD + k] * b[h*ATTD + k];
            v += g_r[h*ATTD + k] * W[(size_t)(h*ATTD + j)*ATTD + k];
        }
        #pragma unroll
        for (int o = 16; o; o >>= 1) {
            u += __shfl_xor_sync(0xffffffffu, u, o);
            v += __shfl_xor_sync(0xffffffffu, v, o);
        }
        if (l == 0) { red[wid] = u; red[4 + wid] = v; }
        __syncthreads();
        if (k == 0) g_u[j] = 0.25f * (red[0] + red[1] + red[2] + red[3]);
        if (k == 1) g_v[j] = 0.25f * (red[4] + red[5] + red[6] + red[7]);
    } else {
        float c = 0.f;
        for (int i = k; i < NHEADS*ATTD; i += 128) c += g_r[i] * b[i];
        #pragma unroll
        for (int o = 16; o; o >>= 1) c += __shfl_xor_sync(0xffffffffu, c, o);
        if (l == 0) red[wid] = c;
        __syncthreads();
        if (k == 0) g_c[0] = 0.25f * (red[0] + red[1] + red[2] + red[3]);
    }
}

// ================= MEGA kernel =================
// One block per 128 rows of x. Loads x tile once (tf32 in smem), computes:
//   z = x@M (2 tiles), fv = relu(x@Wf1+b)@Wf2 (4 tiles, in-smem),
//   p = x.u, q = x.v (during load), x0a = relu((fv+bf2)@fold + bl0).
#define AS_STRIDE 132
#define BS_STRIDE 72
#define SM_AS (128*AS_STRIDE)
#define SM_BS (128*BS_STRIDE)
// float region after As/Bs (word offsets)
#define OFF_FVS   (SM_AS + SM_BS)        // 128*8
#define OFF_PS    (OFF_FVS + 128*8)      // 128
#define OFF_QS    (OFF_PS + 128)         // 128
#define OFF_UV    (OFF_QS + 128)         // 128 u + 128 v
#define OFF_FOLD  (OFF_UV + 256)         // 8*64
#define OFF_BF1   (OFF_FOLD + 512)       // 64
#define OFF_WF2   (OFF_BF1 + 64)         // 64*8
#define OFF_BF2   (OFF_WF2 + 512)        // 8
#define OFF_BL0   (OFF_BF2 + 8)          // 64
#define MEGA_SMEM ((OFF_BL0 + 64) * 4)

__global__ void __launch_bounds__(256) mega_tf32(
    const float* __restrict__ x, const float* __restrict__ Mw,
    const float* __restrict__ Wf1, const float* __restrict__ bf1,
    const float* __restrict__ Wf2, const float* __restrict__ bf2,
    const float* __restrict__ Wl0, const float* __restrict__ bl0,
    float* __restrict__ z, float* __restrict__ x0a, int M) {
    extern __shared__ uint32_t smbuf[];
    uint32_t (*As)[AS_STRIDE] = (uint32_t(*)[AS_STRIDE])smbuf;
    uint32_t (*Bs)[BS_STRIDE] = (uint32_t(*)[BS_STRIDE])(smbuf + SM_AS);
    float* fvs  = (float*)(smbuf + OFF_FVS);
    float* ps   = (float*)(smbuf + OFF_PS);
    float* qs   = (float*)(smbuf + OFF_QS);
    float* uv   = (float*)(smbuf + OFF_UV);
    float* fold = (float*)(smbuf + OFF_FOLD);
    float* bf1s = (float*)(smbuf + OFF_BF1);
    float* wf2s = (float*)(smbuf + OFF_WF2);
    float* bf2s = (float*)(smbuf + OFF_BF2);
    float* bl0s = (float*)(smbuf + OFF_BL0);

    const int t = threadIdx.x;
    const int row0 = blockIdx.x * 128;

    // init small smem
    for (int i = t; i < 128*8; i += 256) fvs[i] = 0.f;
    if (t < 128) { ps[t] = 0.f; qs[t] = 0.f; uv[t] = g_u[t]; uv[128 + t] = g_v[t]; }
    for (int i = t; i < 512; i += 256) {
        int j = i >> 6, o = i & 63;
        fold[i] = Wl0[(2*j)*OUTDIM + o] + Wl0[(2*j+1)*OUTDIM + o];
    }
    if (t < 64) bl0s[t] = bl0[t];
    if (t < 8)  bf2s[t] = bf2[t];
    __syncthreads();

    // load x tile -> As (tf32), accumulate p/q partials
    for (int i = t; i < 128*32; i += 256) {
        int r = i >> 5, k4 = (i & 31) << 2;
        float4 v = make_float4(0.f, 0.f, 0.f, 0.f);
        if (row0 + r < M) v = *(const float4*)(x + (size_t)(row0 + r)*FIN + k4);
        As[r][k4+0] = f2tf32(v.x); As[r][k4+1] = f2tf32(v.y);
        As[r][k4+2] = f2tf32(v.z); As[r][k4+3] = f2tf32(v.w);
        float pp = v.x*uv[k4] + v.y*uv[k4+1] + v.z*uv[k4+2] + v.w*uv[k4+3];
        float qq = v.x*uv[128+k4] + v.y*uv[128+k4+1] + v.z*uv[128+k4+2] + v.w*uv[128+k4+3];
        atomicAdd(&ps[r], pp);
        atomicAdd(&qs[r], qq);
    }
    __syncthreads();
    if (t < 128 && row0 + t < M) { g_p[row0 + t] = ps[t]; g_q[row0 + t] = qs[t]; }

    const int wid = t >> 5, lane = t & 31;
    const int wm = (wid & 3) * 32, wnid = wid >> 2, wn = wnid * 32;
    const int g = lane >> 2, tg = lane & 3;

    float fvacc[4][NFILT] = {};

    #pragma unroll 1
    for (int tile = 0; tile < 6; tile++) {
        const int col0 = (tile < 2) ? tile*64 : (tile - 2)*64;
        const float* Bsrc = (tile < 2) ? Mw : Wf1;
        const int ldb = (tile < 2) ? FIN : HIDDIM;
        __syncthreads();
        for (int i = t; i < 128*16; i += 256) {
            int k = i >> 4, n4 = (i & 15) << 2;
            float4 v = *(const float4*)(Bsrc + (size_t)k*ldb + col0 + n4);
            Bs[k][n4+0] = f2tf32(v.x); Bs[k][n4+1] = f2tf32(v.y);
            Bs[k][n4+2] = f2tf32(v.z); Bs[k][n4+3] = f2tf32(v.w);
        }
        if (tile >= 2 && t < 128) {
            int r = t >> 1, half = t & 1;
            *(float4*)(wf2s + r*8 + half*4) = *(const float4*)(Wf2 + (size_t)(col0 + r)*NFILT + half*4);
            if (half == 0) bf1s[r] = bf1[col0 + r];
        }
        __syncthreads();

        float acc[2][4][4] = {};
        #pragma unroll
        for (int ko = 0; ko < 16; ko++) {
            int k0 = ko * 8;
            uint32_t a[2][4], b[4][2];
            #pragma unroll
            for (int mt = 0; mt < 2; mt++) {
                int r = wm + mt*16 + g;
                a[mt][0] = As[r][k0 + tg];
                a[mt][1] = As[r + 8][k0 + tg];
                a[mt][2] = As[r][k0 + tg + 4];
                a[mt][3] = As[r + 8][k0 + tg + 4];
            }
            #pragma unroll
            for (int nt = 0; nt < 4; nt++) {
                int n = wn + nt*8 + g;
                b[nt][0] = Bs[k0 + tg][n];
                b[nt][1] = Bs[k0 + tg + 4][n];
            }
            #pragma unroll
            for (int mt = 0; mt < 2; mt++)
                #pragma unroll
                for (int nt = 0; nt < 4; nt++)
                    mma_tf32(acc[mt][nt], a[mt], b[nt]);
        }

        if (tile < 2) {
            #pragma unroll
            for (int mt = 0; mt < 2; mt++) {
                int r = row0 + wm + mt*16 + g;
                #pragma unroll
                for (int nt = 0; nt < 4; nt++) {
                    int c = col0 + wn + nt*8 + 2*tg;
                    if (r < M)     *(float2*)(z + (size_t)r*FIN + c)     = make_float2(acc[mt][nt][0], acc[mt][nt][1]);
                    if (r + 8 < M) *(float2*)(z + (size_t)(r+8)*FIN + c) = make_float2(acc[mt][nt][2], acc[mt][nt][3]);
                }
            }
        } else {
            #pragma unroll
            for (int nt = 0; nt < 4; nt++) {
                int nA = wn + nt*8 + 2*tg, nB = nA + 1;
                float bA = bf1s[nA], bB = bf1s[nB];
                const float* wA = wf2s + nA*NFILT;
                const float* wB = wf2s + nB*NFILT;
                #pragma unroll
                for (int mt = 0; mt < 2; mt++) {
                    float v00 = fmaxf(acc[mt][nt][0] + bA, 0.f);
                    float v01 = fmaxf(acc[mt][nt][1] + bB, 0.f);
                    float v10 = fmaxf(acc[mt][nt][2] + bA, 0.f);
                    float v11 = fmaxf(acc[mt][nt][3] + bB, 0.f);
                    #pragma unroll
                    for (int j = 0; j < NFILT; j++) {
                        fvacc[mt*2+0][j] += v00*wA[j] + v01*wB[j];
                        fvacc[mt*2+1][j] += v10*wA[j] + v11*wB[j];
                    }
                }
            }
        }
    }

    // reduce fvacc over quads (n within quad), then into fvs (2 wnid halves)
    #pragma unroll
    for (int ridx = 0; ridx < 4; ridx++)
        #pragma unroll
        for (int j = 0; j < NFILT; j++) {
            float s = fvacc[ridx][j];
            s += __shfl_xor_sync(0xffffffffu, s, 1);
            s += __shfl_xor_sync(0xffffffffu, s, 2);
            fvacc[ridx][j] = s;
        }
    if (tg == 0) {
        #pragma unroll
        for (int ridx = 0; ridx < 4; ridx++) {
            int rl = wm + (ridx >> 1)*16 + (ridx & 1)*8 + g;
            #pragma unroll
            for (int j = 0; j < NFILT; j++)
                atomicAdd(&fvs[rl*NFILT + j], fvacc[ridx][j]);
        }
    }
    __syncthreads();

    // x0a = relu((fv + bf2) @ fold + bl0)
    for (int i = t; i < 128*64; i += 256) {
        int r = i >> 6, o = i & 63;
        if (row0 + r >= M) continue;
        float s = bl0s[o];
        #pragma unroll
        for (int j = 0; j < NFILT; j++)
            s = fmaf(fvs[r*NFILT + j] + bf2s[j], fold[j*64 + o], s);
        x0a[(size_t)(row0 + r)*OUTDIM + o] = fmaxf(s, 0.f);
    }
}

// ================= DeepSet tf32 GEMM (K=64): C = relu(A@B + bias - sub[batch]) =================
// BM=128, BN=64 per block. Optional fused BN sum (per-column sum & sumsq -> g_bn).
#define DAS_STRIDE 68
#define DS_SMEM ((128*DAS_STRIDE + 64*DAS_STRIDE + 128) * 4)

template<bool BNACC>
__global__ void __launch_bounds__(256) ds_tf32(
    const float* __restrict__ A,
    const float* __restrict__ B, int ldb,
    const float* __restrict__ bias,
    const float* __restrict__ sub, int ldsub,
    const int* __restrict__ batch,
    float* __restrict__ C, int ldc, int M) {
    extern __shared__ uint32_t smbuf[];
    uint32_t (*As)[DAS_STRIDE] = (uint32_t(*)[DAS_STRIDE])smbuf;
    uint32_t (*Bs)[DAS_STRIDE] = (uint32_t(*)[DAS_STRIDE])(smbuf + 128*DAS_STRIDE);
    float* bnsm = (float*)(smbuf + 128*DAS_STRIDE + 64*DAS_STRIDE); // [64][2]
    const int t = threadIdx.x;
    const int row0 = blockIdx.y * 128, col0 = blockIdx.x * 64;

    for (int i = t; i < 128*16; i += 256) {
        int r = i >> 4, k4 = (i & 15) << 2;
        float4 v = make_float4(0.f, 0.f, 0.f, 0.f);
        if (row0 + r < M) v = *(const float4*)(A + (size_t)(row0 + r)*OUTDIM + k4);
        As[r][k4+0] = f2tf32(v.x); As[r][k4+1] = f2tf32(v.y);
        As[r][k4+2] = f2tf32(v.z); As[r][k4+3] = f2tf32(v.w);
    }
    for (int i = t; i < 64*16; i += 256) {
        int k = i >> 4, n4 = (i & 15) << 2;
        float4 v = *(const float4*)(B + (size_t)k*ldb + col0 + n4);
        Bs[k][n4+0] = f2tf32(v.x); Bs[k][n4+1] = f2tf32(v.y);
        Bs[k][n4+2] = f2tf32(v.z); Bs[k][n4+3] = f2tf32(v.w);
    }
    if (BNACC && t < 128) bnsm[t] = 0.f;
    __syncthreads();

    const int wid = t >> 5, lane = t & 31;
    const int wm = (wid & 3) * 32, wn = (wid >> 2) * 32;
    const int g = lane >> 2, tg = lane & 3;

    float acc[2][4][4] = {};
    #pragma unroll
    for (int ko = 0; ko < 8; ko++) {
        int k0 = ko * 8;
        uint32_t a[2][4], b[4][2];
        #pragma unroll
        for (int mt = 0; mt < 2; mt++) {
            int r = wm + mt*16 + g;
            a[mt][0] = As[r][k0 + tg];
            a[mt][1] = As[r + 8][k0 + tg];
            a[mt][2] = As[r][k0 + tg + 4];
            a[mt][3] = As[r + 8][k0 + tg + 4];
        }
        #pragma unroll
        for (int nt = 0; nt < 4; nt++) {
            int n = wn + nt*8 + g;
            b[nt][0] = Bs[k0 + tg][n];
            b[nt][1] = Bs[k0 + tg + 4][n];
        }
        #pragma unroll
        for (int mt = 0; mt < 2; mt++)
            #pragma unroll
            for (int nt = 0; nt < 4; nt++)
                mma_tf32(acc[mt][nt], a[mt], b[nt]);
    }

    // epilogue
    float s1[4][2] = {}, s2[4][2] = {};   // [nt][col pair] BN partials
    #pragma unroll
    for (int mt = 0; mt < 2; mt++) {
        int r0g = row0 + wm + mt*16 + g;
        int r1g = r0g + 8;
        bool ok0 = r0g < M, ok1 = r1g < M;
        int b0 = ok0 ? batch[r0g] : 0;
        int b1 = ok1 ? batch[r1g] : 0;
        const float* sub0 = sub + (size_t)b0*ldsub;
        const float* sub1 = sub + (size_t)b1*ldsub;
        #pragma unroll
        for (int nt = 0; nt < 4; nt++) {
            int cA = col0 + wn + nt*8 + 2*tg, cB = cA + 1;
            float biA = bias[cA], biB = bias[cB];
            float v00 = fmaxf(acc[mt][nt][0] + biA - sub0[cA], 0.f);
            float v01 = fmaxf(acc[mt][nt][1] + biB - sub0[cB], 0.f);
            float v10 = fmaxf(acc[mt][nt][2] + biA - sub1[cA], 0.f);
            float v11 = fmaxf(acc[mt][nt][3] + biB - sub1[cB], 0.f);
            if (ok0) *(float2*)(C + (size_t)r0g*ldc + cA) = make_float2(v00, v01);
            if (ok1) *(float2*)(C + (size_t)r1g*ldc + cA) = make_float2(v10, v11);
            if (BNACC) {
                float a0 = (ok0 ? v00 : 0.f) + (ok1 ? v10 : 0.f);
                float a1 = (ok0 ? v01 : 0.f) + (ok1 ? v11 : 0.f);
                s1[nt][0] += a0; s1[nt][1] += a1;
                s2[nt][0] += (ok0 ? v00*v00 : 0.f) + (ok1 ? v10*v10 : 0.f);
                s2[nt][1] += (ok0 ? v01*v01 : 0.f) + (ok1 ? v11*v11 : 0.f);
            }
        }
    }
    if (BNACC) {
        #pragma unroll
        for (int nt = 0; nt < 4; nt++)
            #pragma unroll
            for (int h = 0; h < 2; h++) {
                float a = s1[nt][h], b = s2[nt][h];
                #pragma unroll
                for (int o = 4; o < 32; o <<= 1) {
                    a += __shfl_xor_sync(0xffffffffu, a, o);
                    b += __shfl_xor_sync(0xffffffffu, b, o);
                }
                if (g == 0) {
                    int cl = wn + nt*8 + 2*tg + h;
                    atomicAdd(&bnsm[2*cl], a);
                    atomicAdd(&bnsm[2*cl + 1], b);
                }
            }
        __syncthreads();
        if (t < 64) {
            atomicAdd(&g_bn[col0 + t], bnsm[2*t]);
            atomicAdd(&g_bn[FIN + col0 + t], bnsm[2*t + 1]);
        }
    }
}

// ---------------- edge attention ----------------
__global__ void k_att(const float* __restrict__ x, const int* __restrict__ ei,
                      float* __restrict__ out) {
    int wid = (blockIdx.x * blockDim.x + threadIdx.x) >> 5;
    int l = threadIdx.x & 31;
    if (wid >= NEDGE) return;
    int row = ei[wid], col = ei[NEDGE + wid];
    float4 zv = *(const float4*)(g_z + (size_t)row*FIN + l*4);
    float4 xv = *(const float4*)(x   + (size_t)col*FIN + l*4);
    float d = zv.x*xv.x + zv.y*xv.y + zv.z*xv.z + zv.w*xv.w;
    #pragma unroll
    for (int o = 16; o; o >>= 1) d += __shfl_xor_sync(0xffffffffu, d, o);
    if (l == 0) {
        float s = d + g_p[row] + g_q[col] + g_c[0];
        out[(size_t)NNODE*FIN + wid] = 1.f / (1.f + expf(-s));
    }
}

// ---------------- segment sum over sorted batch ----------------
__global__ void k_seg(const float* __restrict__ v, const int* __restrict__ batch,
                      float* __restrict__ sum, int do_cnt) {
    int t = threadIdx.x;
    int f = t & 63, w = t >> 6;
    int r0 = blockIdx.x * 512;
    int rend = min(r0 + 512, NNODE);
    float acc = 0.f, ccnt = 0.f;
    int cur = -1;
    for (int r = r0 + w; r < rend; r += 4) {
        int g = __ldg(&batch[r]);
        if (g != cur) {
            if (cur >= 0) {
                atomicAdd(&sum[cur*64 + f], acc);
                if (do_cnt && f == 0) atomicAdd(&g_cnt[cur], ccnt);
            }
            acc = 0.f; ccnt = 0.f; cur = g;
        }
        acc += v[(size_t)r*64 + f];
        if (do_cnt && f == 0) ccnt += 1.f;
    }
    if (cur >= 0) {
        atomicAdd(&sum[cur*64 + f], acc);
        if (do_cnt && f == 0) atomicAdd(&g_cnt[cur], ccnt);
    }
}

__global__ void k_mean1(const float* __restrict__ L1) {
    __shared__ float mean[OUTDIM];
    int g = blockIdx.x, t = threadIdx.x;
    float c = fmaxf(g_cnt[g], 1.f);
    mean[t] = g_seg1[g*64 + t] / c;
    __syncthreads();
    float s = 0.f;
    #pragma unroll 4
    for (int k = 0; k < 64; k++) s += mean[k] * L1[k*64 + t];
    g_xm1[g*64 + t] = s;
}

__global__ void k_mean2(const float* __restrict__ L2) {
    __shared__ float mean[OUTDIM];
    int g = blockIdx.x, t = threadIdx.x;
    if (t < 64) mean[t] = g_seg2[g*64 + t] / fmaxf(g_cnt[g], 1.f);
    __syncthreads();
    float s = 0.f;
    #pragma unroll 4
    for (int k = 0; k < 64; k++) s += mean[k] * L2[k*128 + t];
    g_xm2[g*128 + t] = s;
}

__global__ void k_bnfin(const float* __restrict__ gamma, const float* __restrict__ beta) {
    int f = threadIdx.x;
    float mu = g_bn[f] / (float)NNODE;
    float var = g_bn[128 + f] / (float)NNODE - mu*mu;
    float a = gamma[f] * rsqrtf(var + 1e-5f);
    g_bna[f] = a;
    g_bnb[f] = beta[f] - mu*a;
}

__global__ void k_out(const float* __restrict__ x, float* __restrict__ out) {
    int i = blockIdx.x * blockDim.x + threadIdx.x;
    if (i >= NNODE*FIN/4) return;
    int f4 = (i & 31) * 4;
    float4 xv = ((const float4*)x)[i];
    float4 hv = ((const float4*)g_hid2)[i];
    float4 a  = *(const float4*)(g_bna + f4);
    float4 b  = *(const float4*)(g_bnb + f4);
    float4 o;
    o.x = xv.x + hv.x*a.x + b.x;
    o.y = xv.y + hv.y*a.y + b.y;
    o.z = xv.z + hv.z*a.z + b.z;
    o.w = xv.w + hv.w*a.w + b.w;
    ((float4*)out)[i] = o;
}

// ---------------- host launch ----------------
extern "C" void kernel_launch(void* const* d_in, const int* in_sizes, int n_in,
                              void* d_out, int out_size) {
    const float* x      = (const float*)d_in[0];
    const int*   ei     = (const int*)  d_in[1];
    const int*   batch  = (const int*)  d_in[2];
    const float* W_f1   = (const float*)d_in[3];
    const float* b_f1   = (const float*)d_in[4];
    const float* W_f2   = (const float*)d_in[5];
    const float* b_f2   = (const float*)d_in[6];
    const float* W_l0   = (const float*)d_in[7];
    const float* b_l0   = (const float*)d_in[8];
    const float* G1     = (const float*)d_in[9];
    const float* b_g1   = (const float*)d_in[10];
    const float* L1     = (const float*)d_in[11];
    const float* G2     = (const float*)d_in[12];
    const float* b_g2   = (const float*)d_in[13];
    const float* L2     = (const float*)d_in[14];
    const float* gamma  = (const float*)d_in[15];
    const float* beta   = (const float*)d_in[16];
    const float* W_att  = (const float*)d_in[17];
    const float* b_att  = (const float*)d_in[18];
    const float* A_att  = (const float*)d_in[19];
    float* out = (float*)d_out;

    float *pM, *pz, *px0a, *px0b, *pxm1, *pxm2, *phid2, *pseg1, *pseg2;
    cudaGetSymbolAddress((void**)&pM,    g_M);
    cudaGetSymbolAddress((void**)&pz,    g_z);
    cudaGetSymbolAddress((void**)&px0a,  g_x0a);
    cudaGetSymbolAddress((void**)&px0b,  g_x0b);
    cudaGetSymbolAddress((void**)&pxm1,  g_xm1);
    cudaGetSymbolAddress((void**)&pxm2,  g_xm2);
    cudaGetSymbolAddress((void**)&phid2, g_hid2);
    cudaGetSymbolAddress((void**)&pseg1, g_seg1);
    cudaGetSymbolAddress((void**)&pseg2, g_seg2);

    cudaFuncSetAttribute(mega_tf32, cudaFuncAttributeMaxDynamicSharedMemorySize, MEGA_SMEM);
    cudaFuncSetAttribute(ds_tf32<false>, cudaFuncAttributeMaxDynamicSharedMemorySize, DS_SMEM);
    cudaFuncSetAttribute(ds_tf32<true>,  cudaFuncAttributeMaxDynamicSharedMemorySize, DS_SMEM);

    const int rb128 = (NNODE + 127) / 128;  // 782

    k_zero<<<(FIN*FIN + 255)/256, 256>>>();
    k_pre1<<<NHEADS*ATTD + NHEADS, 128>>>(W_att, b_att, A_att);
    k_mgemm<<<dim3(4, 4, 4), 256>>>(W_att);
    k_uvc<<<FIN + 1, 128>>>(W_att, b_att);

    // z, p, q, fv, x0a all in one pass over x
    mega_tf32<<<rb128, 256, MEGA_SMEM>>>(x, pM, W_f1, b_f1, W_f2, b_f2,
                                         W_l0, b_l0, pz, px0a, NNODE);
    k_att<<<(NEDGE*32 + 255)/256, 256>>>(x, ei, out);

    k_seg<<<(NNODE + 511)/512, 256>>>(px0a, batch, pseg1, 1);
    k_mean1<<<NG, 64>>>(L1);
    // x0b = relu(x0a @ G1 + b_g1 - xm1[batch])
    ds_tf32<false><<<dim3(1, rb128), 256, DS_SMEM>>>(
        px0a, G1, OUTDIM, b_g1, pxm1, OUTDIM, batch, px0b, OUTDIM, NNODE);

    k_seg<<<(NNODE + 511)/512, 256>>>(px0b, batch, pseg2, 0);
    k_mean2<<<NG, 128>>>(L2);
    // hid2 = relu(x0b @ G2 + b_g2 - xm2[batch]) + fused BN sums
    ds_tf32<true><<<dim3(2, rb128), 256, DS_SMEM>>>(
        px0b, G2, FIN, b_g2, pxm2, FIN, batch, phid2, FIN, NNODE);

    k_bnfin<<<1, 128>>>(gamma, beta);
    k_out<<<(NNODE*FIN/4 + 255)/256, 256>>>(x, out);
}

// round 9
// speedup vs baseline: 2.4983x; 1.4591x over previous
#include <cuda_runtime.h>
#include <stdint.h>
#include <stddef.h>
#include <math.h>

#define NNODE 100000
#define NEDGE 200000
#define NG 64
#define FIN 128
#define NFILT 8
#define HIDDIM 256
#define OUTDIM 64
#define ATTD 128
#define NHEADS 4

// ---------------- scratch ----------------
__device__ float g_T[NHEADS*ATTD*ATTD];
__device__ float g_r[NHEADS*ATTD];
__device__ float g_M[FIN*FIN];
__device__ float g_u[FIN];
__device__ float g_v[FIN];
__device__ float g_c[1];
__device__ float g_z[NNODE*FIN];
__device__ float g_p[NNODE];
__device__ float g_q[NNODE];
__device__ float g_x0a[NNODE*OUTDIM];
__device__ float g_x0b[NNODE*OUTDIM];
__device__ float g_hid2[NNODE*FIN];
__device__ float g_seg1[NG*OUTDIM];
__device__ float g_seg2[NG*OUTDIM];
__device__ float g_cnt[NG];
__device__ float g_xm1[NG*OUTDIM];
__device__ float g_xm2[NG*FIN];
__device__ float g_bn[2*FIN];
__device__ float g_bna[FIN];
__device__ float g_bnb[FIN];

__device__ __forceinline__ uint32_t f2tf32(float f) {
    uint32_t u;
    asm("cvt.rna.tf32.f32 %0, %1;" : "=r"(u) : "f"(f));
    return u;
}

__device__ __forceinline__ void mma_tf32(float c[4], const uint32_t a[4], const uint32_t b[2]) {
    asm volatile("mma.sync.aligned.m16n8k8.row.col.f32.tf32.tf32.f32 "
                 "{%0,%1,%2,%3}, {%4,%5,%6,%7}, {%8,%9}, {%0,%1,%2,%3};\n"
                 : "+f"(c[0]), "+f"(c[1]), "+f"(c[2]), "+f"(c[3])
                 : "r"(a[0]), "r"(a[1]), "r"(a[2]), "r"(a[3]), "r"(b[0]), "r"(b[1]));
}

// ---------------- zero accumulators ----------------
__global__ void k_zero() {
    int i = blockIdx.x * 256 + threadIdx.x;
    if (i < FIN*FIN)   g_M[i] = 0.f;
    if (i < NG*OUTDIM) { g_seg1[i] = 0.f; g_seg2[i] = 0.f; }
    if (i < NG)        g_cnt[i] = 0.f;
    if (i < 2*FIN)     g_bn[i] = 0.f;
}

// ---------------- attention precompute ----------------
__global__ void k_pre1(const float* __restrict__ W, const float* __restrict__ b,
                       const float* __restrict__ Aa) {
    __shared__ float w[ATTD];
    int bid = blockIdx.x, t = threadIdx.x;
    if (bid < NHEADS*ATTD) {
        int h = bid >> 7, i = bid & 127;
        w[t] = W[(h*ATTD + i)*ATTD + t];
        __syncthreads();
        const float* Ah = Aa + h*ATTD*ATTD;
        float s = 0.f;
        #pragma unroll 4
        for (int k = 0; k < ATTD; k++) s += w[k] * Ah[k*ATTD + t];
        g_T[(h*ATTD + i)*ATTD + t] = s;
    } else {
        int h = bid - NHEADS*ATTD;
        w[t] = b[h*ATTD + t];
        __syncthreads();
        const float* Ah = Aa + h*ATTD*ATTD;
        float s = 0.f;
        #pragma unroll 4
        for (int k = 0; k < ATTD; k++) s += w[k] * Ah[k*ATTD + t];
        g_r[h*ATTD + t] = s;
    }
}

// M += 0.25 * T_h @ W_h^T
__global__ void __launch_bounds__(256) k_mgemm(const float* __restrict__ W) {
    __shared__ float Tt[32][36], Ws[32][36];
    int it = blockIdx.x * 32, jt = blockIdx.y * 32, h = blockIdx.z;
    int t = threadIdx.x;
    int tx = t & 15, ty = t >> 4;
    float acc[2][2] = {};
    for (int kt = 0; kt < ATTD; kt += 32) {
        int r = t >> 3, k4 = (t & 7) << 2;
        *(float4*)&Tt[r][k4] = *(const float4*)(g_T + (size_t)(h*ATTD + it + r)*ATTD + kt + k4);
        *(float4*)&Ws[r][k4] = *(const float4*)(W   + (size_t)(h*ATTD + jt + r)*ATTD + kt + k4);
        __syncthreads();
        #pragma unroll 8
        for (int k = 0; k < 32; k++) {
            float a0 = Tt[ty*2][k], a1 = Tt[ty*2+1][k];
            float b0 = Ws[tx*2][k], b1 = Ws[tx*2+1][k];
            acc[0][0] = fmaf(a0, b0, acc[0][0]);
            acc[0][1] = fmaf(a0, b1, acc[0][1]);
            acc[1][0] = fmaf(a1, b0, acc[1][0]);
            acc[1][1] = fmaf(a1, b1, acc[1][1]);
        }
        __syncthreads();
    }
    #pragma unroll
    for (int i = 0; i < 2; i++)
        #pragma unroll
        for (int j = 0; j < 2; j++)
            atomicAdd(&g_M[(it + ty*2 + i)*FIN + jt + tx*2 + j], 0.25f * acc[i][j]);
}

// u, v, c
__global__ void k_uvc(const float* __restrict__ W, const float* __restrict__ b) {
    __shared__ float red[8];
    int j = blockIdx.x, k = threadIdx.x;
    int wid = k >> 5, l = k & 31;
    if (j < FIN) {
        float u = 0.f, v = 0.f;
        #pragma unroll
        for (int h = 0; h < NHEADS; h++) {
            u += g_T[(size_t)(h*ATTD + j)*ATTD + k] * b[h*ATTD + k];
            v += g_r[h*ATTD + k] * W[(size_t)(h*ATTD + j)*ATTD + k];
        }
        #pragma unroll
        for (int o = 16; o; o >>= 1) {
            u += __shfl_xor_sync(0xffffffffu, u, o);
            v += __shfl_xor_sync(0xffffffffu, v, o);
        }
        if (l == 0) { red[wid] = u; red[4 + wid] = v; }
        __syncthreads();
        if (k == 0) g_u[j] = 0.25f * (red[0] + red[1] + red[2] + red[3]);
        if (k == 1) g_v[j] = 0.25f * (red[4] + red[5] + red[6] + red[7]);
    } else {
        float c = 0.f;
        for (int i = k; i < NHEADS*ATTD; i += 128) c += g_r[i] * b[i];
        #pragma unroll
        for (int o = 16; o; o >>= 1) c += __shfl_xor_sync(0xffffffffu, c, o);
        if (l == 0) red[wid] = c;
        __syncthreads();
        if (k == 0) g_c[0] = 0.25f * (red[0] + red[1] + red[2] + red[3]);
    }
}

// ================= MEGA kernel (double-buffered B, register prefetch) =================
#define AS_STRIDE 132
#define BS_STRIDE 72
#define SM_AS (128*AS_STRIDE)
#define SM_BS (128*BS_STRIDE)
#define OFF_FVS   (SM_AS + 2*SM_BS)      // 128*8
#define OFF_UV    (OFF_FVS + 1024)       // 256
#define OFF_FOLD  (OFF_UV + 256)         // 512
#define OFF_WF2   (OFF_FOLD + 512)       // 2*512
#define OFF_BF1   (OFF_WF2 + 1024)       // 2*64
#define OFF_BF2   (OFF_BF1 + 128)        // 8
#define OFF_BL0   (OFF_BF2 + 8)          // 64
#define MEGA_SMEM ((OFF_BL0 + 64) * 4)

__global__ void __launch_bounds__(256) mega_tf32(
    const float* __restrict__ x, const float* __restrict__ Mw,
    const float* __restrict__ Wf1, const float* __restrict__ bf1,
    const float* __restrict__ Wf2, const float* __restrict__ bf2,
    const float* __restrict__ Wl0, const float* __restrict__ bl0,
    float* __restrict__ z, float* __restrict__ x0a, int M) {
    extern __shared__ uint32_t smbuf[];
    uint32_t (*As)[AS_STRIDE] = (uint32_t(*)[AS_STRIDE])smbuf;
    float* fvs  = (float*)(smbuf + OFF_FVS);
    float* uv   = (float*)(smbuf + OFF_UV);
    float* fold = (float*)(smbuf + OFF_FOLD);
    float* wf2s = (float*)(smbuf + OFF_WF2);
    float* bf1s = (float*)(smbuf + OFF_BF1);
    float* bf2s = (float*)(smbuf + OFF_BF2);
    float* bl0s = (float*)(smbuf + OFF_BL0);

    const int t = threadIdx.x;
    const int row0 = blockIdx.x * 128;

    for (int i = t; i < 128*8; i += 256) fvs[i] = 0.f;
    if (t < 128) { uv[t] = g_u[t]; uv[128 + t] = g_v[t]; }
    for (int i = t; i < 512; i += 256) {
        int j = i >> 6, o = i & 63;
        fold[i] = Wl0[(2*j)*OUTDIM + o] + Wl0[(2*j+1)*OUTDIM + o];
    }
    if (t < 64) bl0s[t] = bl0[t];
    if (t < 8)  bf2s[t] = bf2[t];
    __syncthreads();   // uv ready

    // As load + p/q (warp-uniform row: lanes of one warp cover k4=0..124 of one row)
    for (int i = t; i < 128*32; i += 256) {
        int r = i >> 5, k4 = (i & 31) << 2;
        float4 v = make_float4(0.f, 0.f, 0.f, 0.f);
        if (row0 + r < M) v = *(const float4*)(x + (size_t)(row0 + r)*FIN + k4);
        As[r][k4+0] = f2tf32(v.x); As[r][k4+1] = f2tf32(v.y);
        As[r][k4+2] = f2tf32(v.z); As[r][k4+3] = f2tf32(v.w);
        float pp = v.x*uv[k4] + v.y*uv[k4+1] + v.z*uv[k4+2] + v.w*uv[k4+3];
        float qq = v.x*uv[128+k4] + v.y*uv[128+k4+1] + v.z*uv[128+k4+2] + v.w*uv[128+k4+3];
        #pragma unroll
        for (int o = 16; o; o >>= 1) {
            pp += __shfl_xor_sync(0xffffffffu, pp, o);
            qq += __shfl_xor_sync(0xffffffffu, qq, o);
        }
        if ((i & 31) == 0 && row0 + r < M) { g_p[row0 + r] = pp; g_q[row0 + r] = qq; }
    }
    // B tile 0 into buffer 0
    for (int i = t; i < 128*16; i += 256) {
        int k = i >> 4, n4 = (i & 15) << 2;
        float4 v = *(const float4*)(Mw + (size_t)k*FIN + n4);
        uint32_t* dst = smbuf + SM_AS + k*BS_STRIDE + n4;
        dst[0] = f2tf32(v.x); dst[1] = f2tf32(v.y); dst[2] = f2tf32(v.z); dst[3] = f2tf32(v.w);
    }
    __syncthreads();

    const int wid = t >> 5, lane = t & 31;
    const int wm = (wid & 3) * 32, wn = (wid >> 2) * 32;
    const int g = lane >> 2, tg = lane & 3;

    float fvacc[4][NFILT] = {};
    float4 bpref[8];
    float4 wpref = make_float4(0.f, 0.f, 0.f, 0.f);
    float bf1pref = 0.f;

    #pragma unroll 1
    for (int tile = 0; tile < 6; tile++) {
        const int pb = tile & 1;
        uint32_t (*Bs)[BS_STRIDE] = (uint32_t(*)[BS_STRIDE])(smbuf + SM_AS + pb*SM_BS);

        // issue prefetch LDGs for tile+1 (consumed after the mma phase)
        if (tile < 5) {
            const int ncol0 = (tile + 1 < 2) ? (tile + 1)*64 : (tile - 1)*64;
            const float* nB = (tile + 1 < 2) ? Mw : Wf1;
            const int nldb = (tile + 1 < 2) ? FIN : HIDDIM;
            #pragma unroll
            for (int j = 0; j < 8; j++) {
                int i = t + j*256;
                int k = i >> 4, n4 = (i & 15) << 2;
                bpref[j] = *(const float4*)(nB + (size_t)k*nldb + ncol0 + n4);
            }
            if (tile + 1 >= 2 && t < 128) {
                int r = t >> 1, half = t & 1;
                wpref = *(const float4*)(Wf2 + (size_t)(ncol0 + r)*NFILT + half*4);
                if (half == 0) bf1pref = bf1[ncol0 + r];
            }
        }

        // mma phase
        float acc[2][4][4] = {};
        #pragma unroll
        for (int ko = 0; ko < 16; ko++) {
            int k0 = ko * 8;
            uint32_t a[2][4], b[4][2];
            #pragma unroll
            for (int mt = 0; mt < 2; mt++) {
                int r = wm + mt*16 + g;
                a[mt][0] = As[r][k0 + tg];
                a[mt][1] = As[r + 8][k0 + tg];
                a[mt][2] = As[r][k0 + tg + 4];
                a[mt][3] = As[r + 8][k0 + tg + 4];
            }
            #pragma unroll
            for (int nt = 0; nt < 4; nt++) {
                int n = wn + nt*8 + g;
                b[nt][0] = Bs[k0 + tg][n];
                b[nt][1] = Bs[k0 + tg + 4][n];
            }
            #pragma unroll
            for (int mt = 0; mt < 2; mt++)
                #pragma unroll
                for (int nt = 0; nt < 4; nt++)
                    mma_tf32(acc[mt][nt], a[mt], b[nt]);
        }

        // epilogue
        if (tile < 2) {
            const int col0 = tile*64;
            #pragma unroll
            for (int mt = 0; mt < 2; mt++) {
                int r = row0 + wm + mt*16 + g;
                #pragma unroll
                for (int nt = 0; nt < 4; nt++) {
                    int c = col0 + wn + nt*8 + 2*tg;
                    if (r < M)     *(float2*)(z + (size_t)r*FIN + c)     = make_float2(acc[mt][nt][0], acc[mt][nt][1]);
                    if (r + 8 < M) *(float2*)(z + (size_t)(r+8)*FIN + c) = make_float2(acc[mt][nt][2], acc[mt][nt][3]);
                }
            }
        } else {
            const float* wbuf = wf2s + pb*512;
            const float* bbuf = bf1s + pb*64;
            #pragma unroll
            for (int nt = 0; nt < 4; nt++) {
                int nA = wn + nt*8 + 2*tg, nB2 = nA + 1;
                float bA = bbuf[nA], bB = bbuf[nB2];
                const float* wA = wbuf + nA*NFILT;
                const float* wB = wbuf + nB2*NFILT;
                #pragma unroll
                for (int mt = 0; mt < 2; mt++) {
                    float v00 = fmaxf(acc[mt][nt][0] + bA, 0.f);
                    float v01 = fmaxf(acc[mt][nt][1] + bB, 0.f);
                    float v10 = fmaxf(acc[mt][nt][2] + bA, 0.f);
                    float v11 = fmaxf(acc[mt][nt][3] + bB, 0.f);
                    #pragma unroll
                    for (int j = 0; j < NFILT; j++) {
                        fvacc[mt*2+0][j] += v00*wA[j] + v01*wB[j];
                        fvacc[mt*2+1][j] += v10*wA[j] + v11*wB[j];
                    }
                }
            }
        }

        // commit prefetched data into the other buffer
        if (tile < 5) {
            #pragma unroll
            for (int j = 0; j < 8; j++) {
                int i = t + j*256;
                int k = i >> 4, n4 = (i & 15) << 2;
                uint32_t* dst = smbuf + SM_AS + (pb^1)*SM_BS + k*BS_STRIDE + n4;
                dst[0] = f2tf32(bpref[j].x); dst[1] = f2tf32(bpref[j].y);
                dst[2] = f2tf32(bpref[j].z); dst[3] = f2tf32(bpref[j].w);
            }
            if (tile + 1 >= 2 && t < 128) {
                int r = t >> 1, half = t & 1;
                *(float4*)(wf2s + (pb^1)*512 + r*8 + half*4) = wpref;
                if (half == 0) bf1s[(pb^1)*64 + r] = bf1pref;
            }
        }
        __syncthreads();
    }

    // reduce fvacc over quads, then into fvs
    #pragma unroll
    for (int ridx = 0; ridx < 4; ridx++)
        #pragma unroll
        for (int j = 0; j < NFILT; j++) {
            float s = fvacc[ridx][j];
            s += __shfl_xor_sync(0xffffffffu, s, 1);
            s += __shfl_xor_sync(0xffffffffu, s, 2);
            fvacc[ridx][j] = s;
        }
    if (tg == 0) {
        #pragma unroll
        for (int ridx = 0; ridx < 4; ridx++) {
            int rl = wm + (ridx >> 1)*16 + (ridx & 1)*8 + g;
            #pragma unroll
            for (int j = 0; j < NFILT; j++)
                atomicAdd(&fvs[rl*NFILT + j], fvacc[ridx][j]);
        }
    }
    __syncthreads();

    // x0a = relu((fv + bf2) @ fold + bl0)
    for (int i = t; i < 128*64; i += 256) {
        int r = i >> 6, o = i & 63;
        if (row0 + r >= M) continue;
        float s = bl0s[o];
        #pragma unroll
        for (int j = 0; j < NFILT; j++)
            s = fmaf(fvs[r*NFILT + j] + bf2s[j], fold[j*64 + o], s);
        x0a[(size_t)(row0 + r)*OUTDIM + o] = fmaxf(s, 0.f);
    }
}

// ================= DeepSet tf32 GEMM (K=64) =================
#define DAS_STRIDE 68
#define DS_SMEM ((128*DAS_STRIDE + 64*DAS_STRIDE + 128) * 4)

template<bool BNACC>
__global__ void __launch_bounds__(256) ds_tf32(
    const float* __restrict__ A,
    const float* __restrict__ B, int ldb,
    const float* __restrict__ bias,
    const float* __restrict__ sub, int ldsub,
    const int* __restrict__ batch,
    float* __restrict__ C, int ldc, int M) {
    extern __shared__ uint32_t smbuf[];
    uint32_t (*As)[DAS_STRIDE] = (uint32_t(*)[DAS_STRIDE])smbuf;
    uint32_t (*Bs)[DAS_STRIDE] = (uint32_t(*)[DAS_STRIDE])(smbuf + 128*DAS_STRIDE);
    float* bnsm = (float*)(smbuf + 128*DAS_STRIDE + 64*DAS_STRIDE);
    const int t = threadIdx.x;
    const int row0 = blockIdx.y * 128, col0 = blockIdx.x * 64;

    for (int i = t; i < 128*16; i += 256) {
        int r = i >> 4, k4 = (i & 15) << 2;
        float4 v = make_float4(0.f, 0.f, 0.f, 0.f);
        if (row0 + r < M) v = *(const float4*)(A + (size_t)(row0 + r)*OUTDIM + k4);
        As[r][k4+0] = f2tf32(v.x); As[r][k4+1] = f2tf32(v.y);
        As[r][k4+2] = f2tf32(v.z); As[r][k4+3] = f2tf32(v.w);
    }
    for (int i = t; i < 64*16; i += 256) {
        int k = i >> 4, n4 = (i & 15) << 2;
        float4 v = *(const float4*)(B + (size_t)k*ldb + col0 + n4);
        Bs[k][n4+0] = f2tf32(v.x); Bs[k][n4+1] = f2tf32(v.y);
        Bs[k][n4+2] = f2tf32(v.z); Bs[k][n4+3] = f2tf32(v.w);
    }
    if (BNACC && t < 128) bnsm[t] = 0.f;
    __syncthreads();

    const int wid = t >> 5, lane = t & 31;
    const int wm = (wid & 3) * 32, wn = (wid >> 2) * 32;
    const int g = lane >> 2, tg = lane & 3;

    float acc[2][4][4] = {};
    #pragma unroll
    for (int ko = 0; ko < 8; ko++) {
        int k0 = ko * 8;
        uint32_t a[2][4], b[4][2];
        #pragma unroll
        for (int mt = 0; mt < 2; mt++) {
            int r = wm + mt*16 + g;
            a[mt][0] = As[r][k0 + tg];
            a[mt][1] = As[r + 8][k0 + tg];
            a[mt][2] = As[r][k0 + tg + 4];
            a[mt][3] = As[r + 8][k0 + tg + 4];
        }
        #pragma unroll
        for (int nt = 0; nt < 4; nt++) {
            int n = wn + nt*8 + g;
            b[nt][0] = Bs[k0 + tg][n];
            b[nt][1] = Bs[k0 + tg + 4][n];
        }
        #pragma unroll
        for (int mt = 0; mt < 2; mt++)
            #pragma unroll
            for (int nt = 0; nt < 4; nt++)
                mma_tf32(acc[mt][nt], a[mt], b[nt]);
    }

    float s1[4][2] = {}, s2[4][2] = {};
    #pragma unroll
    for (int mt = 0; mt < 2; mt++) {
        int r0g = row0 + wm + mt*16 + g;
        int r1g = r0g + 8;
        bool ok0 = r0g < M, ok1 = r1g < M;
        int b0 = ok0 ? batch[r0g] : 0;
        int b1 = ok1 ? batch[r1g] : 0;
        const float* sub0 = sub + (size_t)b0*ldsub;
        const float* sub1 = sub + (size_t)b1*ldsub;
        #pragma unroll
        for (int nt = 0; nt < 4; nt++) {
            int cA = col0 + wn + nt*8 + 2*tg, cB = cA + 1;
            float biA = bias[cA], biB = bias[cB];
            float v00 = fmaxf(acc[mt][nt][0] + biA - sub0[cA], 0.f);
            float v01 = fmaxf(acc[mt][nt][1] + biB - sub0[cB], 0.f);
            float v10 = fmaxf(acc[mt][nt][2] + biA - sub1[cA], 0.f);
            float v11 = fmaxf(acc[mt][nt][3] + biB - sub1[cB], 0.f);
            if (ok0) *(float2*)(C + (size_t)r0g*ldc + cA) = make_float2(v00, v01);
            if (ok1) *(float2*)(C + (size_t)r1g*ldc + cA) = make_float2(v10, v11);
            if (BNACC) {
                s1[nt][0] += (ok0 ? v00 : 0.f) + (ok1 ? v10 : 0.f);
                s1[nt][1] += (ok0 ? v01 : 0.f) + (ok1 ? v11 : 0.f);
                s2[nt][0] += (ok0 ? v00*v00 : 0.f) + (ok1 ? v10*v10 : 0.f);
                s2[nt][1] += (ok0 ? v01*v01 : 0.f) + (ok1 ? v11*v11 : 0.f);
            }
        }
    }
    if (BNACC) {
        #pragma unroll
        for (int nt = 0; nt < 4; nt++)
            #pragma unroll
            for (int h = 0; h < 2; h++) {
                float a = s1[nt][h], b = s2[nt][h];
                #pragma unroll
                for (int o = 4; o < 32; o <<= 1) {
                    a += __shfl_xor_sync(0xffffffffu, a, o);
                    b += __shfl_xor_sync(0xffffffffu, b, o);
                }
                if (g == 0) {
                    int cl = wn + nt*8 + 2*tg + h;
                    atomicAdd(&bnsm[2*cl], a);
                    atomicAdd(&bnsm[2*cl + 1], b);
                }
            }
        __syncthreads();
        if (t < 64) {
            atomicAdd(&g_bn[col0 + t], bnsm[2*t]);
            atomicAdd(&g_bn[FIN + col0 + t], bnsm[2*t + 1]);
        }
    }
}

// ---------------- edge attention ----------------
__global__ void k_att(const float* __restrict__ x, const int* __restrict__ ei,
                      float* __restrict__ out) {
    int wid = (blockIdx.x * blockDim.x + threadIdx.x) >> 5;
    int l = threadIdx.x & 31;
    if (wid >= NEDGE) return;
    int row = ei[wid], col = ei[NEDGE + wid];
    float4 zv = *(const float4*)(g_z + (size_t)row*FIN + l*4);
    float4 xv = *(const float4*)(x   + (size_t)col*FIN + l*4);
    float d = zv.x*xv.x + zv.y*xv.y + zv.z*xv.z + zv.w*xv.w;
    #pragma unroll
    for (int o = 16; o; o >>= 1) d += __shfl_xor_sync(0xffffffffu, d, o);
    if (l == 0) {
        float s = d + g_p[row] + g_q[col] + g_c[0];
        out[(size_t)NNODE*FIN + wid] = 1.f / (1.f + expf(-s));
    }
}

// ---------------- segment sum over sorted batch (MLP>=4, 782 blocks) ----------------
__global__ void k_seg(const float* __restrict__ v, const int* __restrict__ batch,
                      float* __restrict__ sum, int do_cnt) {
    int t = threadIdx.x;
    int f = t & 63, w = t >> 6;   // 4 row-lanes per column
    int r0 = blockIdx.x * 128;
    int rend = min(r0 + 128, NNODE);
    float acc = 0.f, ccnt = 0.f;
    int cur = -1;
    for (int rb = r0 + w; rb < rend; rb += 16) {
        float vv[4]; int gg[4];
        #pragma unroll
        for (int j = 0; j < 4; j++) {
            int r = rb + j*4;
            bool ok = r < rend;
            vv[j] = ok ? v[(size_t)r*64 + f] : 0.f;
            gg[j] = ok ? __ldg(&batch[r]) : -2;
        }
        #pragma unroll
        for (int j = 0; j < 4; j++) {
            if (gg[j] != cur) {
                if (cur >= 0) {
                    atomicAdd(&sum[cur*64 + f], acc);
                    if (do_cnt && f == 0) atomicAdd(&g_cnt[cur], ccnt);
                }
                acc = 0.f; ccnt = 0.f; cur = gg[j];
            }
            if (gg[j] >= 0) { acc += vv[j]; ccnt += 1.f; }
        }
    }
    if (cur >= 0) {
        atomicAdd(&sum[cur*64 + f], acc);
        if (do_cnt && f == 0) atomicAdd(&g_cnt[cur], ccnt);
    }
}

__global__ void k_mean1(const float* __restrict__ L1) {
    __shared__ float mean[OUTDIM];
    int g = blockIdx.x, t = threadIdx.x;
    float c = fmaxf(g_cnt[g], 1.f);
    mean[t] = g_seg1[g*64 + t] / c;
    __syncthreads();
    float s = 0.f;
    #pragma unroll 4
    for (int k = 0; k < 64; k++) s += mean[k] * L1[k*64 + t];
    g_xm1[g*64 + t] = s;
}

__global__ void k_mean2(const float* __restrict__ L2) {
    __shared__ float mean[OUTDIM];
    int g = blockIdx.x, t = threadIdx.x;
    if (t < 64) mean[t] = g_seg2[g*64 + t] / fmaxf(g_cnt[g], 1.f);
    __syncthreads();
    float s = 0.f;
    #pragma unroll 4
    for (int k = 0; k < 64; k++) s += mean[k] * L2[k*128 + t];
    g_xm2[g*128 + t] = s;
}

__global__ void k_bnfin(const float* __restrict__ gamma, const float* __restrict__ beta) {
    int f = threadIdx.x;
    float mu = g_bn[f] / (float)NNODE;
    float var = g_bn[128 + f] / (float)NNODE - mu*mu;
    float a = gamma[f] * rsqrtf(var + 1e-5f);
    g_bna[f] = a;
    g_bnb[f] = beta[f] - mu*a;
}

__global__ void k_out(const float* __restrict__ x, float* __restrict__ out) {
    int i = blockIdx.x * blockDim.x + threadIdx.x;
    if (i >= NNODE*FIN/4) return;
    int f4 = (i & 31) * 4;
    float4 xv = ((const float4*)x)[i];
    float4 hv = ((const float4*)g_hid2)[i];
    float4 a  = *(const float4*)(g_bna + f4);
    float4 b  = *(const float4*)(g_bnb + f4);
    float4 o;
    o.x = xv.x + hv.x*a.x + b.x;
    o.y = xv.y + hv.y*a.y + b.y;
    o.z = xv.z + hv.z*a.z + b.z;
    o.w = xv.w + hv.w*a.w + b.w;
    ((float4*)out)[i] = o;
}

// ---------------- host launch ----------------
extern "C" void kernel_launch(void* const* d_in, const int* in_sizes, int n_in,
                              void* d_out, int out_size) {
    const float* x      = (const float*)d_in[0];
    const int*   ei     = (const int*)  d_in[1];
    const int*   batch  = (const int*)  d_in[2];
    const float* W_f1   = (const float*)d_in[3];
    const float* b_f1   = (const float*)d_in[4];
    const float* W_f2   = (const float*)d_in[5];
    const float* b_f2   = (const float*)d_in[6];
    const float* W_l0   = (const float*)d_in[7];
    const float* b_l0   = (const float*)d_in[8];
    const float* G1     = (const float*)d_in[9];
    const float* b_g1   = (const float*)d_in[10];
    const float* L1     = (const float*)d_in[11];
    const float* G2     = (const float*)d_in[12];
    const float* b_g2   = (const float*)d_in[13];
    const float* L2     = (const float*)d_in[14];
    const float* gamma  = (const float*)d_in[15];
    const float* beta   = (const float*)d_in[16];
    const float* W_att  = (const float*)d_in[17];
    const float* b_att  = (const float*)d_in[18];
    const float* A_att  = (const float*)d_in[19];
    float* out = (float*)d_out;

    float *pM, *pz, *px0a, *px0b, *pxm1, *pxm2, *phid2, *pseg1, *pseg2;
    cudaGetSymbolAddress((void**)&pM,    g_M);
    cudaGetSymbolAddress((void**)&pz,    g_z);
    cudaGetSymbolAddress((void**)&px0a,  g_x0a);
    cudaGetSymbolAddress((void**)&px0b,  g_x0b);
    cudaGetSymbolAddress((void**)&pxm1,  g_xm1);
    cudaGetSymbolAddress((void**)&pxm2,  g_xm2);
    cudaGetSymbolAddress((void**)&phid2, g_hid2);
    cudaGetSymbolAddress((void**)&pseg1, g_seg1);
    cudaGetSymbolAddress((void**)&pseg2, g_seg2);

    cudaFuncSetAttribute(mega_tf32, cudaFuncAttributeMaxDynamicSharedMemorySize, MEGA_SMEM);
    cudaFuncSetAttribute(ds_tf32<false>, cudaFuncAttributeMaxDynamicSharedMemorySize, DS_SMEM);
    cudaFuncSetAttribute(ds_tf32<true>,  cudaFuncAttributeMaxDynamicSharedMemorySize, DS_SMEM);

    const int rb128 = (NNODE + 127) / 128;  // 782

    k_zero<<<64, 256>>>();
    k_pre1<<<NHEADS*ATTD + NHEADS, 128>>>(W_att, b_att, A_att);
    k_mgemm<<<dim3(4, 4, 4), 256>>>(W_att);
    k_uvc<<<FIN + 1, 128>>>(W_att, b_att);

    mega_tf32<<<rb128, 256, MEGA_SMEM>>>(x, pM, W_f1, b_f1, W_f2, b_f2,
                                         W_l0, b_l0, pz, px0a, NNODE);
    k_att<<<(NEDGE*32 + 255)/256, 256>>>(x, ei, out);

    k_seg<<<rb128, 256>>>(px0a, batch, pseg1, 1);
    k_mean1<<<NG, 64>>>(L1);
    ds_tf32<false><<<dim3(1, rb128), 256, DS_SMEM>>>(
        px0a, G1, OUTDIM, b_g1, pxm1, OUTDIM, batch, px0b, OUTDIM, NNODE);

    k_seg<<<rb128, 256>>>(px0b, batch, pseg2, 0);
    k_mean2<<<NG, 128>>>(L2);
    ds_tf32<true><<<dim3(2, rb128), 256, DS_SMEM>>>(
        px0b, G2, FIN, b_g2, pxm2, FIN, batch, phid2, FIN, NNODE);

    k_bnfin<<<1, 128>>>(gamma, beta);
    k_out<<<(NNODE*FIN/4 + 255)/256, 256>>>(x, out);
}

// round 10
// speedup vs baseline: 2.5107x; 1.0050x over previous
#include <cuda_runtime.h>
#include <stdint.h>
#include <stddef.h>
#include <math.h>

#define NNODE 100000
#define NEDGE 200000
#define NG 64
#define FIN 128
#define NFILT 8
#define HIDDIM 256
#define OUTDIM 64
#define ATTD 128
#define NHEADS 4

// ---------------- scratch ----------------
__device__ float g_T[NHEADS*ATTD*ATTD];
__device__ float g_r[NHEADS*ATTD];
__device__ float g_M[FIN*FIN];
__device__ float g_u[FIN];
__device__ float g_v[FIN];
__device__ float g_c[1];
__device__ float g_z[NNODE*FIN];
__device__ float g_p[NNODE];
__device__ float g_q[NNODE];
__device__ float g_x0a[NNODE*OUTDIM];
__device__ float g_x0b[NNODE*OUTDIM];
__device__ float g_hid2[NNODE*FIN];
__device__ float g_seg1[NG*OUTDIM];
__device__ float g_seg2[NG*OUTDIM];
__device__ float g_cnt[NG];
__device__ float g_xm1[NG*OUTDIM];
__device__ float g_xm2[NG*FIN];
__device__ float g_bn[2*FIN];
__device__ float g_bna[FIN];
__device__ float g_bnb[FIN];

__device__ __forceinline__ uint32_t f2tf32(float f) {
    uint32_t u;
    asm("cvt.rna.tf32.f32 %0, %1;" : "=r"(u) : "f"(f));
    return u;
}

__device__ __forceinline__ void mma_tf32(float c[4], const uint32_t a[4], const uint32_t b[2]) {
    asm volatile("mma.sync.aligned.m16n8k8.row.col.f32.tf32.tf32.f32 "
                 "{%0,%1,%2,%3}, {%4,%5,%6,%7}, {%8,%9}, {%0,%1,%2,%3};\n"
                 : "+f"(c[0]), "+f"(c[1]), "+f"(c[2]), "+f"(c[3])
                 : "r"(a[0]), "r"(a[1]), "r"(a[2]), "r"(a[3]), "r"(b[0]), "r"(b[1]));
}

// ---------------- zero accumulators ----------------
__global__ void k_zero() {
    int i = blockIdx.x * 256 + threadIdx.x;
    if (i < FIN*FIN)   g_M[i] = 0.f;
    if (i < NG*OUTDIM) { g_seg1[i] = 0.f; g_seg2[i] = 0.f; }
    if (i < NG)        g_cnt[i] = 0.f;
    if (i < 2*FIN)     g_bn[i] = 0.f;
}

// ---------------- attention precompute ----------------
__global__ void k_pre1(const float* __restrict__ W, const float* __restrict__ b,
                       const float* __restrict__ Aa) {
    __shared__ float w[ATTD];
    int bid = blockIdx.x, t = threadIdx.x;
    if (bid < NHEADS*ATTD) {
        int h = bid >> 7, i = bid & 127;
        w[t] = W[(h*ATTD + i)*ATTD + t];
        __syncthreads();
        const float* Ah = Aa + h*ATTD*ATTD;
        float s = 0.f;
        #pragma unroll 4
        for (int k = 0; k < ATTD; k++) s += w[k] * Ah[k*ATTD + t];
        g_T[(h*ATTD + i)*ATTD + t] = s;
    } else {
        int h = bid - NHEADS*ATTD;
        w[t] = b[h*ATTD + t];
        __syncthreads();
        const float* Ah = Aa + h*ATTD*ATTD;
        float s = 0.f;
        #pragma unroll 4
        for (int k = 0; k < ATTD; k++) s += w[k] * Ah[k*ATTD + t];
        g_r[h*ATTD + t] = s;
    }
}

// M += 0.25 * T_h @ W_h^T
__global__ void __launch_bounds__(256) k_mgemm(const float* __restrict__ W) {
    __shared__ float Tt[32][36], Ws[32][36];
    int it = blockIdx.x * 32, jt = blockIdx.y * 32, h = blockIdx.z;
    int t = threadIdx.x;
    int tx = t & 15, ty = t >> 4;
    float acc[2][2] = {};
    for (int kt = 0; kt < ATTD; kt += 32) {
        int r = t >> 3, k4 = (t & 7) << 2;
        *(float4*)&Tt[r][k4] = *(const float4*)(g_T + (size_t)(h*ATTD + it + r)*ATTD + kt + k4);
        *(float4*)&Ws[r][k4] = *(const float4*)(W   + (size_t)(h*ATTD + jt + r)*ATTD + kt + k4);
        __syncthreads();
        #pragma unroll 8
        for (int k = 0; k < 32; k++) {
            float a0 = Tt[ty*2][k], a1 = Tt[ty*2+1][k];
            float b0 = Ws[tx*2][k], b1 = Ws[tx*2+1][k];
            acc[0][0] = fmaf(a0, b0, acc[0][0]);
            acc[0][1] = fmaf(a0, b1, acc[0][1]);
            acc[1][0] = fmaf(a1, b0, acc[1][0]);
            acc[1][1] = fmaf(a1, b1, acc[1][1]);
        }
        __syncthreads();
    }
    #pragma unroll
    for (int i = 0; i < 2; i++)
        #pragma unroll
        for (int j = 0; j < 2; j++)
            atomicAdd(&g_M[(it + ty*2 + i)*FIN + jt + tx*2 + j], 0.25f * acc[i][j]);
}

// u, v, c
__global__ void k_uvc(const float* __restrict__ W, const float* __restrict__ b) {
    __shared__ float red[8];
    int j = blockIdx.x, k = threadIdx.x;
    int wid = k >> 5, l = k & 31;
    if (j < FIN) {
        float u = 0.f, v = 0.f;
        #pragma unroll
        for (int h = 0; h < NHEADS; h++) {
            u += g_T[(size_t)(h*ATTD + j)*ATTD + k] * b[h*ATTD + k];
            v += g_r[h*ATTD + k] * W[(size_t)(h*ATTD + j)*ATTD + k];
        }
        #pragma unroll
        for (int o = 16; o; o >>= 1) {
            u += __shfl_xor_sync(0xffffffffu, u, o);
            v += __shfl_xor_sync(0xffffffffu, v, o);
        }
        if (l == 0) { red[wid] = u; red[4 + wid] = v; }
        __syncthreads();
        if (k == 0) g_u[j] = 0.25f * (red[0] + red[1] + red[2] + red[3]);
        if (k == 1) g_v[j] = 0.25f * (red[4] + red[5] + red[6] + red[7]);
    } else {
        float c = 0.f;
        for (int i = k; i < NHEADS*ATTD; i += 128) c += g_r[i] * b[i];
        #pragma unroll
        for (int o = 16; o; o >>= 1) c += __shfl_xor_sync(0xffffffffu, c, o);
        if (l == 0) red[wid] = c;
        __syncthreads();
        if (k == 0) g_c[0] = 0.25f * (red[0] + red[1] + red[2] + red[3]);
    }
}

// ================= MEGA kernel (double-buffered B, register prefetch) =================
#define AS_STRIDE 132
#define BS_STRIDE 72
#define SM_AS (128*AS_STRIDE)
#define SM_BS (128*BS_STRIDE)
#define OFF_FVS   (SM_AS + 2*SM_BS)
#define OFF_UV    (OFF_FVS + 1024)
#define OFF_FOLD  (OFF_UV + 256)
#define OFF_WF2   (OFF_FOLD + 512)
#define OFF_BF1   (OFF_WF2 + 1024)
#define OFF_BF2   (OFF_BF1 + 128)
#define OFF_BL0   (OFF_BF2 + 8)
#define MEGA_SMEM ((OFF_BL0 + 64) * 4)

__global__ void __launch_bounds__(256) mega_tf32(
    const float* __restrict__ x, const float* __restrict__ Mw,
    const float* __restrict__ Wf1, const float* __restrict__ bf1,
    const float* __restrict__ Wf2, const float* __restrict__ bf2,
    const float* __restrict__ Wl0, const float* __restrict__ bl0,
    float* __restrict__ z, float* __restrict__ x0a, int M) {
    extern __shared__ uint32_t smbuf[];
    uint32_t (*As)[AS_STRIDE] = (uint32_t(*)[AS_STRIDE])smbuf;
    float* fvs  = (float*)(smbuf + OFF_FVS);
    float* uv   = (float*)(smbuf + OFF_UV);
    float* fold = (float*)(smbuf + OFF_FOLD);
    float* wf2s = (float*)(smbuf + OFF_WF2);
    float* bf1s = (float*)(smbuf + OFF_BF1);
    float* bf2s = (float*)(smbuf + OFF_BF2);
    float* bl0s = (float*)(smbuf + OFF_BL0);

    const int t = threadIdx.x;
    const int row0 = blockIdx.x * 128;

    for (int i = t; i < 128*8; i += 256) fvs[i] = 0.f;
    if (t < 128) { uv[t] = g_u[t]; uv[128 + t] = g_v[t]; }
    for (int i = t; i < 512; i += 256) {
        int j = i >> 6, o = i & 63;
        fold[i] = Wl0[(2*j)*OUTDIM + o] + Wl0[(2*j+1)*OUTDIM + o];
    }
    if (t < 64) bl0s[t] = bl0[t];
    if (t < 8)  bf2s[t] = bf2[t];
    __syncthreads();

    for (int i = t; i < 128*32; i += 256) {
        int r = i >> 5, k4 = (i & 31) << 2;
        float4 v = make_float4(0.f, 0.f, 0.f, 0.f);
        if (row0 + r < M) v = *(const float4*)(x + (size_t)(row0 + r)*FIN + k4);
        As[r][k4+0] = f2tf32(v.x); As[r][k4+1] = f2tf32(v.y);
        As[r][k4+2] = f2tf32(v.z); As[r][k4+3] = f2tf32(v.w);
        float pp = v.x*uv[k4] + v.y*uv[k4+1] + v.z*uv[k4+2] + v.w*uv[k4+3];
        float qq = v.x*uv[128+k4] + v.y*uv[128+k4+1] + v.z*uv[128+k4+2] + v.w*uv[128+k4+3];
        #pragma unroll
        for (int o = 16; o; o >>= 1) {
            pp += __shfl_xor_sync(0xffffffffu, pp, o);
            qq += __shfl_xor_sync(0xffffffffu, qq, o);
        }
        if ((i & 31) == 0 && row0 + r < M) { g_p[row0 + r] = pp; g_q[row0 + r] = qq; }
    }
    for (int i = t; i < 128*16; i += 256) {
        int k = i >> 4, n4 = (i & 15) << 2;
        float4 v = *(const float4*)(Mw + (size_t)k*FIN + n4);
        uint32_t* dst = smbuf + SM_AS + k*BS_STRIDE + n4;
        dst[0] = f2tf32(v.x); dst[1] = f2tf32(v.y); dst[2] = f2tf32(v.z); dst[3] = f2tf32(v.w);
    }
    __syncthreads();

    const int wid = t >> 5, lane = t & 31;
    const int wm = (wid & 3) * 32, wn = (wid >> 2) * 32;
    const int g = lane >> 2, tg = lane & 3;

    float fvacc[4][NFILT] = {};
    float4 bpref[8];
    float4 wpref = make_float4(0.f, 0.f, 0.f, 0.f);
    float bf1pref = 0.f;

    #pragma unroll 1
    for (int tile = 0; tile < 6; tile++) {
        const int pb = tile & 1;
        uint32_t (*Bs)[BS_STRIDE] = (uint32_t(*)[BS_STRIDE])(smbuf + SM_AS + pb*SM_BS);

        if (tile < 5) {
            const int ncol0 = (tile + 1 < 2) ? (tile + 1)*64 : (tile - 1)*64;
            const float* nB = (tile + 1 < 2) ? Mw : Wf1;
            const int nldb = (tile + 1 < 2) ? FIN : HIDDIM;
            #pragma unroll
            for (int j = 0; j < 8; j++) {
                int i = t + j*256;
                int k = i >> 4, n4 = (i & 15) << 2;
                bpref[j] = *(const float4*)(nB + (size_t)k*nldb + ncol0 + n4);
            }
            if (tile + 1 >= 2 && t < 128) {
                int r = t >> 1, half = t & 1;
                wpref = *(const float4*)(Wf2 + (size_t)(ncol0 + r)*NFILT + half*4);
                if (half == 0) bf1pref = bf1[ncol0 + r];
            }
        }

        float acc[2][4][4] = {};
        #pragma unroll
        for (int ko = 0; ko < 16; ko++) {
            int k0 = ko * 8;
            uint32_t a[2][4], b[4][2];
            #pragma unroll
            for (int mt = 0; mt < 2; mt++) {
                int r = wm + mt*16 + g;
                a[mt][0] = As[r][k0 + tg];
                a[mt][1] = As[r + 8][k0 + tg];
                a[mt][2] = As[r][k0 + tg + 4];
                a[mt][3] = As[r + 8][k0 + tg + 4];
            }
            #pragma unroll
            for (int nt = 0; nt < 4; nt++) {
                int n = wn + nt*8 + g;
                b[nt][0] = Bs[k0 + tg][n];
                b[nt][1] = Bs[k0 + tg + 4][n];
            }
            #pragma unroll
            for (int mt = 0; mt < 2; mt++)
                #pragma unroll
                for (int nt = 0; nt < 4; nt++)
                    mma_tf32(acc[mt][nt], a[mt], b[nt]);
        }

        if (tile < 2) {
            const int col0 = tile*64;
            #pragma unroll
            for (int mt = 0; mt < 2; mt++) {
                int r = row0 + wm + mt*16 + g;
                #pragma unroll
                for (int nt = 0; nt < 4; nt++) {
                    int c = col0 + wn + nt*8 + 2*tg;
                    if (r < M)     *(float2*)(z + (size_t)r*FIN + c)     = make_float2(acc[mt][nt][0], acc[mt][nt][1]);
                    if (r + 8 < M) *(float2*)(z + (size_t)(r+8)*FIN + c) = make_float2(acc[mt][nt][2], acc[mt][nt][3]);
                }
            }
        } else {
            const float* wbuf = wf2s + pb*512;
            const float* bbuf = bf1s + pb*64;
            #pragma unroll
            for (int nt = 0; nt < 4; nt++) {
                int nA = wn + nt*8 + 2*tg, nB2 = nA + 1;
                float bA = bbuf[nA], bB = bbuf[nB2];
                const float* wA = wbuf + nA*NFILT;
                const float* wB = wbuf + nB2*NFILT;
                #pragma unroll
                for (int mt = 0; mt < 2; mt++) {
                    float v00 = fmaxf(acc[mt][nt][0] + bA, 0.f);
                    float v01 = fmaxf(acc[mt][nt][1] + bB, 0.f);
                    float v10 = fmaxf(acc[mt][nt][2] + bA, 0.f);
                    float v11 = fmaxf(acc[mt][nt][3] + bB, 0.f);
                    #pragma unroll
                    for (int j = 0; j < NFILT; j++) {
                        fvacc[mt*2+0][j] += v00*wA[j] + v01*wB[j];
                        fvacc[mt*2+1][j] += v10*wA[j] + v11*wB[j];
                    }
                }
            }
        }

        if (tile < 5) {
            #pragma unroll
            for (int j = 0; j < 8; j++) {
                int i = t + j*256;
                int k = i >> 4, n4 = (i & 15) << 2;
                uint32_t* dst = smbuf + SM_AS + (pb^1)*SM_BS + k*BS_STRIDE + n4;
                dst[0] = f2tf32(bpref[j].x); dst[1] = f2tf32(bpref[j].y);
                dst[2] = f2tf32(bpref[j].z); dst[3] = f2tf32(bpref[j].w);
            }
            if (tile + 1 >= 2 && t < 128) {
                int r = t >> 1, half = t & 1;
                *(float4*)(wf2s + (pb^1)*512 + r*8 + half*4) = wpref;
                if (half == 0) bf1s[(pb^1)*64 + r] = bf1pref;
            }
        }
        __syncthreads();
    }

    #pragma unroll
    for (int ridx = 0; ridx < 4; ridx++)
        #pragma unroll
        for (int j = 0; j < NFILT; j++) {
            float s = fvacc[ridx][j];
            s += __shfl_xor_sync(0xffffffffu, s, 1);
            s += __shfl_xor_sync(0xffffffffu, s, 2);
            fvacc[ridx][j] = s;
        }
    if (tg == 0) {
        #pragma unroll
        for (int ridx = 0; ridx < 4; ridx++) {
            int rl = wm + (ridx >> 1)*16 + (ridx & 1)*8 + g;
            #pragma unroll
            for (int j = 0; j < NFILT; j++)
                atomicAdd(&fvs[rl*NFILT + j], fvacc[ridx][j]);
        }
    }
    __syncthreads();

    for (int i = t; i < 128*64; i += 256) {
        int r = i >> 6, o = i & 63;
        if (row0 + r >= M) continue;
        float s = bl0s[o];
        #pragma unroll
        for (int j = 0; j < NFILT; j++)
            s = fmaf(fvs[r*NFILT + j] + bf2s[j], fold[j*64 + o], s);
        x0a[(size_t)(row0 + r)*OUTDIM + o] = fmaxf(s, 0.f);
    }
}

// ================= DeepSet tf32 GEMM (K=64) =================
#define DAS_STRIDE 68
#define DS_SMEM ((128*DAS_STRIDE + 64*DAS_STRIDE + 128) * 4)

template<bool BNACC>
__global__ void __launch_bounds__(256) ds_tf32(
    const float* __restrict__ A,
    const float* __restrict__ B, int ldb,
    const float* __restrict__ bias,
    const float* __restrict__ sub, int ldsub,
    const int* __restrict__ batch,
    float* __restrict__ C, int ldc, int M) {
    extern __shared__ uint32_t smbuf[];
    uint32_t (*As)[DAS_STRIDE] = (uint32_t(*)[DAS_STRIDE])smbuf;
    uint32_t (*Bs)[DAS_STRIDE] = (uint32_t(*)[DAS_STRIDE])(smbuf + 128*DAS_STRIDE);
    float* bnsm = (float*)(smbuf + 128*DAS_STRIDE + 64*DAS_STRIDE);
    const int t = threadIdx.x;
    const int row0 = blockIdx.y * 128, col0 = blockIdx.x * 64;

    for (int i = t; i < 128*16; i += 256) {
        int r = i >> 4, k4 = (i & 15) << 2;
        float4 v = make_float4(0.f, 0.f, 0.f, 0.f);
        if (row0 + r < M) v = *(const float4*)(A + (size_t)(row0 + r)*OUTDIM + k4);
        As[r][k4+0] = f2tf32(v.x); As[r][k4+1] = f2tf32(v.y);
        As[r][k4+2] = f2tf32(v.z); As[r][k4+3] = f2tf32(v.w);
    }
    for (int i = t; i < 64*16; i += 256) {
        int k = i >> 4, n4 = (i & 15) << 2;
        float4 v = *(const float4*)(B + (size_t)k*ldb + col0 + n4);
        Bs[k][n4+0] = f2tf32(v.x); Bs[k][n4+1] = f2tf32(v.y);
        Bs[k][n4+2] = f2tf32(v.z); Bs[k][n4+3] = f2tf32(v.w);
    }
    if (BNACC && t < 128) bnsm[t] = 0.f;
    __syncthreads();

    const int wid = t >> 5, lane = t & 31;
    const int wm = (wid & 3) * 32, wn = (wid >> 2) * 32;
    const int g = lane >> 2, tg = lane & 3;

    float acc[2][4][4] = {};
    #pragma unroll
    for (int ko = 0; ko < 8; ko++) {
        int k0 = ko * 8;
        uint32_t a[2][4], b[4][2];
        #pragma unroll
        for (int mt = 0; mt < 2; mt++) {
            int r = wm + mt*16 + g;
            a[mt][0] = As[r][k0 + tg];
            a[mt][1] = As[r + 8][k0 + tg];
            a[mt][2] = As[r][k0 + tg + 4];
            a[mt][3] = As[r + 8][k0 + tg + 4];
        }
        #pragma unroll
        for (int nt = 0; nt < 4; nt++) {
            int n = wn + nt*8 + g;
            b[nt][0] = Bs[k0 + tg][n];
            b[nt][1] = Bs[k0 + tg + 4][n];
        }
        #pragma unroll
        for (int mt = 0; mt < 2; mt++)
            #pragma unroll
            for (int nt = 0; nt < 4; nt++)
                mma_tf32(acc[mt][nt], a[mt], b[nt]);
    }

    float s1[4][2] = {}, s2[4][2] = {};
    #pragma unroll
    for (int mt = 0; mt < 2; mt++) {
        int r0g = row0 + wm + mt*16 + g;
        int r1g = r0g + 8;
        bool ok0 = r0g < M, ok1 = r1g < M;
        int b0 = ok0 ? batch[r0g] : 0;
        int b1 = ok1 ? batch[r1g] : 0;
        const float* sub0 = sub + (size_t)b0*ldsub;
        const float* sub1 = sub + (size_t)b1*ldsub;
        #pragma unroll
        for (int nt = 0; nt < 4; nt++) {
            int cA = col0 + wn + nt*8 + 2*tg, cB = cA + 1;
            float biA = bias[cA], biB = bias[cB];
            float v00 = fmaxf(acc[mt][nt][0] + biA - sub0[cA], 0.f);
            float v01 = fmaxf(acc[mt][nt][1] + biB - sub0[cB], 0.f);
            float v10 = fmaxf(acc[mt][nt][2] + biA - sub1[cA], 0.f);
            float v11 = fmaxf(acc[mt][nt][3] + biB - sub1[cB], 0.f);
            if (ok0) *(float2*)(C + (size_t)r0g*ldc + cA) = make_float2(v00, v01);
            if (ok1) *(float2*)(C + (size_t)r1g*ldc + cA) = make_float2(v10, v11);
            if (BNACC) {
                s1[nt][0] += (ok0 ? v00 : 0.f) + (ok1 ? v10 : 0.f);
                s1[nt][1] += (ok0 ? v01 : 0.f) + (ok1 ? v11 : 0.f);
                s2[nt][0] += (ok0 ? v00*v00 : 0.f) + (ok1 ? v10*v10 : 0.f);
                s2[nt][1] += (ok0 ? v01*v01 : 0.f) + (ok1 ? v11*v11 : 0.f);
            }
        }
    }
    if (BNACC) {
        #pragma unroll
        for (int nt = 0; nt < 4; nt++)
            #pragma unroll
            for (int h = 0; h < 2; h++) {
                float a = s1[nt][h], b = s2[nt][h];
                #pragma unroll
                for (int o = 4; o < 32; o <<= 1) {
                    a += __shfl_xor_sync(0xffffffffu, a, o);
                    b += __shfl_xor_sync(0xffffffffu, b, o);
                }
                if (g == 0) {
                    int cl = wn + nt*8 + 2*tg + h;
                    atomicAdd(&bnsm[2*cl], a);
                    atomicAdd(&bnsm[2*cl + 1], b);
                }
            }
        __syncthreads();
        if (t < 64) {
            atomicAdd(&g_bn[col0 + t], bnsm[2*t]);
            atomicAdd(&g_bn[FIN + col0 + t], bnsm[2*t + 1]);
        }
    }
}

// ---------------- edge attention ----------------
__global__ void k_att(const float* __restrict__ x, const int* __restrict__ ei,
                      float* __restrict__ out) {
    int wid = (blockIdx.x * blockDim.x + threadIdx.x) >> 5;
    int l = threadIdx.x & 31;
    if (wid >= NEDGE) return;
    int row = ei[wid], col = ei[NEDGE + wid];
    float4 zv = *(const float4*)(g_z + (size_t)row*FIN + l*4);
    float4 xv = *(const float4*)(x   + (size_t)col*FIN + l*4);
    float d = zv.x*xv.x + zv.y*xv.y + zv.z*xv.z + zv.w*xv.w;
    #pragma unroll
    for (int o = 16; o; o >>= 1) d += __shfl_xor_sync(0xffffffffu, d, o);
    if (l == 0) {
        float s = d + g_p[row] + g_q[col] + g_c[0];
        out[(size_t)NNODE*FIN + wid] = 1.f / (1.f + expf(-s));
    }
}

// ---------------- segment sum over sorted batch (MLP>=4, 782 blocks) ----------------
__global__ void k_seg(const float* __restrict__ v, const int* __restrict__ batch,
                      float* __restrict__ sum, int do_cnt) {
    int t = threadIdx.x;
    int f = t & 63, w = t >> 6;
    int r0 = blockIdx.x * 128;
    int rend = min(r0 + 128, NNODE);
    float acc = 0.f, ccnt = 0.f;
    int cur = -1;
    for (int rb = r0 + w; rb < rend; rb += 16) {
        float vv[4]; int gg[4];
        #pragma unroll
        for (int j = 0; j < 4; j++) {
            int r = rb + j*4;
            bool ok = r < rend;
            vv[j] = ok ? v[(size_t)r*64 + f] : 0.f;
            gg[j] = ok ? __ldg(&batch[r]) : -2;
        }
        #pragma unroll
        for (int j = 0; j < 4; j++) {
            if (gg[j] != cur) {
                if (cur >= 0) {
                    atomicAdd(&sum[cur*64 + f], acc);
                    if (do_cnt && f == 0) atomicAdd(&g_cnt[cur], ccnt);
                }
                acc = 0.f; ccnt = 0.f; cur = gg[j];
            }
            if (gg[j] >= 0) { acc += vv[j]; ccnt += 1.f; }
        }
    }
    if (cur >= 0) {
        atomicAdd(&sum[cur*64 + f], acc);
        if (do_cnt && f == 0) atomicAdd(&g_cnt[cur], ccnt);
    }
}

__global__ void k_mean1(const float* __restrict__ L1) {
    __shared__ float mean[OUTDIM];
    int g = blockIdx.x, t = threadIdx.x;
    float c = fmaxf(g_cnt[g], 1.f);
    mean[t] = g_seg1[g*64 + t] / c;
    __syncthreads();
    float s = 0.f;
    #pragma unroll 4
    for (int k = 0; k < 64; k++) s += mean[k] * L1[k*64 + t];
    g_xm1[g*64 + t] = s;
}

__global__ void k_mean2(const float* __restrict__ L2) {
    __shared__ float mean[OUTDIM];
    int g = blockIdx.x, t = threadIdx.x;
    if (t < 64) mean[t] = g_seg2[g*64 + t] / fmaxf(g_cnt[g], 1.f);
    __syncthreads();
    float s = 0.f;
    #pragma unroll 4
    for (int k = 0; k < 64; k++) s += mean[k] * L2[k*128 + t];
    g_xm2[g*128 + t] = s;
}

__global__ void k_bnfin(const float* __restrict__ gamma, const float* __restrict__ beta) {
    int f = threadIdx.x;
    float mu = g_bn[f] / (float)NNODE;
    float var = g_bn[128 + f] / (float)NNODE - mu*mu;
    float a = gamma[f] * rsqrtf(var + 1e-5f);
    g_bna[f] = a;
    g_bnb[f] = beta[f] - mu*a;
}

__global__ void k_out(const float* __restrict__ x, float* __restrict__ out) {
    int i = blockIdx.x * blockDim.x + threadIdx.x;
    if (i >= NNODE*FIN/4) return;
    int f4 = (i & 31) * 4;
    float4 xv = ((const float4*)x)[i];
    float4 hv = ((const float4*)g_hid2)[i];
    float4 a  = *(const float4*)(g_bna + f4);
    float4 b  = *(const float4*)(g_bnb + f4);
    float4 o;
    o.x = xv.x + hv.x*a.x + b.x;
    o.y = xv.y + hv.y*a.y + b.y;
    o.z = xv.z + hv.z*a.z + b.z;
    o.w = xv.w + hv.w*a.w + b.w;
    ((float4*)out)[i] = o;
}

// ---------------- host launch ----------------
extern "C" void kernel_launch(void* const* d_in, const int* in_sizes, int n_in,
                              void* d_out, int out_size) {
    const float* x      = (const float*)d_in[0];
    const int*   ei     = (const int*)  d_in[1];
    const int*   batch  = (const int*)  d_in[2];
    const float* W_f1   = (const float*)d_in[3];
    const float* b_f1   = (const float*)d_in[4];
    const float* W_f2   = (const float*)d_in[5];
    const float* b_f2   = (const float*)d_in[6];
    const float* W_l0   = (const float*)d_in[7];
    const float* b_l0   = (const float*)d_in[8];
    const float* G1     = (const float*)d_in[9];
    const float* b_g1   = (const float*)d_in[10];
    const float* L1     = (const float*)d_in[11];
    const float* G2     = (const float*)d_in[12];
    const float* b_g2   = (const float*)d_in[13];
    const float* L2     = (const float*)d_in[14];
    const float* gamma  = (const float*)d_in[15];
    const float* beta   = (const float*)d_in[16];
    const float* W_att  = (const float*)d_in[17];
    const float* b_att  = (const float*)d_in[18];
    const float* A_att  = (const float*)d_in[19];
    float* out = (float*)d_out;

    float *pM, *pz, *px0a, *px0b, *pxm1, *pxm2, *phid2, *pseg1, *pseg2;
    cudaGetSymbolAddress((void**)&pM,    g_M);
    cudaGetSymbolAddress((void**)&pz,    g_z);
    cudaGetSymbolAddress((void**)&px0a,  g_x0a);
    cudaGetSymbolAddress((void**)&px0b,  g_x0b);
    cudaGetSymbolAddress((void**)&pxm1,  g_xm1);
    cudaGetSymbolAddress((void**)&pxm2,  g_xm2);
    cudaGetSymbolAddress((void**)&phid2, g_hid2);
    cudaGetSymbolAddress((void**)&pseg1, g_seg1);
    cudaGetSymbolAddress((void**)&pseg2, g_seg2);

    cudaFuncSetAttribute(mega_tf32, cudaFuncAttributeMaxDynamicSharedMemorySize, MEGA_SMEM);
    cudaFuncSetAttribute(ds_tf32<false>, cudaFuncAttributeMaxDynamicSharedMemorySize, DS_SMEM);
    cudaFuncSetAttribute(ds_tf32<true>,  cudaFuncAttributeMaxDynamicSharedMemorySize, DS_SMEM);

    // Side stream + fork/join events. Created lazily on the first (uncaptured
    // correctness) call; reused on the capture call so the fork/join become
    // graph edges. Work is identical on every call.
    static cudaStream_t s_att = nullptr;
    static cudaEvent_t ev_fork = nullptr, ev_join = nullptr;
    if (s_att == nullptr) {
        cudaStreamCreateWithFlags(&s_att, cudaStreamNonBlocking);
        cudaEventCreateWithFlags(&ev_fork, cudaEventDisableTiming);
        cudaEventCreateWithFlags(&ev_join, cudaEventDisableTiming);
    }

    const int rb128 = (NNODE + 127) / 128;  // 782

    k_zero<<<64, 256>>>();
    k_pre1<<<NHEADS*ATTD + NHEADS, 128>>>(W_att, b_att, A_att);
    k_mgemm<<<dim3(4, 4, 4), 256>>>(W_att);
    k_uvc<<<FIN + 1, 128>>>(W_att, b_att);

    mega_tf32<<<rb128, 256, MEGA_SMEM>>>(x, pM, W_f1, b_f1, W_f2, b_f2,
                                         W_l0, b_l0, pz, px0a, NNODE);

    // fork: edge attention runs concurrently with the DeepSet/BN chain
    cudaEventRecord(ev_fork, 0);
    cudaStreamWaitEvent(s_att, ev_fork, 0);
    k_att<<<(NEDGE*32 + 255)/256, 256, 0, s_att>>>(x, ei, out);
    cudaEventRecord(ev_join, s_att);

    k_seg<<<rb128, 256>>>(px0a, batch, pseg1, 1);
    k_mean1<<<NG, 64>>>(L1);
    ds_tf32<false><<<dim3(1, rb128), 256, DS_SMEM>>>(
        px0a, G1, OUTDIM, b_g1, pxm1, OUTDIM, batch, px0b, OUTDIM, NNODE);

    k_seg<<<rb128, 256>>>(px0b, batch, pseg2, 0);
    k_mean2<<<NG, 128>>>(L2);
    ds_tf32<true><<<dim3(2, rb128), 256, DS_SMEM>>>(
        px0b, G2, FIN, b_g2, pxm2, FIN, batch, phid2, FIN, NNODE);

    k_bnfin<<<1, 128>>>(gamma, beta);
    k_out<<<(NNODE*FIN/4 + 255)/256, 256>>>(x, out);

    // join: make the attention branch part of the graph's terminal frontier
    cudaStreamWaitEvent(0, ev_join, 0);
}

// round 11
// speedup vs baseline: 2.8022x; 1.1161x over previous
#include <cuda_runtime.h>
#include <cuda_fp16.h>
#include <stdint.h>
#include <stddef.h>
#include <math.h>

#define NNODE 100000
#define NEDGE 200000
#define NG 64
#define FIN 128
#define NFILT 8
#define HIDDIM 256
#define OUTDIM 64
#define ATTD 128
#define NHEADS 4

// ---------------- scratch ----------------
__device__ float g_T[NHEADS*ATTD*ATTD];
__device__ float g_r[NHEADS*ATTD];
__device__ float g_M[FIN*FIN];
__device__ float g_u[FIN];
__device__ float g_v[FIN];
__device__ float g_c[1];
__device__ float g_z[NNODE*FIN];
__device__ float g_p[NNODE];
__device__ float g_q[NNODE];
__device__ float g_x0a[NNODE*OUTDIM];
__device__ float g_x0b[NNODE*OUTDIM];
__device__ float g_hid2[NNODE*FIN];
__device__ float g_seg1[NG*OUTDIM];
__device__ float g_seg2[NG*OUTDIM];
__device__ float g_cnt[NG];
__device__ float g_xm1[NG*OUTDIM];
__device__ float g_xm2[NG*FIN];
__device__ float g_bn[2*FIN];
__device__ float g_bna[FIN];
__device__ float g_bnb[FIN];

__device__ __forceinline__ uint32_t f2h2(float lo, float hi) {
    __half2 h = __floats2half2_rn(lo, hi);
    return *(uint32_t*)&h;
}

// fp16 mma m16n8k16, fp32 accumulate. Fragment mantissa = 11 bits (same as tf32).
__device__ __forceinline__ void mma_f16(float c[4], const uint32_t a[4], const uint32_t b[2]) {
    asm volatile("mma.sync.aligned.m16n8k16.row.col.f32.f16.f16.f32 "
                 "{%0,%1,%2,%3}, {%4,%5,%6,%7}, {%8,%9}, {%0,%1,%2,%3};\n"
                 : "+f"(c[0]), "+f"(c[1]), "+f"(c[2]), "+f"(c[3])
                 : "r"(a[0]), "r"(a[1]), "r"(a[2]), "r"(a[3]), "r"(b[0]), "r"(b[1]));
}

// ---------------- zero accumulators ----------------
__global__ void k_zero() {
    int i = blockIdx.x * 256 + threadIdx.x;
    if (i < FIN*FIN)   g_M[i] = 0.f;
    if (i < NG*OUTDIM) { g_seg1[i] = 0.f; g_seg2[i] = 0.f; }
    if (i < NG)        g_cnt[i] = 0.f;
    if (i < 2*FIN)     g_bn[i] = 0.f;
}

// ---------------- attention precompute ----------------
__global__ void k_pre1(const float* __restrict__ W, const float* __restrict__ b,
                       const float* __restrict__ Aa) {
    __shared__ float w[ATTD];
    int bid = blockIdx.x, t = threadIdx.x;
    if (bid < NHEADS*ATTD) {
        int h = bid >> 7, i = bid & 127;
        w[t] = W[(h*ATTD + i)*ATTD + t];
        __syncthreads();
        const float* Ah = Aa + h*ATTD*ATTD;
        float s = 0.f;
        #pragma unroll 4
        for (int k = 0; k < ATTD; k++) s += w[k] * Ah[k*ATTD + t];
        g_T[(h*ATTD + i)*ATTD + t] = s;
    } else {
        int h = bid - NHEADS*ATTD;
        w[t] = b[h*ATTD + t];
        __syncthreads();
        const float* Ah = Aa + h*ATTD*ATTD;
        float s = 0.f;
        #pragma unroll 4
        for (int k = 0; k < ATTD; k++) s += w[k] * Ah[k*ATTD + t];
        g_r[h*ATTD + t] = s;
    }
}

// M += 0.25 * T_h @ W_h^T
__global__ void __launch_bounds__(256) k_mgemm(const float* __restrict__ W) {
    __shared__ float Tt[32][36], Ws[32][36];
    int it = blockIdx.x * 32, jt = blockIdx.y * 32, h = blockIdx.z;
    int t = threadIdx.x;
    int tx = t & 15, ty = t >> 4;
    float acc[2][2] = {};
    for (int kt = 0; kt < ATTD; kt += 32) {
        int r = t >> 3, k4 = (t & 7) << 2;
        *(float4*)&Tt[r][k4] = *(const float4*)(g_T + (size_t)(h*ATTD + it + r)*ATTD + kt + k4);
        *(float4*)&Ws[r][k4] = *(const float4*)(W   + (size_t)(h*ATTD + jt + r)*ATTD + kt + k4);
        __syncthreads();
        #pragma unroll 8
        for (int k = 0; k < 32; k++) {
            float a0 = Tt[ty*2][k], a1 = Tt[ty*2+1][k];
            float b0 = Ws[tx*2][k], b1 = Ws[tx*2+1][k];
            acc[0][0] = fmaf(a0, b0, acc[0][0]);
            acc[0][1] = fmaf(a0, b1, acc[0][1]);
            acc[1][0] = fmaf(a1, b0, acc[1][0]);
            acc[1][1] = fmaf(a1, b1, acc[1][1]);
        }
        __syncthreads();
    }
    #pragma unroll
    for (int i = 0; i < 2; i++)
        #pragma unroll
        for (int j = 0; j < 2; j++)
            atomicAdd(&g_M[(it + ty*2 + i)*FIN + jt + tx*2 + j], 0.25f * acc[i][j]);
}

// u, v, c
__global__ void k_uvc(const float* __restrict__ W, const float* __restrict__ b) {
    __shared__ float red[8];
    int j = blockIdx.x, k = threadIdx.x;
    int wid = k >> 5, l = k & 31;
    if (j < FIN) {
        float u = 0.f, v = 0.f;
        #pragma unroll
        for (int h = 0; h < NHEADS; h++) {
            u += g_T[(size_t)(h*ATTD + j)*ATTD + k] * b[h*ATTD + k];
            v += g_r[h*ATTD + k] * W[(size_t)(h*ATTD + j)*ATTD + k];
        }
        #pragma unroll
        for (int o = 16; o; o >>= 1) {
            u += __shfl_xor_sync(0xffffffffu, u, o);
            v += __shfl_xor_sync(0xffffffffu, v, o);
        }
        if (l == 0) { red[wid] = u; red[4 + wid] = v; }
        __syncthreads();
        if (k == 0) g_u[j] = 0.25f * (red[0] + red[1] + red[2] + red[3]);
        if (k == 1) g_v[j] = 0.25f * (red[4] + red[5] + red[6] + red[7]);
    } else {
        float c = 0.f;
        for (int i = k; i < NHEADS*ATTD; i += 128) c += g_r[i] * b[i];
        #pragma unroll
        for (int o = 16; o; o >>= 1) c += __shfl_xor_sync(0xffffffffu, c, o);
        if (l == 0) red[wid] = c;
        __syncthreads();
        if (k == 0) g_c[0] = 0.25f * (red[0] + red[1] + red[2] + red[3]);
    }
}

// ================= MEGA kernel — fp16 mma m16n8k16 =================
// As2: [128 rows][68 u32] (half2, k-pairs); Bs2: 2 buffers [64 n][68 u32] (half2 along k).
// Stride 68 => bank index 4*row + tg: conflict-free fragment loads.
#define AS2_STRIDE 68
#define SM_AS2 (128*AS2_STRIDE)
#define SM_BS2 (64*AS2_STRIDE)
#define OFF_FVS   (SM_AS2 + 2*SM_BS2)
#define OFF_UV    (OFF_FVS + 1024)
#define OFF_FOLD  (OFF_UV + 256)
#define OFF_WF2   (OFF_FOLD + 512)
#define OFF_BF1   (OFF_WF2 + 1024)
#define OFF_BF2   (OFF_BF1 + 128)
#define OFF_BL0   (OFF_BF2 + 8)
#define MEGA_SMEM ((OFF_BL0 + 64) * 4)

__global__ void __launch_bounds__(256) mega_f16(
    const float* __restrict__ x, const float* __restrict__ Mw,
    const float* __restrict__ Wf1, const float* __restrict__ bf1,
    const float* __restrict__ Wf2, const float* __restrict__ bf2,
    const float* __restrict__ Wl0, const float* __restrict__ bl0,
    float* __restrict__ z, float* __restrict__ x0a, int M) {
    extern __shared__ uint32_t smbuf[];
    uint32_t* As2 = smbuf;
    float* fvs  = (float*)(smbuf + OFF_FVS);
    float* uv   = (float*)(smbuf + OFF_UV);
    float* fold = (float*)(smbuf + OFF_FOLD);
    float* wf2s = (float*)(smbuf + OFF_WF2);
    float* bf1s = (float*)(smbuf + OFF_BF1);
    float* bf2s = (float*)(smbuf + OFF_BF2);
    float* bl0s = (float*)(smbuf + OFF_BL0);

    const int t = threadIdx.x;
    const int row0 = blockIdx.x * 128;

    for (int i = t; i < 128*8; i += 256) fvs[i] = 0.f;
    if (t < 128) { uv[t] = g_u[t]; uv[128 + t] = g_v[t]; }
    for (int i = t; i < 512; i += 256) {
        int j = i >> 6, o = i & 63;
        fold[i] = Wl0[(2*j)*OUTDIM + o] + Wl0[(2*j+1)*OUTDIM + o];
    }
    if (t < 64) bl0s[t] = bl0[t];
    if (t < 8)  bf2s[t] = bf2[t];
    __syncthreads();

    // As load (fp16 pack) + p/q warp reductions
    for (int i = t; i < 128*32; i += 256) {
        int r = i >> 5, k4 = (i & 31) << 2;
        float4 v = make_float4(0.f, 0.f, 0.f, 0.f);
        if (row0 + r < M) v = *(const float4*)(x + (size_t)(row0 + r)*FIN + k4);
        As2[r*AS2_STRIDE + (k4 >> 1)]     = f2h2(v.x, v.y);
        As2[r*AS2_STRIDE + (k4 >> 1) + 1] = f2h2(v.z, v.w);
        float pp = v.x*uv[k4] + v.y*uv[k4+1] + v.z*uv[k4+2] + v.w*uv[k4+3];
        float qq = v.x*uv[128+k4] + v.y*uv[128+k4+1] + v.z*uv[128+k4+2] + v.w*uv[128+k4+3];
        #pragma unroll
        for (int o = 16; o; o >>= 1) {
            pp += __shfl_xor_sync(0xffffffffu, pp, o);
            qq += __shfl_xor_sync(0xffffffffu, qq, o);
        }
        if ((i & 31) == 0 && row0 + r < M) { g_p[row0 + r] = pp; g_q[row0 + r] = qq; }
    }
    // B tile 0 (Mw cols 0..63) -> buffer 0, transposed to [n][kpair]
    #pragma unroll
    for (int it2 = 0; it2 < 4; it2++) {
        int i = t + it2*256;                 // 0..1023
        int kp = i >> 4, n4 = (i & 15) << 2;
        float4 r0 = *(const float4*)(Mw + (size_t)(2*kp)*FIN + n4);
        float4 r1 = *(const float4*)(Mw + (size_t)(2*kp + 1)*FIN + n4);
        uint32_t* base = smbuf + SM_AS2;
        base[(n4+0)*AS2_STRIDE + kp] = f2h2(r0.x, r1.x);
        base[(n4+1)*AS2_STRIDE + kp] = f2h2(r0.y, r1.y);
        base[(n4+2)*AS2_STRIDE + kp] = f2h2(r0.z, r1.z);
        base[(n4+3)*AS2_STRIDE + kp] = f2h2(r0.w, r1.w);
    }
    __syncthreads();

    const int wid = t >> 5, lane = t & 31;
    const int wm = (wid & 3) * 32, wn = (wid >> 2) * 32;
    const int g = lane >> 2, tg = lane & 3;

    float fvacc[4][NFILT] = {};
    float4 bpref[8];
    float4 wpref = make_float4(0.f, 0.f, 0.f, 0.f);
    float bf1pref = 0.f;

    #pragma unroll 1
    for (int tile = 0; tile < 6; tile++) {
        const int pb = tile & 1;
        const uint32_t* Bs2 = smbuf + SM_AS2 + pb*SM_BS2;

        if (tile < 5) {
            const int ncol0 = (tile + 1 < 2) ? (tile + 1)*64 : (tile - 1)*64;
            const float* nB = (tile + 1 < 2) ? Mw : Wf1;
            const int nldb = (tile + 1 < 2) ? FIN : HIDDIM;
            #pragma unroll
            for (int it2 = 0; it2 < 4; it2++) {
                int i = t + it2*256;
                int kp = i >> 4, n4 = (i & 15) << 2;
                bpref[it2*2]     = *(const float4*)(nB + (size_t)(2*kp)*nldb + ncol0 + n4);
                bpref[it2*2 + 1] = *(const float4*)(nB + (size_t)(2*kp + 1)*nldb + ncol0 + n4);
            }
            if (tile + 1 >= 2 && t < 128) {
                int r = t >> 1, half = t & 1;
                wpref = *(const float4*)(Wf2 + (size_t)(ncol0 + r)*NFILT + half*4);
                if (half == 0) bf1pref = bf1[ncol0 + r];
            }
        }

        // mma phase: 8 k16-steps
        float acc[2][4][4] = {};
        #pragma unroll
        for (int ko = 0; ko < 8; ko++) {
            int k0 = ko * 8;
            uint32_t a[2][4], b[4][2];
            #pragma unroll
            for (int mt = 0; mt < 2; mt++) {
                int r = wm + mt*16 + g;
                a[mt][0] = As2[r*AS2_STRIDE + k0 + tg];
                a[mt][1] = As2[(r + 8)*AS2_STRIDE + k0 + tg];
                a[mt][2] = As2[r*AS2_STRIDE + k0 + tg + 4];
                a[mt][3] = As2[(r + 8)*AS2_STRIDE + k0 + tg + 4];
            }
            #pragma unroll
            for (int nt = 0; nt < 4; nt++) {
                int n = wn + nt*8 + g;
                b[nt][0] = Bs2[n*AS2_STRIDE + k0 + tg];
                b[nt][1] = Bs2[n*AS2_STRIDE + k0 + tg + 4];
            }
            #pragma unroll
            for (int mt = 0; mt < 2; mt++)
                #pragma unroll
                for (int nt = 0; nt < 4; nt++)
                    mma_f16(acc[mt][nt], a[mt], b[nt]);
        }

        if (tile < 2) {
            const int col0 = tile*64;
            #pragma unroll
            for (int mt = 0; mt < 2; mt++) {
                int r = row0 + wm + mt*16 + g;
                #pragma unroll
                for (int nt = 0; nt < 4; nt++) {
                    int c = col0 + wn + nt*8 + 2*tg;
                    if (r < M)     *(float2*)(z + (size_t)r*FIN + c)     = make_float2(acc[mt][nt][0], acc[mt][nt][1]);
                    if (r + 8 < M) *(float2*)(z + (size_t)(r+8)*FIN + c) = make_float2(acc[mt][nt][2], acc[mt][nt][3]);
                }
            }
        } else {
            const float* wbuf = wf2s + pb*512;
            const float* bbuf = bf1s + pb*64;
            #pragma unroll
            for (int nt = 0; nt < 4; nt++) {
                int nA = wn + nt*8 + 2*tg, nB2 = nA + 1;
                float bA = bbuf[nA], bB = bbuf[nB2];
                const float* wA = wbuf + nA*NFILT;
                const float* wB = wbuf + nB2*NFILT;
                #pragma unroll
                for (int mt = 0; mt < 2; mt++) {
                    float v00 = fmaxf(acc[mt][nt][0] + bA, 0.f);
                    float v01 = fmaxf(acc[mt][nt][1] + bB, 0.f);
                    float v10 = fmaxf(acc[mt][nt][2] + bA, 0.f);
                    float v11 = fmaxf(acc[mt][nt][3] + bB, 0.f);
                    #pragma unroll
                    for (int j = 0; j < NFILT; j++) {
                        fvacc[mt*2+0][j] += v00*wA[j] + v01*wB[j];
                        fvacc[mt*2+1][j] += v10*wA[j] + v11*wB[j];
                    }
                }
            }
        }

        if (tile < 5) {
            uint32_t* base = smbuf + SM_AS2 + (pb^1)*SM_BS2;
            #pragma unroll
            for (int it2 = 0; it2 < 4; it2++) {
                int i = t + it2*256;
                int kp = i >> 4, n4 = (i & 15) << 2;
                float4 r0 = bpref[it2*2], r1 = bpref[it2*2 + 1];
                base[(n4+0)*AS2_STRIDE + kp] = f2h2(r0.x, r1.x);
                base[(n4+1)*AS2_STRIDE + kp] = f2h2(r0.y, r1.y);
                base[(n4+2)*AS2_STRIDE + kp] = f2h2(r0.z, r1.z);
                base[(n4+3)*AS2_STRIDE + kp] = f2h2(r0.w, r1.w);
            }
            if (tile + 1 >= 2 && t < 128) {
                int r = t >> 1, half = t & 1;
                *(float4*)(wf2s + (pb^1)*512 + r*8 + half*4) = wpref;
                if (half == 0) bf1s[(pb^1)*64 + r] = bf1pref;
            }
        }
        __syncthreads();
    }

    #pragma unroll
    for (int ridx = 0; ridx < 4; ridx++)
        #pragma unroll
        for (int j = 0; j < NFILT; j++) {
            float s = fvacc[ridx][j];
            s += __shfl_xor_sync(0xffffffffu, s, 1);
            s += __shfl_xor_sync(0xffffffffu, s, 2);
            fvacc[ridx][j] = s;
        }
    if (tg == 0) {
        #pragma unroll
        for (int ridx = 0; ridx < 4; ridx++) {
            int rl = wm + (ridx >> 1)*16 + (ridx & 1)*8 + g;
            #pragma unroll
            for (int j = 0; j < NFILT; j++)
                atomicAdd(&fvs[rl*NFILT + j], fvacc[ridx][j]);
        }
    }
    __syncthreads();

    for (int i = t; i < 128*64; i += 256) {
        int r = i >> 6, o = i & 63;
        if (row0 + r >= M) continue;
        float s = bl0s[o];
        #pragma unroll
        for (int j = 0; j < NFILT; j++)
            s = fmaf(fvs[r*NFILT + j] + bf2s[j], fold[j*64 + o], s);
        x0a[(size_t)(row0 + r)*OUTDIM + o] = fmaxf(s, 0.f);
    }
}

// ================= DeepSet fp16 GEMM (K=64) =================
#define DS_STRIDE 36
#define DS_SMEM ((128*DS_STRIDE + 64*DS_STRIDE + 128) * 4)

template<bool BNACC>
__global__ void __launch_bounds__(256) ds_f16(
    const float* __restrict__ A,
    const float* __restrict__ B, int ldb,
    const float* __restrict__ bias,
    const float* __restrict__ sub, int ldsub,
    const int* __restrict__ batch,
    float* __restrict__ C, int ldc, int M) {
    extern __shared__ uint32_t smbuf[];
    uint32_t* As2 = smbuf;                       // [128][36]
    uint32_t* Bs2 = smbuf + 128*DS_STRIDE;       // [64][36]
    float* bnsm = (float*)(smbuf + 128*DS_STRIDE + 64*DS_STRIDE);
    const int t = threadIdx.x;
    const int row0 = blockIdx.y * 128, col0 = blockIdx.x * 64;

    for (int i = t; i < 128*16; i += 256) {
        int r = i >> 4, k4 = (i & 15) << 2;
        float4 v = make_float4(0.f, 0.f, 0.f, 0.f);
        if (row0 + r < M) v = *(const float4*)(A + (size_t)(row0 + r)*OUTDIM + k4);
        As2[r*DS_STRIDE + (k4 >> 1)]     = f2h2(v.x, v.y);
        As2[r*DS_STRIDE + (k4 >> 1) + 1] = f2h2(v.z, v.w);
    }
    // B transpose: 32 kpairs x 64 n
    for (int i = t; i < 512; i += 256) {
        int kp = i >> 4, n4 = (i & 15) << 2;
        float4 r0 = *(const float4*)(B + (size_t)(2*kp)*ldb + col0 + n4);
        float4 r1 = *(const float4*)(B + (size_t)(2*kp + 1)*ldb + col0 + n4);
        Bs2[(n4+0)*DS_STRIDE + kp] = f2h2(r0.x, r1.x);
        Bs2[(n4+1)*DS_STRIDE + kp] = f2h2(r0.y, r1.y);
        Bs2[(n4+2)*DS_STRIDE + kp] = f2h2(r0.z, r1.z);
        Bs2[(n4+3)*DS_STRIDE + kp] = f2h2(r0.w, r1.w);
    }
    if (BNACC && t < 128) bnsm[t] = 0.f;
    __syncthreads();

    const int wid = t >> 5, lane = t & 31;
    const int wm = (wid & 3) * 32, wn = (wid >> 2) * 32;
    const int g = lane >> 2, tg = lane & 3;

    float acc[2][4][4] = {};
    #pragma unroll
    for (int ko = 0; ko < 4; ko++) {
        int k0 = ko * 8;
        uint32_t a[2][4], b[4][2];
        #pragma unroll
        for (int mt = 0; mt < 2; mt++) {
            int r = wm + mt*16 + g;
            a[mt][0] = As2[r*DS_STRIDE + k0 + tg];
            a[mt][1] = As2[(r + 8)*DS_STRIDE + k0 + tg];
            a[mt][2] = As2[r*DS_STRIDE + k0 + tg + 4];
            a[mt][3] = As2[(r + 8)*DS_STRIDE + k0 + tg + 4];
        }
        #pragma unroll
        for (int nt = 0; nt < 4; nt++) {
            int n = wn + nt*8 + g;
            b[nt][0] = Bs2[n*DS_STRIDE + k0 + tg];
            b[nt][1] = Bs2[n*DS_STRIDE + k0 + tg + 4];
        }
        #pragma unroll
        for (int mt = 0; mt < 2; mt++)
            #pragma unroll
            for (int nt = 0; nt < 4; nt++)
                mma_f16(acc[mt][nt], a[mt], b[nt]);
    }

    float s1[4][2] = {}, s2[4][2] = {};
    #pragma unroll
    for (int mt = 0; mt < 2; mt++) {
        int r0g = row0 + wm + mt*16 + g;
        int r1g = r0g + 8;
        bool ok0 = r0g < M, ok1 = r1g < M;
        int b0 = ok0 ? batch[r0g] : 0;
        int b1 = ok1 ? batch[r1g] : 0;
        const float* sub0 = sub + (size_t)b0*ldsub;
        const float* sub1 = sub + (size_t)b1*ldsub;
        #pragma unroll
        for (int nt = 0; nt < 4; nt++) {
            int cA = col0 + wn + nt*8 + 2*tg, cB = cA + 1;
            float biA = bias[cA], biB = bias[cB];
            float v00 = fmaxf(acc[mt][nt][0] + biA - sub0[cA], 0.f);
            float v01 = fmaxf(acc[mt][nt][1] + biB - sub0[cB], 0.f);
            float v10 = fmaxf(acc[mt][nt][2] + biA - sub1[cA], 0.f);
            float v11 = fmaxf(acc[mt][nt][3] + biB - sub1[cB], 0.f);
            if (ok0) *(float2*)(C + (size_t)r0g*ldc + cA) = make_float2(v00, v01);
            if (ok1) *(float2*)(C + (size_t)r1g*ldc + cA) = make_float2(v10, v11);
            if (BNACC) {
                s1[nt][0] += (ok0 ? v00 : 0.f) + (ok1 ? v10 : 0.f);
                s1[nt][1] += (ok0 ? v01 : 0.f) + (ok1 ? v11 : 0.f);
                s2[nt][0] += (ok0 ? v00*v00 : 0.f) + (ok1 ? v10*v10 : 0.f);
                s2[nt][1] += (ok0 ? v01*v01 : 0.f) + (ok1 ? v11*v11 : 0.f);
            }
        }
    }
    if (BNACC) {
        #pragma unroll
        for (int nt = 0; nt < 4; nt++)
            #pragma unroll
            for (int h = 0; h < 2; h++) {
                float a = s1[nt][h], b = s2[nt][h];
                #pragma unroll
                for (int o = 4; o < 32; o <<= 1) {
                    a += __shfl_xor_sync(0xffffffffu, a, o);
                    b += __shfl_xor_sync(0xffffffffu, b, o);
                }
                if (g == 0) {
                    int cl = wn + nt*8 + 2*tg + h;
                    atomicAdd(&bnsm[2*cl], a);
                    atomicAdd(&bnsm[2*cl + 1], b);
                }
            }
        __syncthreads();
        if (t < 64) {
            atomicAdd(&g_bn[col0 + t], bnsm[2*t]);
            atomicAdd(&g_bn[FIN + col0 + t], bnsm[2*t + 1]);
        }
    }
}

// ---------------- edge attention ----------------
__global__ void k_att(const float* __restrict__ x, const int* __restrict__ ei,
                      float* __restrict__ out) {
    int wid = (blockIdx.x * blockDim.x + threadIdx.x) >> 5;
    int l = threadIdx.x & 31;
    if (wid >= NEDGE) return;
    int row = ei[wid], col = ei[NEDGE + wid];
    float4 zv = *(const float4*)(g_z + (size_t)row*FIN + l*4);
    float4 xv = *(const float4*)(x   + (size_t)col*FIN + l*4);
    float d = zv.x*xv.x + zv.y*xv.y + zv.z*xv.z + zv.w*xv.w;
    #pragma unroll
    for (int o = 16; o; o >>= 1) d += __shfl_xor_sync(0xffffffffu, d, o);
    if (l == 0) {
        float s = d + g_p[row] + g_q[col] + g_c[0];
        out[(size_t)NNODE*FIN + wid] = 1.f / (1.f + expf(-s));
    }
}

// ---------------- segment sum over sorted batch ----------------
__global__ void k_seg(const float* __restrict__ v, const int* __restrict__ batch,
                      float* __restrict__ sum, int do_cnt) {
    int t = threadIdx.x;
    int f = t & 63, w = t >> 6;
    int r0 = blockIdx.x * 128;
    int rend = min(r0 + 128, NNODE);
    float acc = 0.f, ccnt = 0.f;
    int cur = -1;
    for (int rb = r0 + w; rb < rend; rb += 16) {
        float vv[4]; int gg[4];
        #pragma unroll
        for (int j = 0; j < 4; j++) {
            int r = rb + j*4;
            bool ok = r < rend;
            vv[j] = ok ? v[(size_t)r*64 + f] : 0.f;
            gg[j] = ok ? __ldg(&batch[r]) : -2;
        }
        #pragma unroll
        for (int j = 0; j < 4; j++) {
            if (gg[j] != cur) {
                if (cur >= 0) {
                    atomicAdd(&sum[cur*64 + f], acc);
                    if (do_cnt && f == 0) atomicAdd(&g_cnt[cur], ccnt);
                }
                acc = 0.f; ccnt = 0.f; cur = gg[j];
            }
            if (gg[j] >= 0) { acc += vv[j]; ccnt += 1.f; }
        }
    }
    if (cur >= 0) {
        atomicAdd(&sum[cur*64 + f], acc);
        if (do_cnt && f == 0) atomicAdd(&g_cnt[cur], ccnt);
    }
}

__global__ void k_mean1(const float* __restrict__ L1) {
    __shared__ float mean[OUTDIM];
    int g = blockIdx.x, t = threadIdx.x;
    float c = fmaxf(g_cnt[g], 1.f);
    mean[t] = g_seg1[g*64 + t] / c;
    __syncthreads();
    float s = 0.f;
    #pragma unroll 4
    for (int k = 0; k < 64; k++) s += mean[k] * L1[k*64 + t];
    g_xm1[g*64 + t] = s;
}

__global__ void k_mean2(const float* __restrict__ L2) {
    __shared__ float mean[OUTDIM];
    int g = blockIdx.x, t = threadIdx.x;
    if (t < 64) mean[t] = g_seg2[g*64 + t] / fmaxf(g_cnt[g], 1.f);
    __syncthreads();
    float s = 0.f;
    #pragma unroll 4
    for (int k = 0; k < 64; k++) s += mean[k] * L2[k*128 + t];
    g_xm2[g*128 + t] = s;
}

__global__ void k_bnfin(const float* __restrict__ gamma, const float* __restrict__ beta) {
    int f = threadIdx.x;
    float mu = g_bn[f] / (float)NNODE;
    float var = g_bn[128 + f] / (float)NNODE - mu*mu;
    float a = gamma[f] * rsqrtf(var + 1e-5f);
    g_bna[f] = a;
    g_bnb[f] = beta[f] - mu*a;
}

__global__ void k_out(const float* __restrict__ x, float* __restrict__ out) {
    int i = blockIdx.x * blockDim.x + threadIdx.x;
    if (i >= NNODE*FIN/4) return;
    int f4 = (i & 31) * 4;
    float4 xv = ((const float4*)x)[i];
    float4 hv = ((const float4*)g_hid2)[i];
    float4 a  = *(const float4*)(g_bna + f4);
    float4 b  = *(const float4*)(g_bnb + f4);
    float4 o;
    o.x = xv.x + hv.x*a.x + b.x;
    o.y = xv.y + hv.y*a.y + b.y;
    o.z = xv.z + hv.z*a.z + b.z;
    o.w = xv.w + hv.w*a.w + b.w;
    ((float4*)out)[i] = o;
}

// ---------------- host launch ----------------
extern "C" void kernel_launch(void* const* d_in, const int* in_sizes, int n_in,
                              void* d_out, int out_size) {
    const float* x      = (const float*)d_in[0];
    const int*   ei     = (const int*)  d_in[1];
    const int*   batch  = (const int*)  d_in[2];
    const float* W_f1   = (const float*)d_in[3];
    const float* b_f1   = (const float*)d_in[4];
    const float* W_f2   = (const float*)d_in[5];
    const float* b_f2   = (const float*)d_in[6];
    const float* W_l0   = (const float*)d_in[7];
    const float* b_l0   = (const float*)d_in[8];
    const float* G1     = (const float*)d_in[9];
    const float* b_g1   = (const float*)d_in[10];
    const float* L1     = (const float*)d_in[11];
    const float* G2     = (const float*)d_in[12];
    const float* b_g2   = (const float*)d_in[13];
    const float* L2     = (const float*)d_in[14];
    const float* gamma  = (const float*)d_in[15];
    const float* beta   = (const float*)d_in[16];
    const float* W_att  = (const float*)d_in[17];
    const float* b_att  = (const float*)d_in[18];
    const float* A_att  = (const float*)d_in[19];
    float* out = (float*)d_out;

    float *pM, *pz, *px0a, *px0b, *pxm1, *pxm2, *phid2, *pseg1, *pseg2;
    cudaGetSymbolAddress((void**)&pM,    g_M);
    cudaGetSymbolAddress((void**)&pz,    g_z);
    cudaGetSymbolAddress((void**)&px0a,  g_x0a);
    cudaGetSymbolAddress((void**)&px0b,  g_x0b);
    cudaGetSymbolAddress((void**)&pxm1,  g_xm1);
    cudaGetSymbolAddress((void**)&pxm2,  g_xm2);
    cudaGetSymbolAddress((void**)&phid2, g_hid2);
    cudaGetSymbolAddress((void**)&pseg1, g_seg1);
    cudaGetSymbolAddress((void**)&pseg2, g_seg2);

    cudaFuncSetAttribute(mega_f16, cudaFuncAttributeMaxDynamicSharedMemorySize, MEGA_SMEM);
    cudaFuncSetAttribute(ds_f16<false>, cudaFuncAttributeMaxDynamicSharedMemorySize, DS_SMEM);
    cudaFuncSetAttribute(ds_f16<true>,  cudaFuncAttributeMaxDynamicSharedMemorySize, DS_SMEM);

    static cudaStream_t s_att = nullptr;
    static cudaEvent_t ev_fork = nullptr, ev_join = nullptr;
    if (s_att == nullptr) {
        cudaStreamCreateWithFlags(&s_att, cudaStreamNonBlocking);
        cudaEventCreateWithFlags(&ev_fork, cudaEventDisableTiming);
        cudaEventCreateWithFlags(&ev_join, cudaEventDisableTiming);
    }

    const int rb128 = (NNODE + 127) / 128;  // 782

    k_zero<<<64, 256>>>();
    k_pre1<<<NHEADS*ATTD + NHEADS, 128>>>(W_att, b_att, A_att);
    k_mgemm<<<dim3(4, 4, 4), 256>>>(W_att);
    k_uvc<<<FIN + 1, 128>>>(W_att, b_att);

    mega_f16<<<rb128, 256, MEGA_SMEM>>>(x, pM, W_f1, b_f1, W_f2, b_f2,
                                        W_l0, b_l0, pz, px0a, NNODE);

    cudaEventRecord(ev_fork, 0);
    cudaStreamWaitEvent(s_att, ev_fork, 0);
    k_att<<<(NEDGE*32 + 255)/256, 256, 0, s_att>>>(x, ei, out);
    cudaEventRecord(ev_join, s_att);

    k_seg<<<rb128, 256>>>(px0a, batch, pseg1, 1);
    k_mean1<<<NG, 64>>>(L1);
    ds_f16<false><<<dim3(1, rb128), 256, DS_SMEM>>>(
        px0a, G1, OUTDIM, b_g1, pxm1, OUTDIM, batch, px0b, OUTDIM, NNODE);

    k_seg<<<rb128, 256>>>(px0b, batch, pseg2, 0);
    k_mean2<<<NG, 128>>>(L2);
    ds_f16<true><<<dim3(2, rb128), 256, DS_SMEM>>>(
        px0b, G2, FIN, b_g2, pxm2, FIN, batch, phid2, FIN, NNODE);

    k_bnfin<<<1, 128>>>(gamma, beta);
    k_out<<<(NNODE*FIN/4 + 255)/256, 256>>>(x, out);

    cudaStreamWaitEvent(0, ev_join, 0);
}

// round 16
// speedup vs baseline: 2.8232x; 1.0075x over previous
#include <cuda_runtime.h>
#include <cuda_fp16.h>
#include <stdint.h>
#include <stddef.h>
#include <math.h>

#define NNODE 100000
#define NEDGE 200000
#define NG 64
#define FIN 128
#define NFILT 8
#define HIDDIM 256
#define OUTDIM 64
#define ATTD 128
#define NHEADS 4

// ---------------- scratch ----------------
__device__ float g_T[NHEADS*ATTD*ATTD];
__device__ float g_r[NHEADS*ATTD];
__device__ float g_M[FIN*FIN];
__device__ float g_u[FIN];
__device__ float g_v[FIN];
__device__ float g_c[1];
__device__ uint32_t g_zh[NNODE*64];   // z = x@M as half2 (k_att operand)
__device__ uint32_t g_xh[NNODE*64];   // x as half2 (k_att operand)
__device__ float g_p[NNODE];
__device__ float g_q[NNODE];
__device__ float g_x0a[NNODE*OUTDIM];
__device__ float g_x0b[NNODE*OUTDIM];
__device__ float g_hid2[NNODE*FIN];
__device__ float g_seg1[NG*OUTDIM];
__device__ float g_seg2[NG*OUTDIM];
__device__ float g_cnt[NG];
__device__ float g_xm1[NG*OUTDIM];
__device__ float g_xm2[NG*FIN];
__device__ float g_bn[2*FIN];
__device__ float g_bna[FIN];
__device__ float g_bnb[FIN];

__device__ __forceinline__ uint32_t f2h2(float lo, float hi) {
    __half2 h = __floats2half2_rn(lo, hi);
    return *(uint32_t*)&h;
}

// fp16 mma m16n8k16, fp32 accumulate (11-bit mantissa inputs, same as tf32).
__device__ __forceinline__ void mma_f16(float c[4], const uint32_t a[4], const uint32_t b[2]) {
    asm volatile("mma.sync.aligned.m16n8k16.row.col.f32.f16.f16.f32 "
                 "{%0,%1,%2,%3}, {%4,%5,%6,%7}, {%8,%9}, {%0,%1,%2,%3};\n"
                 : "+f"(c[0]), "+f"(c[1]), "+f"(c[2]), "+f"(c[3])
                 : "r"(a[0]), "r"(a[1]), "r"(a[2]), "r"(a[3]), "r"(b[0]), "r"(b[1]));
}

// ---------------- zero accumulators ----------------
__global__ void k_zero() {
    int i = blockIdx.x * 256 + threadIdx.x;
    if (i < FIN*FIN)   g_M[i] = 0.f;
    if (i < NG*OUTDIM) { g_seg1[i] = 0.f; g_seg2[i] = 0.f; }
    if (i < NG)        g_cnt[i] = 0.f;
    if (i < 2*FIN)     g_bn[i] = 0.f;
}

// ---------------- attention precompute ----------------
__global__ void k_pre1(const float* __restrict__ W, const float* __restrict__ b,
                       const float* __restrict__ Aa) {
    __shared__ float w[ATTD];
    int bid = blockIdx.x, t = threadIdx.x;
    if (bid < NHEADS*ATTD) {
        int h = bid >> 7, i = bid & 127;
        w[t] = W[(h*ATTD + i)*ATTD + t];
        __syncthreads();
        const float* Ah = Aa + h*ATTD*ATTD;
        float s = 0.f;
        #pragma unroll 4
        for (int k = 0; k < ATTD; k++) s += w[k] * Ah[k*ATTD + t];
        g_T[(h*ATTD + i)*ATTD + t] = s;
    } else {
        int h = bid - NHEADS*ATTD;
        w[t] = b[h*ATTD + t];
        __syncthreads();
        const float* Ah = Aa + h*ATTD*ATTD;
        float s = 0.f;
        #pragma unroll 4
        for (int k = 0; k < ATTD; k++) s += w[k] * Ah[k*ATTD + t];
        g_r[h*ATTD + t] = s;
    }
}

// M += 0.25 * T_h @ W_h^T
__global__ void __launch_bounds__(256) k_mgemm(const float* __restrict__ W) {
    __shared__ float Tt[32][36], Ws[32][36];
    int it = blockIdx.x * 32, jt = blockIdx.y * 32, h = blockIdx.z;
    int t = threadIdx.x;
    int tx = t & 15, ty = t >> 4;
    float acc[2][2] = {};
    for (int kt = 0; kt < ATTD; kt += 32) {
        int r = t >> 3, k4 = (t & 7) << 2;
        *(float4*)&Tt[r][k4] = *(const float4*)(g_T + (size_t)(h*ATTD + it + r)*ATTD + kt + k4);
        *(float4*)&Ws[r][k4] = *(const float4*)(W   + (size_t)(h*ATTD + jt + r)*ATTD + kt + k4);
        __syncthreads();
        #pragma unroll 8
        for (int k = 0; k < 32; k++) {
            float a0 = Tt[ty*2][k], a1 = Tt[ty*2+1][k];
            float b0 = Ws[tx*2][k], b1 = Ws[tx*2+1][k];
            acc[0][0] = fmaf(a0, b0, acc[0][0]);
            acc[0][1] = fmaf(a0, b1, acc[0][1]);
            acc[1][0] = fmaf(a1, b0, acc[1][0]);
            acc[1][1] = fmaf(a1, b1, acc[1][1]);
        }
        __syncthreads();
    }
    #pragma unroll
    for (int i = 0; i < 2; i++)
        #pragma unroll
        for (int j = 0; j < 2; j++)
            atomicAdd(&g_M[(it + ty*2 + i)*FIN + jt + tx*2 + j], 0.25f * acc[i][j]);
}

// u, v, c
__global__ void k_uvc(const float* __restrict__ W, const float* __restrict__ b) {
    __shared__ float red[8];
    int j = blockIdx.x, k = threadIdx.x;
    int wid = k >> 5, l = k & 31;
    if (j < FIN) {
        float u = 0.f, v = 0.f;
        #pragma unroll
        for (int h = 0; h < NHEADS; h++) {
            u += g_T[(size_t)(h*ATTD + j)*ATTD + k] * b[h*ATTD + k];
            v += g_r[h*ATTD + k] * W[(size_t)(h*ATTD + j)*ATTD + k];
        }
        #pragma unroll
        for (int o = 16; o; o >>= 1) {
            u += __shfl_xor_sync(0xffffffffu, u, o);
            v += __shfl_xor_sync(0xffffffffu, v, o);
        }
        if (l == 0) { red[wid] = u; red[4 + wid] = v; }
        __syncthreads();
        if (k == 0) g_u[j] = 0.25f * (red[0] + red[1] + red[2] + red[3]);
        if (k == 1) g_v[j] = 0.25f * (red[4] + red[5] + red[6] + red[7]);
    } else {
        float c = 0.f;
        for (int i = k; i < NHEADS*ATTD; i += 128) c += g_r[i] * b[i];
        #pragma unroll
        for (int o = 16; o; o >>= 1) c += __shfl_xor_sync(0xffffffffu, c, o);
        if (l == 0) red[wid] = c;
        __syncthreads();
        if (k == 0) g_c[0] = 0.25f * (red[0] + red[1] + red[2] + red[3]);
    }
}

// ================= MEGA kernel — fp16 mma m16n8k16 =================
#define AS2_STRIDE 68
#define SM_AS2 (128*AS2_STRIDE)
#define SM_BS2 (64*AS2_STRIDE)
#define OFF_FVS   (SM_AS2 + 2*SM_BS2)
#define OFF_UV    (OFF_FVS + 1024)
#define OFF_FOLD  (OFF_UV + 256)
#define OFF_WF2   (OFF_FOLD + 512)
#define OFF_BF1   (OFF_WF2 + 1024)
#define OFF_BF2   (OFF_BF1 + 128)
#define OFF_BL0   (OFF_BF2 + 8)
#define MEGA_SMEM ((OFF_BL0 + 64) * 4)

__global__ void __launch_bounds__(256) mega_f16(
    const float* __restrict__ x, const float* __restrict__ Mw,
    const float* __restrict__ Wf1, const float* __restrict__ bf1,
    const float* __restrict__ Wf2, const float* __restrict__ bf2,
    const float* __restrict__ Wl0, const float* __restrict__ bl0,
    float* __restrict__ x0a, int M) {
    extern __shared__ uint32_t smbuf[];
    uint32_t* As2 = smbuf;
    float* fvs  = (float*)(smbuf + OFF_FVS);
    float* uv   = (float*)(smbuf + OFF_UV);
    float* fold = (float*)(smbuf + OFF_FOLD);
    float* wf2s = (float*)(smbuf + OFF_WF2);
    float* bf1s = (float*)(smbuf + OFF_BF1);
    float* bf2s = (float*)(smbuf + OFF_BF2);
    float* bl0s = (float*)(smbuf + OFF_BL0);

    const int t = threadIdx.x;
    const int row0 = blockIdx.x * 128;

    for (int i = t; i < 128*8; i += 256) fvs[i] = 0.f;
    if (t < 128) { uv[t] = g_u[t]; uv[128 + t] = g_v[t]; }
    for (int i = t; i < 512; i += 256) {
        int j = i >> 6, o = i & 63;
        fold[i] = Wl0[(2*j)*OUTDIM + o] + Wl0[(2*j+1)*OUTDIM + o];
    }
    if (t < 64) bl0s[t] = bl0[t];
    if (t < 8)  bf2s[t] = bf2[t];
    __syncthreads();

    // As load (fp16 pack) + fp16 shadow of x + p/q warp reductions
    for (int i = t; i < 128*32; i += 256) {
        int r = i >> 5, k4 = (i & 31) << 2;
        float4 v = make_float4(0.f, 0.f, 0.f, 0.f);
        bool ok = row0 + r < M;
        if (ok) v = *(const float4*)(x + (size_t)(row0 + r)*FIN + k4);
        uint32_t h0 = f2h2(v.x, v.y), h1 = f2h2(v.z, v.w);
        As2[r*AS2_STRIDE + (k4 >> 1)]     = h0;
        As2[r*AS2_STRIDE + (k4 >> 1) + 1] = h1;
        if (ok) *(uint2*)(g_xh + (size_t)(row0 + r)*64 + (k4 >> 1)) = make_uint2(h0, h1);
        float pp = v.x*uv[k4] + v.y*uv[k4+1] + v.z*uv[k4+2] + v.w*uv[k4+3];
        float qq = v.x*uv[128+k4] + v.y*uv[128+k4+1] + v.z*uv[128+k4+2] + v.w*uv[128+k4+3];
        #pragma unroll
        for (int o = 16; o; o >>= 1) {
            pp += __shfl_xor_sync(0xffffffffu, pp, o);
            qq += __shfl_xor_sync(0xffffffffu, qq, o);
        }
        if ((i & 31) == 0 && ok) { g_p[row0 + r] = pp; g_q[row0 + r] = qq; }
    }
    // B tile 0 (Mw cols 0..63) -> buffer 0, transposed to [n][kpair]
    #pragma unroll
    for (int it2 = 0; it2 < 4; it2++) {
        int i = t + it2*256;
        int kp = i >> 4, n4 = (i & 15) << 2;
        float4 r0 = *(const float4*)(Mw + (size_t)(2*kp)*FIN + n4);
        float4 r1 = *(const float4*)(Mw + (size_t)(2*kp + 1)*FIN + n4);
        uint32_t* base = smbuf + SM_AS2;
        base[(n4+0)*AS2_STRIDE + kp] = f2h2(r0.x, r1.x);
        base[(n4+1)*AS2_STRIDE + kp] = f2h2(r0.y, r1.y);
        base[(n4+2)*AS2_STRIDE + kp] = f2h2(r0.z, r1.z);
        base[(n4+3)*AS2_STRIDE + kp] = f2h2(r0.w, r1.w);
    }
    __syncthreads();

    const int wid = t >> 5, lane = t & 31;
    const int wm = (wid & 3) * 32, wn = (wid >> 2) * 32;
    const int g = lane >> 2, tg = lane & 3;

    float fvacc[4][NFILT] = {};
    float4 bpref[8];
    float4 wpref = make_float4(0.f, 0.f, 0.f, 0.f);
    float bf1pref = 0.f;

    #pragma unroll 1
    for (int tile = 0; tile < 6; tile++) {
        const int pb = tile & 1;
        const uint32_t* Bs2 = smbuf + SM_AS2 + pb*SM_BS2;

        if (tile < 5) {
            const int ncol0 = (tile + 1 < 2) ? (tile + 1)*64 : (tile - 1)*64;
            const float* nB = (tile + 1 < 2) ? Mw : Wf1;
            const int nldb = (tile + 1 < 2) ? FIN : HIDDIM;
            #pragma unroll
            for (int it2 = 0; it2 < 4; it2++) {
                int i = t + it2*256;
                int kp = i >> 4, n4 = (i & 15) << 2;
                bpref[it2*2]     = *(const float4*)(nB + (size_t)(2*kp)*nldb + ncol0 + n4);
                bpref[it2*2 + 1] = *(const float4*)(nB + (size_t)(2*kp + 1)*nldb + ncol0 + n4);
            }
            if (tile + 1 >= 2 && t < 128) {
                int r = t >> 1, half = t & 1;
                wpref = *(const float4*)(Wf2 + (size_t)(ncol0 + r)*NFILT + half*4);
                if (half == 0) bf1pref = bf1[ncol0 + r];
            }
        }

        float acc[2][4][4] = {};
        #pragma unroll
        for (int ko = 0; ko < 8; ko++) {
            int k0 = ko * 8;
            uint32_t a[2][4], b[4][2];
            #pragma unroll
            for (int mt = 0; mt < 2; mt++) {
                int r = wm + mt*16 + g;
                a[mt][0] = As2[r*AS2_STRIDE + k0 + tg];
                a[mt][1] = As2[(r + 8)*AS2_STRIDE + k0 + tg];
                a[mt][2] = As2[r*AS2_STRIDE + k0 + tg + 4];
                a[mt][3] = As2[(r + 8)*AS2_STRIDE + k0 + tg + 4];
            }
            #pragma unroll
            for (int nt = 0; nt < 4; nt++) {
                int n = wn + nt*8 + g;
                b[nt][0] = Bs2[n*AS2_STRIDE + k0 + tg];
                b[nt][1] = Bs2[n*AS2_STRIDE + k0 + tg + 4];
            }
            #pragma unroll
            for (int mt = 0; mt < 2; mt++)
                #pragma unroll
                for (int nt = 0; nt < 4; nt++)
                    mma_f16(acc[mt][nt], a[mt], b[nt]);
        }

        if (tile < 2) {
            const int col0 = tile*64;
            #pragma unroll
            for (int mt = 0; mt < 2; mt++) {
                int r = row0 + wm + mt*16 + g;
                #pragma unroll
                for (int nt = 0; nt < 4; nt++) {
                    int c = col0 + wn + nt*8 + 2*tg;
                    if (r < M)     g_zh[(size_t)r*64 + (c >> 1)]     = f2h2(acc[mt][nt][0], acc[mt][nt][1]);
                    if (r + 8 < M) g_zh[(size_t)(r+8)*64 + (c >> 1)] = f2h2(acc[mt][nt][2], acc[mt][nt][3]);
                }
            }
        } else {
            const float* wbuf = wf2s + pb*512;
            const float* bbuf = bf1s + pb*64;
            #pragma unroll
            for (int nt = 0; nt < 4; nt++) {
                int nA = wn + nt*8 + 2*tg, nB2 = nA + 1;
                float bA = bbuf[nA], bB = bbuf[nB2];
                const float* wA = wbuf + nA*NFILT;
                const float* wB = wbuf + nB2*NFILT;
                #pragma unroll
                for (int mt = 0; mt < 2; mt++) {
                    float v00 = fmaxf(acc[mt][nt][0] + bA, 0.f);
                    float v01 = fmaxf(acc[mt][nt][1] + bB, 0.f);
                    float v10 = fmaxf(acc[mt][nt][2] + bA, 0.f);
                    float v11 = fmaxf(acc[mt][nt][3] + bB, 0.f);
                    #pragma unroll
                    for (int j = 0; j < NFILT; j++) {
                        fvacc[mt*2+0][j] += v00*wA[j] + v01*wB[j];
                        fvacc[mt*2+1][j] += v10*wA[j] + v11*wB[j];
                    }
                }
            }
        }

        if (tile < 5) {
            uint32_t* base = smbuf + SM_AS2 + (pb^1)*SM_BS2;
            #pragma unroll
            for (int it2 = 0; it2 < 4; it2++) {
                int i = t + it2*256;
                int kp = i >> 4, n4 = (i & 15) << 2;
                float4 r0 = bpref[it2*2], r1 = bpref[it2*2 + 1];
                base[(n4+0)*AS2_STRIDE + kp] = f2h2(r0.x, r1.x);
                base[(n4+1)*AS2_STRIDE + kp] = f2h2(r0.y, r1.y);
                base[(n4+2)*AS2_STRIDE + kp] = f2h2(r0.z, r1.z);
                base[(n4+3)*AS2_STRIDE + kp] = f2h2(r0.w, r1.w);
            }
            if (tile + 1 >= 2 && t < 128) {
                int r = t >> 1, half = t & 1;
                *(float4*)(wf2s + (pb^1)*512 + r*8 + half*4) = wpref;
                if (half == 0) bf1s[(pb^1)*64 + r] = bf1pref;
            }
        }
        __syncthreads();
    }

    #pragma unroll
    for (int ridx = 0; ridx < 4; ridx++)
        #pragma unroll
        for (int j = 0; j < NFILT; j++) {
            float s = fvacc[ridx][j];
            s += __shfl_xor_sync(0xffffffffu, s, 1);
            s += __shfl_xor_sync(0xffffffffu, s, 2);
            fvacc[ridx][j] = s;
        }
    if (tg == 0) {
        #pragma unroll
        for (int ridx = 0; ridx < 4; ridx++) {
            int rl = wm + (ridx >> 1)*16 + (ridx & 1)*8 + g;
            #pragma unroll
            for (int j = 0; j < NFILT; j++)
                atomicAdd(&fvs[rl*NFILT + j], fvacc[ridx][j]);
        }
    }
    __syncthreads();

    for (int i = t; i < 128*64; i += 256) {
        int r = i >> 6, o = i & 63;
        if (row0 + r >= M) continue;
        float s = bl0s[o];
        #pragma unroll
        for (int j = 0; j < NFILT; j++)
            s = fmaf(fvs[r*NFILT + j] + bf2s[j], fold[j*64 + o], s);
        x0a[(size_t)(row0 + r)*OUTDIM + o] = fmaxf(s, 0.f);
    }
}

// ================= DeepSet fp16 GEMM (K=64) =================
#define DS_STRIDE 36
#define DS_SMEM ((128*DS_STRIDE + 64*DS_STRIDE + 128) * 4)

template<bool BNACC>
__global__ void __launch_bounds__(256) ds_f16(
    const float* __restrict__ A,
    const float* __restrict__ B, int ldb,
    const float* __restrict__ bias,
    const float* __restrict__ sub, int ldsub,
    const int* __restrict__ batch,
    float* __restrict__ C, int ldc, int M) {
    extern __shared__ uint32_t smbuf[];
    uint32_t* As2 = smbuf;
    uint32_t* Bs2 = smbuf + 128*DS_STRIDE;
    float* bnsm = (float*)(smbuf + 128*DS_STRIDE + 64*DS_STRIDE);
    const int t = threadIdx.x;
    const int row0 = blockIdx.y * 128, col0 = blockIdx.x * 64;

    for (int i = t; i < 128*16; i += 256) {
        int r = i >> 4, k4 = (i & 15) << 2;
        float4 v = make_float4(0.f, 0.f, 0.f, 0.f);
        if (row0 + r < M) v = *(const float4*)(A + (size_t)(row0 + r)*OUTDIM + k4);
        As2[r*DS_STRIDE + (k4 >> 1)]     = f2h2(v.x, v.y);
        As2[r*DS_STRIDE + (k4 >> 1) + 1] = f2h2(v.z, v.w);
    }
    for (int i = t; i < 512; i += 256) {
        int kp = i >> 4, n4 = (i & 15) << 2;
        float4 r0 = *(const float4*)(B + (size_t)(2*kp)*ldb + col0 + n4);
        float4 r1 = *(const float4*)(B + (size_t)(2*kp + 1)*ldb + col0 + n4);
        Bs2[(n4+0)*DS_STRIDE + kp] = f2h2(r0.x, r1.x);
        Bs2[(n4+1)*DS_STRIDE + kp] = f2h2(r0.y, r1.y);
        Bs2[(n4+2)*DS_STRIDE + kp] = f2h2(r0.z, r1.z);
        Bs2[(n4+3)*DS_STRIDE + kp] = f2h2(r0.w, r1.w);
    }
    if (BNACC && t < 128) bnsm[t] = 0.f;
    __syncthreads();

    const int wid = t >> 5, lane = t & 31;
    const int wm = (wid & 3) * 32, wn = (wid >> 2) * 32;
    const int g = lane >> 2, tg = lane & 3;

    float acc[2][4][4] = {};
    #pragma unroll
    for (int ko = 0; ko < 4; ko++) {
        int k0 = ko * 8;
        uint32_t a[2][4], b[4][2];
        #pragma unroll
        for (int mt = 0; mt < 2; mt++) {
            int r = wm + mt*16 + g;
            a[mt][0] = As2[r*DS_STRIDE + k0 + tg];
            a[mt][1] = As2[(r + 8)*DS_STRIDE + k0 + tg];
            a[mt][2] = As2[r*DS_STRIDE + k0 + tg + 4];
            a[mt][3] = As2[(r + 8)*DS_STRIDE + k0 + tg + 4];
        }
        #pragma unroll
        for (int nt = 0; nt < 4; nt++) {
            int n = wn + nt*8 + g;
            b[nt][0] = Bs2[n*DS_STRIDE + k0 + tg];
            b[nt][1] = Bs2[n*DS_STRIDE + k0 + tg + 4];
        }
        #pragma unroll
        for (int mt = 0; mt < 2; mt++)
            #pragma unroll
            for (int nt = 0; nt < 4; nt++)
                mma_f16(acc[mt][nt], a[mt], b[nt]);
    }

    float s1[4][2] = {}, s2[4][2] = {};
    #pragma unroll
    for (int mt = 0; mt < 2; mt++) {
        int r0g = row0 + wm + mt*16 + g;
        int r1g = r0g + 8;
        bool ok0 = r0g < M, ok1 = r1g < M;
        int b0 = ok0 ? batch[r0g] : 0;
        int b1 = ok1 ? batch[r1g] : 0;
        const float* sub0 = sub + (size_t)b0*ldsub;
        const float* sub1 = sub + (size_t)b1*ldsub;
        #pragma unroll
        for (int nt = 0; nt < 4; nt++) {
            int cA = col0 + wn + nt*8 + 2*tg, cB = cA + 1;
            float biA = bias[cA], biB = bias[cB];
            float v00 = fmaxf(acc[mt][nt][0] + biA - sub0[cA], 0.f);
            float v01 = fmaxf(acc[mt][nt][1] + biB - sub0[cB], 0.f);
            float v10 = fmaxf(acc[mt][nt][2] + biA - sub1[cA], 0.f);
            float v11 = fmaxf(acc[mt][nt][3] + biB - sub1[cB], 0.f);
            if (ok0) *(float2*)(C + (size_t)r0g*ldc + cA) = make_float2(v00, v01);
            if (ok1) *(float2*)(C + (size_t)r1g*ldc + cA) = make_float2(v10, v11);
            if (BNACC) {
                s1[nt][0] += (ok0 ? v00 : 0.f) + (ok1 ? v10 : 0.f);
                s1[nt][1] += (ok0 ? v01 : 0.f) + (ok1 ? v11 : 0.f);
                s2[nt][0] += (ok0 ? v00*v00 : 0.f) + (ok1 ? v10*v10 : 0.f);
                s2[nt][1] += (ok0 ? v01*v01 : 0.f) + (ok1 ? v11*v11 : 0.f);
            }
        }
    }
    if (BNACC) {
        #pragma unroll
        for (int nt = 0; nt < 4; nt++)
            #pragma unroll
            for (int h = 0; h < 2; h++) {
                float a = s1[nt][h], b = s2[nt][h];
                #pragma unroll
                for (int o = 4; o < 32; o <<= 1) {
                    a += __shfl_xor_sync(0xffffffffu, a, o);
                    b += __shfl_xor_sync(0xffffffffu, b, o);
                }
                if (g == 0) {
                    int cl = wn + nt*8 + 2*tg + h;
                    atomicAdd(&bnsm[2*cl], a);
                    atomicAdd(&bnsm[2*cl + 1], b);
                }
            }
        __syncthreads();
        if (t < 64) {
            atomicAdd(&g_bn[col0 + t], bnsm[2*t]);
            atomicAdd(&g_bn[FIN + col0 + t], bnsm[2*t + 1]);
        }
    }
}

// ---------------- edge attention (fp16 operands, fp32 accumulate) ----------------
__global__ void k_att(const int* __restrict__ ei, float* __restrict__ out) {
    int wid = (blockIdx.x * blockDim.x + threadIdx.x) >> 5;
    int l = threadIdx.x & 31;
    if (wid >= NEDGE) return;
    int row = ei[wid], col = ei[NEDGE + wid];
    uint2 zv = *(const uint2*)(g_zh + (size_t)row*64 + l*2);
    uint2 xv = *(const uint2*)(g_xh + (size_t)col*64 + l*2);
    float2 z0 = __half22float2(*(__half2*)&zv.x);
    float2 z1 = __half22float2(*(__half2*)&zv.y);
    float2 x0 = __half22float2(*(__half2*)&xv.x);
    float2 x1 = __half22float2(*(__half2*)&xv.y);
    float d = z0.x*x0.x + z0.y*x0.y + z1.x*x1.x + z1.y*x1.y;
    #pragma unroll
    for (int o = 16; o; o >>= 1) d += __shfl_xor_sync(0xffffffffu, d, o);
    if (l == 0) {
        float s = d + g_p[row] + g_q[col] + g_c[0];
        out[(size_t)NNODE*FIN + wid] = 1.f / (1.f + expf(-s));
    }
}

// ---------------- segment sum over sorted batch ----------------
__global__ void k_seg(const float* __restrict__ v, const int* __restrict__ batch,
                      float* __restrict__ sum, int do_cnt) {
    int t = threadIdx.x;
    int f = t & 63, w = t >> 6;
    int r0 = blockIdx.x * 128;
    int rend = min(r0 + 128, NNODE);
    float acc = 0.f, ccnt = 0.f;
    int cur = -1;
    for (int rb = r0 + w; rb < rend; rb += 16) {
        float vv[4]; int gg[4];
        #pragma unroll
        for (int j = 0; j < 4; j++) {
            int r = rb + j*4;
            bool ok = r < rend;
            vv[j] = ok ? v[(size_t)r*64 + f] : 0.f;
            gg[j] = ok ? __ldg(&batch[r]) : -2;
        }
        #pragma unroll
        for (int j = 0; j < 4; j++) {
            if (gg[j] != cur) {
                if (cur >= 0) {
                    atomicAdd(&sum[cur*64 + f], acc);
                    if (do_cnt && f == 0) atomicAdd(&g_cnt[cur], ccnt);
                }
                acc = 0.f; ccnt = 0.f; cur = gg[j];
            }
            if (gg[j] >= 0) { acc += vv[j]; ccnt += 1.f; }
        }
    }
    if (cur >= 0) {
        atomicAdd(&sum[cur*64 + f], acc);
        if (do_cnt && f == 0) atomicAdd(&g_cnt[cur], ccnt);
    }
}

__global__ void k_mean1(const float* __restrict__ L1) {
    __shared__ float mean[OUTDIM];
    int g = blockIdx.x, t = threadIdx.x;
    float c = fmaxf(g_cnt[g], 1.f);
    mean[t] = g_seg1[g*64 + t] / c;
    __syncthreads();
    float s = 0.f;
    #pragma unroll 4
    for (int k = 0; k < 64; k++) s += mean[k] * L1[k*64 + t];
    g_xm1[g*64 + t] = s;
}

__global__ void k_mean2(const float* __restrict__ L2) {
    __shared__ float mean[OUTDIM];
    int g = blockIdx.x, t = threadIdx.x;
    if (t < 64) mean[t] = g_seg2[g*64 + t] / fmaxf(g_cnt[g], 1.f);
    __syncthreads();
    float s = 0.f;
    #pragma unroll 4
    for (int k = 0; k < 64; k++) s += mean[k] * L2[k*128 + t];
    g_xm2[g*128 + t] = s;
}

__global__ void k_bnfin(const float* __restrict__ gamma, const float* __restrict__ beta) {
    int f = threadIdx.x;
    float mu = g_bn[f] / (float)NNODE;
    float var = g_bn[128 + f] / (float)NNODE - mu*mu;
    float a = gamma[f] * rsqrtf(var + 1e-5f);
    g_bna[f] = a;
    g_bnb[f] = beta[f] - mu*a;
}

__global__ void k_out(const float* __restrict__ x, float* __restrict__ out) {
    int i = blockIdx.x * blockDim.x + threadIdx.x;
    if (i >= NNODE*FIN/4) return;
    int f4 = (i & 31) * 4;
    float4 xv = ((const float4*)x)[i];
    float4 hv = ((const float4*)g_hid2)[i];
    float4 a  = *(const float4*)(g_bna + f4);
    float4 b  = *(const float4*)(g_bnb + f4);
    float4 o;
    o.x = xv.x + hv.x*a.x + b.x;
    o.y = xv.y + hv.y*a.y + b.y;
    o.z = xv.z + hv.z*a.z + b.z;
    o.w = xv.w + hv.w*a.w + b.w;
    ((float4*)out)[i] = o;
}

// ---------------- host launch ----------------
extern "C" void kernel_launch(void* const* d_in, const int* in_sizes, int n_in,
                              void* d_out, int out_size) {
    const float* x      = (const float*)d_in[0];
    const int*   ei     = (const int*)  d_in[1];
    const int*   batch  = (const int*)  d_in[2];
    const float* W_f1   = (const float*)d_in[3];
    const float* b_f1   = (const float*)d_in[4];
    const float* W_f2   = (const float*)d_in[5];
    const float* b_f2   = (const float*)d_in[6];
    const float* W_l0   = (const float*)d_in[7];
    const float* b_l0   = (const float*)d_in[8];
    const float* G1     = (const float*)d_in[9];
    const float* b_g1   = (const float*)d_in[10];
    const float* L1     = (const float*)d_in[11];
    const float* G2     = (const float*)d_in[12];
    const float* b_g2   = (const float*)d_in[13];
    const float* L2     = (const float*)d_in[14];
    const float* gamma  = (const float*)d_in[15];
    const float* beta   = (const float*)d_in[16];
    const float* W_att  = (const float*)d_in[17];
    const float* b_att  = (const float*)d_in[18];
    const float* A_att  = (const float*)d_in[19];
    float* out = (float*)d_out;

    float *pM, *px0a, *px0b, *pxm1, *pxm2, *phid2, *pseg1, *pseg2;
    cudaGetSymbolAddress((void**)&pM,    g_M);
    cudaGetSymbolAddress((void**)&px0a,  g_x0a);
    cudaGetSymbolAddress((void**)&px0b,  g_x0b);
    cudaGetSymbolAddress((void**)&pxm1,  g_xm1);
    cudaGetSymbolAddress((void**)&pxm2,  g_xm2);
    cudaGetSymbolAddress((void**)&phid2, g_hid2);
    cudaGetSymbolAddress((void**)&pseg1, g_seg1);
    cudaGetSymbolAddress((void**)&pseg2, g_seg2);

    cudaFuncSetAttribute(mega_f16, cudaFuncAttributeMaxDynamicSharedMemorySize, MEGA_SMEM);
    cudaFuncSetAttribute(ds_f16<false>, cudaFuncAttributeMaxDynamicSharedMemorySize, DS_SMEM);
    cudaFuncSetAttribute(ds_f16<true>,  cudaFuncAttributeMaxDynamicSharedMemorySize, DS_SMEM);

    static cudaStream_t s_att = nullptr;
    static cudaEvent_t ev_fork = nullptr, ev_join = nullptr;
    if (s_att == nullptr) {
        cudaStreamCreateWithFlags(&s_att, cudaStreamNonBlocking);
        cudaEventCreateWithFlags(&ev_fork, cudaEventDisableTiming);
        cudaEventCreateWithFlags(&ev_join, cudaEventDisableTiming);
    }

    const int rb128 = (NNODE + 127) / 128;  // 782

    k_zero<<<64, 256>>>();
    k_pre1<<<NHEADS*ATTD + NHEADS, 128>>>(W_att, b_att, A_att);
    k_mgemm<<<dim3(4, 4, 4), 256>>>(W_att);
    k_uvc<<<FIN + 1, 128>>>(W_att, b_att);

    mega_f16<<<rb128, 256, MEGA_SMEM>>>(x, pM, W_f1, b_f1, W_f2, b_f2,
                                        W_l0, b_l0, px0a, NNODE);

    cudaEventRecord(ev_fork, 0);
    cudaStreamWaitEvent(s_att, ev_fork, 0);
    k_att<<<(NEDGE*32 + 255)/256, 256, 0, s_att>>>(ei, out);
    cudaEventRecord(ev_join, s_att);

    k_seg<<<rb128, 256>>>(px0a, batch, pseg1, 1);
    k_mean1<<<NG, 64>>>(L1);
    ds_f16<false><<<dim3(1, rb128), 256, DS_SMEM>>>(
        px0a, G1, OUTDIM, b_g1, pxm1, OUTDIM, batch, px0b, OUTDIM, NNODE);

    k_seg<<<rb128, 256>>>(px0b, batch, pseg2, 0);
    k_mean2<<<NG, 128>>>(L2);
    ds_f16<true><<<dim3(2, rb128), 256, DS_SMEM>>>(
        px0b, G2, FIN, b_g2, pxm2, FIN, batch, phid2, FIN, NNODE);

    k_bnfin<<<1, 128>>>(gamma, beta);
    k_out<<<(NNODE*FIN/4 + 255)/256, 256>>>(x, out);

    cudaStreamWaitEvent(0, ev_join, 0);
}